// round 3
// baseline (speedup 1.0000x reference)
#include <cuda_runtime.h>
#include <math.h>
#include <stdint.h>

#define B_  4
#define L_  1024
#define D_  1024
#define H_  16
#define HD_ 64
#define D3_ 3072

// Scratch (allocation-free rule: device globals)
__device__ float g_qkv[(size_t)B_ * L_ * D3_];   // [B,L,3D]  q|k|v
__device__ float g_y[(size_t)B_ * L_ * D_];      // [B,L,D]   attention output (heads merged)

// ---------------------------------------------------------------------------
// tf32 helpers
// ---------------------------------------------------------------------------
__device__ __forceinline__ uint32_t f2tf32(float x) {
    uint32_t r;
    asm("cvt.rna.tf32.f32 %0, %1;" : "=r"(r) : "f"(x));
    return r;
}

__device__ __forceinline__ void mma_tf32(float* c,
                                         uint32_t a0, uint32_t a1, uint32_t a2, uint32_t a3,
                                         uint32_t b0, uint32_t b1) {
    asm volatile(
        "mma.sync.aligned.m16n8k8.row.col.f32.tf32.tf32.f32 "
        "{%0,%1,%2,%3},{%4,%5,%6,%7},{%8,%9},{%0,%1,%2,%3};\n"
        : "+f"(c[0]), "+f"(c[1]), "+f"(c[2]), "+f"(c[3])
        : "r"(a0), "r"(a1), "r"(a2), "r"(a3), "r"(b0), "r"(b1));
}

// ---------------------------------------------------------------------------
// Tensor-core GEMM (NT): C[m,n] = sum_k A[m,k]*B[n,k].
// tf32 mma.m16n8k8 with hi/lo error compensation (AhiBhi + AhiBlo + AloBhi).
// 128x128 block tile, BK=8, 256 threads = 8 warps (2m x 4n), warp tile 64x32.
// Smem [k][m] layout with stride 136 -> conflict-free fragment gathers.
// M,N multiples of 128, K multiple of 8.
// ---------------------------------------------------------------------------
#define SST 136
__global__ __launch_bounds__(256) void tgemm_nt(const float* __restrict__ A,
                                                const float* __restrict__ Bm,
                                                float* __restrict__ C,
                                                int M, int N, int K) {
    __shared__ uint32_t Ashi[8][SST];
    __shared__ uint32_t Aslo[8][SST];
    __shared__ uint32_t Bshi[8][SST];
    __shared__ uint32_t Bslo[8][SST];

    const int tid  = threadIdx.x;
    const int warp = tid >> 5, lane = tid & 31;
    const int g = lane >> 2, tig = lane & 3;
    const int wm = (warp >> 2) * 64;      // 0 or 64
    const int wn = (warp & 3) * 32;       // 0,32,64,96
    const int bm = blockIdx.y * 128, bn = blockIdx.x * 128;

    const int lr = tid >> 1;              // 0..127 row within tile
    const int lk = (tid & 1) * 4;         // 0 or 4

    const float* Ag = A  + (size_t)(bm + lr) * K + lk;
    const float* Bg = Bm + (size_t)(bn + lr) * K + lk;
    float4 ap = *(const float4*)Ag;
    float4 bp = *(const float4*)Bg;

    float acc[4][4][4];
#pragma unroll
    for (int mi = 0; mi < 4; ++mi)
#pragma unroll
        for (int ni = 0; ni < 4; ++ni)
#pragma unroll
            for (int r = 0; r < 4; ++r) acc[mi][ni][r] = 0.f;

    const int nk = K >> 3;
    for (int kt = 0; kt < nk; ++kt) {
        // split fp32 -> tf32 hi + tf32 lo, store transposed [k][m]
        {
            const float av[4] = {ap.x, ap.y, ap.z, ap.w};
            const float bv[4] = {bp.x, bp.y, bp.z, bp.w};
#pragma unroll
            for (int j = 0; j < 4; ++j) {
                uint32_t hi = f2tf32(av[j]);
                Ashi[lk + j][lr] = hi;
                Aslo[lk + j][lr] = f2tf32(av[j] - __uint_as_float(hi));
                uint32_t hib = f2tf32(bv[j]);
                Bshi[lk + j][lr] = hib;
                Bslo[lk + j][lr] = f2tf32(bv[j] - __uint_as_float(hib));
            }
        }
        __syncthreads();
        if (kt + 1 < nk) {
            ap = *(const float4*)(Ag + (size_t)(kt + 1) * 8);
            bp = *(const float4*)(Bg + (size_t)(kt + 1) * 8);
        }

        // B fragments for all 4 n-tiles (hi + lo)
        uint32_t bh[4][2], bl[4][2];
#pragma unroll
        for (int ni = 0; ni < 4; ++ni) {
            int n0 = wn + ni * 8 + g;
            bh[ni][0] = Bshi[tig][n0];     bh[ni][1] = Bshi[tig + 4][n0];
            bl[ni][0] = Bslo[tig][n0];     bl[ni][1] = Bslo[tig + 4][n0];
        }

#pragma unroll
        for (int mi = 0; mi < 4; ++mi) {
            int m0 = wm + mi * 16 + g;
            uint32_t ah0 = Ashi[tig][m0],     ah1 = Ashi[tig][m0 + 8];
            uint32_t ah2 = Ashi[tig + 4][m0], ah3 = Ashi[tig + 4][m0 + 8];
            uint32_t al0 = Aslo[tig][m0],     al1 = Aslo[tig][m0 + 8];
            uint32_t al2 = Aslo[tig + 4][m0], al3 = Aslo[tig + 4][m0 + 8];
#pragma unroll
            for (int ni = 0; ni < 4; ++ni) {
                mma_tf32(acc[mi][ni], ah0, ah1, ah2, ah3, bh[ni][0], bh[ni][1]);
                mma_tf32(acc[mi][ni], ah0, ah1, ah2, ah3, bl[ni][0], bl[ni][1]);
                mma_tf32(acc[mi][ni], al0, al1, al2, al3, bh[ni][0], bh[ni][1]);
            }
        }
        __syncthreads();
    }

    // epilogue: c0 (g, 2tig), c1 (g, 2tig+1), c2 (g+8, 2tig), c3 (g+8, 2tig+1)
#pragma unroll
    for (int mi = 0; mi < 4; ++mi) {
        int ra = bm + wm + mi * 16 + g;
#pragma unroll
        for (int ni = 0; ni < 4; ++ni) {
            int col = bn + wn + ni * 8 + 2 * tig;
            float* c0 = C + (size_t)ra * N + col;
            float* c1 = C + (size_t)(ra + 8) * N + col;
            *(float2*)c0 = make_float2(acc[mi][ni][0], acc[mi][ni][1]);
            *(float2*)c1 = make_float2(acc[mi][ni][2], acc[mi][ni][3]);
        }
    }
}

// ---------------------------------------------------------------------------
// Dual-path causal flash attention, fp32 (unchanged from R1 passing version).
// ---------------------------------------------------------------------------
__global__ __launch_bounds__(256) void attn_kernel(const float* __restrict__ qg_in,
                                                   const float* __restrict__ kg_in,
                                                   float* __restrict__ y) {
    __shared__ float bufA[64 * 64];
    __shared__ float bufB[64 * 64];
    __shared__ float Ps[64 * 64];

    const int bh = blockIdx.y;
    const int b  = bh >> 4;
    const int h  = bh & 15;
    const int rt = blockIdx.x;
    const int tid = threadIdx.x;
    const int tx = tid & 15, ty = tid >> 4;

    const float* qbase  = g_qkv + (size_t)b * L_ * D3_ + h * HD_;
    const float* kbase  = qbase + D_;
    const float* vbase  = qbase + 2 * D_;
    const float* qgbase = qg_in + (size_t)b * L_ * D_ + h * HD_;
    const float* kgbase = kg_in + (size_t)b * L_ * D_ + h * HD_;

    const int ls  = tid >> 2;
    const int ld0 = (tid & 3) * 16;

    float mrow[4], lrow[4], oacc[4][4];
#pragma unroll
    for (int i = 0; i < 4; ++i) {
        mrow[i] = -INFINITY;
        lrow[i] = 0.f;
#pragma unroll
        for (int j = 0; j < 4; ++j) oacc[i][j] = 0.f;
    }

    const float SC = 0.125f / 6.931471805599453f;

    for (int t = 0; t <= rt; ++t) {
        float S[4][4];
#pragma unroll
        for (int i = 0; i < 4; ++i)
#pragma unroll
            for (int j = 0; j < 4; ++j) S[i][j] = 0.f;

        __syncthreads();
        {
            const float* gq = qbase + (size_t)(rt * 64 + ls) * D3_ + ld0;
            const float* gk = kbase + (size_t)(t  * 64 + ls) * D3_ + ld0;
#pragma unroll
            for (int q = 0; q < 4; ++q) {
                float4 va = *(const float4*)(gq + q * 4);
                bufA[(ld0 + q * 4 + 0) * 64 + ls] = va.x;
                bufA[(ld0 + q * 4 + 1) * 64 + ls] = va.y;
                bufA[(ld0 + q * 4 + 2) * 64 + ls] = va.z;
                bufA[(ld0 + q * 4 + 3) * 64 + ls] = va.w;
                float4 vb = *(const float4*)(gk + q * 4);
                bufB[(ld0 + q * 4 + 0) * 64 + ls] = vb.x;
                bufB[(ld0 + q * 4 + 1) * 64 + ls] = vb.y;
                bufB[(ld0 + q * 4 + 2) * 64 + ls] = vb.z;
                bufB[(ld0 + q * 4 + 3) * 64 + ls] = vb.w;
            }
        }
        __syncthreads();
#pragma unroll 4
        for (int d = 0; d < 64; ++d) {
            float4 a = *(const float4*)&bufA[d * 64 + ty * 4];
            float4 c = *(const float4*)&bufB[d * 64 + tx * 4];
            float ar[4] = {a.x, a.y, a.z, a.w};
            float cr[4] = {c.x, c.y, c.z, c.w};
#pragma unroll
            for (int i = 0; i < 4; ++i)
#pragma unroll
                for (int j = 0; j < 4; ++j)
                    S[i][j] = fmaf(ar[i], cr[j], S[i][j]);
        }

        __syncthreads();
        {
            const float* gq = qgbase + (size_t)(rt * 64 + ls) * D_ + ld0;
            const float* gk = kgbase + (size_t)(t  * 64 + ls) * D_ + ld0;
#pragma unroll
            for (int q = 0; q < 4; ++q) {
                float4 va = *(const float4*)(gq + q * 4);
                bufA[(ld0 + q * 4 + 0) * 64 + ls] = va.x;
                bufA[(ld0 + q * 4 + 1) * 64 + ls] = va.y;
                bufA[(ld0 + q * 4 + 2) * 64 + ls] = va.z;
                bufA[(ld0 + q * 4 + 3) * 64 + ls] = va.w;
                float4 vb = *(const float4*)(gk + q * 4);
                bufB[(ld0 + q * 4 + 0) * 64 + ls] = vb.x;
                bufB[(ld0 + q * 4 + 1) * 64 + ls] = vb.y;
                bufB[(ld0 + q * 4 + 2) * 64 + ls] = vb.z;
                bufB[(ld0 + q * 4 + 3) * 64 + ls] = vb.w;
            }
        }
        __syncthreads();
#pragma unroll 4
        for (int d = 0; d < 64; ++d) {
            float4 a = *(const float4*)&bufA[d * 64 + ty * 4];
            float4 c = *(const float4*)&bufB[d * 64 + tx * 4];
            float ar[4] = {a.x, a.y, a.z, a.w};
            float cr[4] = {c.x, c.y, c.z, c.w};
#pragma unroll
            for (int i = 0; i < 4; ++i)
#pragma unroll
                for (int j = 0; j < 4; ++j)
                    S[i][j] = fmaf(ar[i], cr[j], S[i][j]);
        }

        const bool diag = (t == rt);
#pragma unroll
        for (int i = 0; i < 4; ++i)
#pragma unroll
            for (int j = 0; j < 4; ++j) {
                S[i][j] *= SC;
                if (diag && (tx * 4 + j) > (ty * 4 + i)) S[i][j] = -INFINITY;
            }

#pragma unroll
        for (int i = 0; i < 4; ++i) {
            float mt = fmaxf(fmaxf(S[i][0], S[i][1]), fmaxf(S[i][2], S[i][3]));
#pragma unroll
            for (int off = 8; off >= 1; off >>= 1)
                mt = fmaxf(mt, __shfl_xor_sync(0xffffffffu, mt, off));
            float mnew  = fmaxf(mrow[i], mt);
            float alpha = __expf(mrow[i] - mnew);
            float p0 = __expf(S[i][0] - mnew);
            float p1 = __expf(S[i][1] - mnew);
            float p2 = __expf(S[i][2] - mnew);
            float p3 = __expf(S[i][3] - mnew);
            float ps = p0 + p1 + p2 + p3;
#pragma unroll
            for (int off = 8; off >= 1; off >>= 1)
                ps += __shfl_xor_sync(0xffffffffu, ps, off);
            lrow[i] = lrow[i] * alpha + ps;
            mrow[i] = mnew;
#pragma unroll
            for (int j = 0; j < 4; ++j) oacc[i][j] *= alpha;
            *(float4*)&Ps[(ty * 4 + i) * 64 + tx * 4] = make_float4(p0, p1, p2, p3);
        }

        __syncthreads();
        {
            const float* gv = vbase + (size_t)(t * 64 + ls) * D3_ + ld0;
#pragma unroll
            for (int q = 0; q < 4; ++q)
                *(float4*)&bufB[ls * 64 + ld0 + q * 4] = *(const float4*)(gv + q * 4);
        }
        __syncthreads();
#pragma unroll 4
        for (int s = 0; s < 64; ++s) {
            float4 bv = *(const float4*)&bufB[s * 64 + tx * 4];
#pragma unroll
            for (int i = 0; i < 4; ++i) {
                float a = Ps[(ty * 4 + i) * 64 + s];
                oacc[i][0] = fmaf(a, bv.x, oacc[i][0]);
                oacc[i][1] = fmaf(a, bv.y, oacc[i][1]);
                oacc[i][2] = fmaf(a, bv.z, oacc[i][2]);
                oacc[i][3] = fmaf(a, bv.w, oacc[i][3]);
            }
        }
    }

    float* yrow = y + ((size_t)b * L_ + (size_t)rt * 64) * D_ + h * HD_;
#pragma unroll
    for (int i = 0; i < 4; ++i) {
        float inv = 1.f / lrow[i];
        int row = ty * 4 + i;
        *(float4*)&yrow[(size_t)row * D_ + tx * 4] =
            make_float4(oacc[i][0] * inv, oacc[i][1] * inv,
                        oacc[i][2] * inv, oacc[i][3] * inv);
    }
}

// ---------------------------------------------------------------------------
extern "C" void kernel_launch(void* const* d_in, const int* in_sizes, int n_in,
                              void* d_out, int out_size) {
    const float* x    = (const float*)d_in[0];
    const float* q_g  = (const float*)d_in[1];
    const float* k_g  = (const float*)d_in[2];
    const float* Wqkv = (const float*)d_in[3];
    const float* Wout = (const float*)d_in[4];
    float* out = (float*)d_out;

    float *qkv, *y;
    cudaGetSymbolAddress((void**)&qkv, g_qkv);
    cudaGetSymbolAddress((void**)&y, g_y);

    // 1) qkv = x @ Wqkv^T : [4096,1024] x [3072,1024]^T -> [4096,3072]
    dim3 g1(D3_ / 128, (B_ * L_) / 128);
    tgemm_nt<<<g1, 256>>>(x, Wqkv, qkv, B_ * L_, D3_, D_);

    // 2) dual-path causal attention -> y [B,L,D]
    attn_kernel<<<dim3(16, B_ * H_), 256>>>(q_g, k_g, y);

    // 3) out = y @ Wout^T : [4096,1024] x [1024,1024]^T -> [4096,1024]
    dim3 g3(D_ / 128, (B_ * L_) / 128);
    tgemm_nt<<<g3, 256>>>(y, Wout, out, B_ * L_, D_, D_);
}

// round 4
// speedup vs baseline: 1.2386x; 1.2386x over previous
#include <cuda_runtime.h>
#include <cuda_fp16.h>
#include <math.h>
#include <stdint.h>

#define B_  4
#define L_  1024
#define D_  1024
#define H_  16
#define HD_ 64
#define D3_ 3072

// Scratch (allocation-free rule: device globals)
__device__ float g_qkv[(size_t)B_ * L_ * D3_];   // [B,L,3D]  q|k|v
__device__ float g_y[(size_t)B_ * L_ * D_];      // [B,L,D]   attention output (heads merged)

// ---------------------------------------------------------------------------
// fp16 helpers
// ---------------------------------------------------------------------------
__device__ __forceinline__ uint32_t pack_h2(__half a, __half b) {
    __half2 h = __halves2half2(a, b);
    return *(uint32_t*)&h;
}

// split two floats into packed hi (fp16) and lo (fp16 of residual)
__device__ __forceinline__ void split2(float x0, float x1, uint32_t& hi, uint32_t& lo) {
    __half h0 = __float2half_rn(x0);
    __half h1 = __float2half_rn(x1);
    __half l0 = __float2half_rn(x0 - __half2float(h0));
    __half l1 = __float2half_rn(x1 - __half2float(h1));
    hi = pack_h2(h0, h1);
    lo = pack_h2(l0, l1);
}

__device__ __forceinline__ void mma_f16(float* c,
                                        uint32_t a0, uint32_t a1, uint32_t a2, uint32_t a3,
                                        uint32_t b0, uint32_t b1) {
    asm volatile(
        "mma.sync.aligned.m16n8k16.row.col.f32.f16.f16.f32 "
        "{%0,%1,%2,%3},{%4,%5,%6,%7},{%8,%9},{%0,%1,%2,%3};\n"
        : "+f"(c[0]), "+f"(c[1]), "+f"(c[2]), "+f"(c[3])
        : "r"(a0), "r"(a1), "r"(a2), "r"(a3), "r"(b0), "r"(b1));
}

// ---------------------------------------------------------------------------
// Tensor-core GEMM (NT): C[m,n] = sum_k A[m,k]*B[n,k].
// fp16 m16n8k16 with hi/lo error compensation (AhiBhi + AhiBlo + AloBhi).
// 128x128 block tile, BK=16, 256 threads = 8 warps (2m x 4n), warp tile 64x32.
// Double-buffered smem, one __syncthreads per K-chunk.
// Smem rows hold 8 k-pairs (u32) padded to stride 9 -> near-conflict-free.
// M,N multiples of 128, K multiple of 16.
// ---------------------------------------------------------------------------
#define RS 9
__global__ __launch_bounds__(256) void tgemm_nt(const float* __restrict__ A,
                                                const float* __restrict__ Bm,
                                                float* __restrict__ C,
                                                int M, int N, int K) {
    __shared__ uint32_t Ahi[2][128 * RS];
    __shared__ uint32_t Alo[2][128 * RS];
    __shared__ uint32_t Bhi[2][128 * RS];
    __shared__ uint32_t Blo[2][128 * RS];

    const int tid  = threadIdx.x;
    const int warp = tid >> 5, lane = tid & 31;
    const int g = lane >> 2, tig = lane & 3;
    const int wm = (warp >> 2) * 64;      // 0 or 64
    const int wn = (warp & 3) * 32;       // 0,32,64,96
    const int bm = blockIdx.y * 128, bn = blockIdx.x * 128;

    const int lr = tid >> 1;              // 0..127 row within tile
    const int lk = (tid & 1) * 8;         // k offset 0 or 8

    const float* Ag = A  + (size_t)(bm + lr) * K + lk;
    const float* Bg = Bm + (size_t)(bn + lr) * K + lk;

    float acc[4][4][4];
#pragma unroll
    for (int mi = 0; mi < 4; ++mi)
#pragma unroll
        for (int ni = 0; ni < 4; ++ni)
#pragma unroll
            for (int r = 0; r < 4; ++r) acc[mi][ni][r] = 0.f;

    // prefetch chunk 0
    float4 a0 = *(const float4*)Ag;
    float4 a1 = *(const float4*)(Ag + 4);
    float4 b0 = *(const float4*)Bg;
    float4 b1 = *(const float4*)(Bg + 4);

    const int sbase = lr * RS + (lk >> 1);   // u32 index of first k-pair

    // fill buffer 0
    {
        uint32_t h, l;
        split2(a0.x, a0.y, h, l); Ahi[0][sbase + 0] = h; Alo[0][sbase + 0] = l;
        split2(a0.z, a0.w, h, l); Ahi[0][sbase + 1] = h; Alo[0][sbase + 1] = l;
        split2(a1.x, a1.y, h, l); Ahi[0][sbase + 2] = h; Alo[0][sbase + 2] = l;
        split2(a1.z, a1.w, h, l); Ahi[0][sbase + 3] = h; Alo[0][sbase + 3] = l;
        split2(b0.x, b0.y, h, l); Bhi[0][sbase + 0] = h; Blo[0][sbase + 0] = l;
        split2(b0.z, b0.w, h, l); Bhi[0][sbase + 1] = h; Blo[0][sbase + 1] = l;
        split2(b1.x, b1.y, h, l); Bhi[0][sbase + 2] = h; Blo[0][sbase + 2] = l;
        split2(b1.z, b1.w, h, l); Bhi[0][sbase + 3] = h; Blo[0][sbase + 3] = l;
    }
    __syncthreads();

    const int nk = K >> 4;                 // chunks of 16
    for (int kt = 0; kt < nk; ++kt) {
        const int cur = kt & 1;
        // prefetch next chunk from gmem
        if (kt + 1 < nk) {
            const float* An = Ag + (size_t)(kt + 1) * 16;
            const float* Bn = Bg + (size_t)(kt + 1) * 16;
            a0 = *(const float4*)An;
            a1 = *(const float4*)(An + 4);
            b0 = *(const float4*)Bn;
            b1 = *(const float4*)(Bn + 4);
        }

        // B fragments for all 4 n-tiles (hi + lo)
        const uint32_t* Bh = Bhi[cur];
        const uint32_t* Bl = Blo[cur];
        uint32_t bh[4][2], bl[4][2];
#pragma unroll
        for (int ni = 0; ni < 4; ++ni) {
            int n0 = (wn + ni * 8 + g) * RS;
            bh[ni][0] = Bh[n0 + tig];  bh[ni][1] = Bh[n0 + tig + 4];
            bl[ni][0] = Bl[n0 + tig];  bl[ni][1] = Bl[n0 + tig + 4];
        }

        const uint32_t* Ah = Ahi[cur];
        const uint32_t* Al = Alo[cur];
#pragma unroll
        for (int mi = 0; mi < 4; ++mi) {
            int m0 = (wm + mi * 16 + g) * RS;
            int m8 = m0 + 8 * RS;
            uint32_t ah0 = Ah[m0 + tig], ah1 = Ah[m8 + tig];
            uint32_t ah2 = Ah[m0 + tig + 4], ah3 = Ah[m8 + tig + 4];
            uint32_t al0 = Al[m0 + tig], al1 = Al[m8 + tig];
            uint32_t al2 = Al[m0 + tig + 4], al3 = Al[m8 + tig + 4];
#pragma unroll
            for (int ni = 0; ni < 4; ++ni) {
                mma_f16(acc[mi][ni], ah0, ah1, ah2, ah3, bh[ni][0], bh[ni][1]);
                mma_f16(acc[mi][ni], ah0, ah1, ah2, ah3, bl[ni][0], bl[ni][1]);
                mma_f16(acc[mi][ni], al0, al1, al2, al3, bh[ni][0], bh[ni][1]);
            }
        }

        // fill the other buffer for next chunk
        if (kt + 1 < nk) {
            const int nxt = cur ^ 1;
            uint32_t h, l;
            split2(a0.x, a0.y, h, l); Ahi[nxt][sbase + 0] = h; Alo[nxt][sbase + 0] = l;
            split2(a0.z, a0.w, h, l); Ahi[nxt][sbase + 1] = h; Alo[nxt][sbase + 1] = l;
            split2(a1.x, a1.y, h, l); Ahi[nxt][sbase + 2] = h; Alo[nxt][sbase + 2] = l;
            split2(a1.z, a1.w, h, l); Ahi[nxt][sbase + 3] = h; Alo[nxt][sbase + 3] = l;
            split2(b0.x, b0.y, h, l); Bhi[nxt][sbase + 0] = h; Blo[nxt][sbase + 0] = l;
            split2(b0.z, b0.w, h, l); Bhi[nxt][sbase + 1] = h; Blo[nxt][sbase + 1] = l;
            split2(b1.x, b1.y, h, l); Bhi[nxt][sbase + 2] = h; Blo[nxt][sbase + 2] = l;
            split2(b1.z, b1.w, h, l); Bhi[nxt][sbase + 3] = h; Blo[nxt][sbase + 3] = l;
        }
        __syncthreads();
    }

    // epilogue: c0 (g, 2tig), c1 (g, 2tig+1), c2 (g+8, 2tig), c3 (g+8, 2tig+1)
#pragma unroll
    for (int mi = 0; mi < 4; ++mi) {
        int ra = bm + wm + mi * 16 + g;
#pragma unroll
        for (int ni = 0; ni < 4; ++ni) {
            int col = bn + wn + ni * 8 + 2 * tig;
            float* c0 = C + (size_t)ra * N + col;
            float* c1 = C + (size_t)(ra + 8) * N + col;
            *(float2*)c0 = make_float2(acc[mi][ni][0], acc[mi][ni][1]);
            *(float2*)c1 = make_float2(acc[mi][ni][2], acc[mi][ni][3]);
        }
    }
}

// ---------------------------------------------------------------------------
// Dual-path causal flash attention, fp32 (unchanged from R1 passing version).
// ---------------------------------------------------------------------------
__global__ __launch_bounds__(256) void attn_kernel(const float* __restrict__ qg_in,
                                                   const float* __restrict__ kg_in,
                                                   float* __restrict__ y) {
    __shared__ float bufA[64 * 64];
    __shared__ float bufB[64 * 64];
    __shared__ float Ps[64 * 64];

    const int bh = blockIdx.y;
    const int b  = bh >> 4;
    const int h  = bh & 15;
    const int rt = blockIdx.x;
    const int tid = threadIdx.x;
    const int tx = tid & 15, ty = tid >> 4;

    const float* qbase  = g_qkv + (size_t)b * L_ * D3_ + h * HD_;
    const float* kbase  = qbase + D_;
    const float* vbase  = qbase + 2 * D_;
    const float* qgbase = qg_in + (size_t)b * L_ * D_ + h * HD_;
    const float* kgbase = kg_in + (size_t)b * L_ * D_ + h * HD_;

    const int ls  = tid >> 2;
    const int ld0 = (tid & 3) * 16;

    float mrow[4], lrow[4], oacc[4][4];
#pragma unroll
    for (int i = 0; i < 4; ++i) {
        mrow[i] = -INFINITY;
        lrow[i] = 0.f;
#pragma unroll
        for (int j = 0; j < 4; ++j) oacc[i][j] = 0.f;
    }

    const float SC = 0.125f / 6.931471805599453f;

    for (int t = 0; t <= rt; ++t) {
        float S[4][4];
#pragma unroll
        for (int i = 0; i < 4; ++i)
#pragma unroll
            for (int j = 0; j < 4; ++j) S[i][j] = 0.f;

        __syncthreads();
        {
            const float* gq = qbase + (size_t)(rt * 64 + ls) * D3_ + ld0;
            const float* gk = kbase + (size_t)(t  * 64 + ls) * D3_ + ld0;
#pragma unroll
            for (int q = 0; q < 4; ++q) {
                float4 va = *(const float4*)(gq + q * 4);
                bufA[(ld0 + q * 4 + 0) * 64 + ls] = va.x;
                bufA[(ld0 + q * 4 + 1) * 64 + ls] = va.y;
                bufA[(ld0 + q * 4 + 2) * 64 + ls] = va.z;
                bufA[(ld0 + q * 4 + 3) * 64 + ls] = va.w;
                float4 vb = *(const float4*)(gk + q * 4);
                bufB[(ld0 + q * 4 + 0) * 64 + ls] = vb.x;
                bufB[(ld0 + q * 4 + 1) * 64 + ls] = vb.y;
                bufB[(ld0 + q * 4 + 2) * 64 + ls] = vb.z;
                bufB[(ld0 + q * 4 + 3) * 64 + ls] = vb.w;
            }
        }
        __syncthreads();
#pragma unroll 4
        for (int d = 0; d < 64; ++d) {
            float4 a = *(const float4*)&bufA[d * 64 + ty * 4];
            float4 c = *(const float4*)&bufB[d * 64 + tx * 4];
            float ar[4] = {a.x, a.y, a.z, a.w};
            float cr[4] = {c.x, c.y, c.z, c.w};
#pragma unroll
            for (int i = 0; i < 4; ++i)
#pragma unroll
                for (int j = 0; j < 4; ++j)
                    S[i][j] = fmaf(ar[i], cr[j], S[i][j]);
        }

        __syncthreads();
        {
            const float* gq = qgbase + (size_t)(rt * 64 + ls) * D_ + ld0;
            const float* gk = kgbase + (size_t)(t  * 64 + ls) * D_ + ld0;
#pragma unroll
            for (int q = 0; q < 4; ++q) {
                float4 va = *(const float4*)(gq + q * 4);
                bufA[(ld0 + q * 4 + 0) * 64 + ls] = va.x;
                bufA[(ld0 + q * 4 + 1) * 64 + ls] = va.y;
                bufA[(ld0 + q * 4 + 2) * 64 + ls] = va.z;
                bufA[(ld0 + q * 4 + 3) * 64 + ls] = va.w;
                float4 vb = *(const float4*)(gk + q * 4);
                bufB[(ld0 + q * 4 + 0) * 64 + ls] = vb.x;
                bufB[(ld0 + q * 4 + 1) * 64 + ls] = vb.y;
                bufB[(ld0 + q * 4 + 2) * 64 + ls] = vb.z;
                bufB[(ld0 + q * 4 + 3) * 64 + ls] = vb.w;
            }
        }
        __syncthreads();
#pragma unroll 4
        for (int d = 0; d < 64; ++d) {
            float4 a = *(const float4*)&bufA[d * 64 + ty * 4];
            float4 c = *(const float4*)&bufB[d * 64 + tx * 4];
            float ar[4] = {a.x, a.y, a.z, a.w};
            float cr[4] = {c.x, c.y, c.z, c.w};
#pragma unroll
            for (int i = 0; i < 4; ++i)
#pragma unroll
                for (int j = 0; j < 4; ++j)
                    S[i][j] = fmaf(ar[i], cr[j], S[i][j]);
        }

        const bool diag = (t == rt);
#pragma unroll
        for (int i = 0; i < 4; ++i)
#pragma unroll
            for (int j = 0; j < 4; ++j) {
                S[i][j] *= SC;
                if (diag && (tx * 4 + j) > (ty * 4 + i)) S[i][j] = -INFINITY;
            }

#pragma unroll
        for (int i = 0; i < 4; ++i) {
            float mt = fmaxf(fmaxf(S[i][0], S[i][1]), fmaxf(S[i][2], S[i][3]));
#pragma unroll
            for (int off = 8; off >= 1; off >>= 1)
                mt = fmaxf(mt, __shfl_xor_sync(0xffffffffu, mt, off));
            float mnew  = fmaxf(mrow[i], mt);
            float alpha = __expf(mrow[i] - mnew);
            float p0 = __expf(S[i][0] - mnew);
            float p1 = __expf(S[i][1] - mnew);
            float p2 = __expf(S[i][2] - mnew);
            float p3 = __expf(S[i][3] - mnew);
            float ps = p0 + p1 + p2 + p3;
#pragma unroll
            for (int off = 8; off >= 1; off >>= 1)
                ps += __shfl_xor_sync(0xffffffffu, ps, off);
            lrow[i] = lrow[i] * alpha + ps;
            mrow[i] = mnew;
#pragma unroll
            for (int j = 0; j < 4; ++j) oacc[i][j] *= alpha;
            *(float4*)&Ps[(ty * 4 + i) * 64 + tx * 4] = make_float4(p0, p1, p2, p3);
        }

        __syncthreads();
        {
            const float* gv = vbase + (size_t)(t * 64 + ls) * D3_ + ld0;
#pragma unroll
            for (int q = 0; q < 4; ++q)
                *(float4*)&bufB[ls * 64 + ld0 + q * 4] = *(const float4*)(gv + q * 4);
        }
        __syncthreads();
#pragma unroll 4
        for (int s = 0; s < 64; ++s) {
            float4 bv = *(const float4*)&bufB[s * 64 + tx * 4];
#pragma unroll
            for (int i = 0; i < 4; ++i) {
                float a = Ps[(ty * 4 + i) * 64 + s];
                oacc[i][0] = fmaf(a, bv.x, oacc[i][0]);
                oacc[i][1] = fmaf(a, bv.y, oacc[i][1]);
                oacc[i][2] = fmaf(a, bv.z, oacc[i][2]);
                oacc[i][3] = fmaf(a, bv.w, oacc[i][3]);
            }
        }
    }

    float* yrow = y + ((size_t)b * L_ + (size_t)rt * 64) * D_ + h * HD_;
#pragma unroll
    for (int i = 0; i < 4; ++i) {
        float inv = 1.f / lrow[i];
        int row = ty * 4 + i;
        *(float4*)&yrow[(size_t)row * D_ + tx * 4] =
            make_float4(oacc[i][0] * inv, oacc[i][1] * inv,
                        oacc[i][2] * inv, oacc[i][3] * inv);
    }
}

// ---------------------------------------------------------------------------
extern "C" void kernel_launch(void* const* d_in, const int* in_sizes, int n_in,
                              void* d_out, int out_size) {
    const float* x    = (const float*)d_in[0];
    const float* q_g  = (const float*)d_in[1];
    const float* k_g  = (const float*)d_in[2];
    const float* Wqkv = (const float*)d_in[3];
    const float* Wout = (const float*)d_in[4];
    float* out = (float*)d_out;

    float *qkv, *y;
    cudaGetSymbolAddress((void**)&qkv, g_qkv);
    cudaGetSymbolAddress((void**)&y, g_y);

    // 1) qkv = x @ Wqkv^T : [4096,1024] x [3072,1024]^T -> [4096,3072]
    dim3 g1(D3_ / 128, (B_ * L_) / 128);
    tgemm_nt<<<g1, 256>>>(x, Wqkv, qkv, B_ * L_, D3_, D_);

    // 2) dual-path causal attention -> y [B,L,D]
    attn_kernel<<<dim3(16, B_ * H_), 256>>>(q_g, k_g, y);

    // 3) out = y @ Wout^T : [4096,1024] x [1024,1024]^T -> [4096,1024]
    dim3 g3(D_ / 128, (B_ * L_) / 128);
    tgemm_nt<<<g3, 256>>>(y, Wout, out, B_ * L_, D_, D_);
}

// round 5
// speedup vs baseline: 2.5592x; 2.0662x over previous
#include <cuda_runtime.h>
#include <cuda_fp16.h>
#include <math.h>
#include <stdint.h>

#define B_  4
#define L_  1024
#define D_  1024
#define H_  16
#define HD_ 64
#define D3_ 3072

// Scratch (allocation-free rule: device globals)
__device__ float g_qkv[(size_t)B_ * L_ * D3_];   // [B,L,3D]  q|k|v
__device__ float g_y[(size_t)B_ * L_ * D_];      // [B,L,D]   attention output

// ---------------------------------------------------------------------------
// helpers
// ---------------------------------------------------------------------------
__device__ __forceinline__ uint32_t cvta_s(const void* p) {
    return (uint32_t)__cvta_generic_to_shared(p);
}
__device__ __forceinline__ uint32_t pack_h2(__half a, __half b) {
    __half2 h = __halves2half2(a, b);
    return *(uint32_t*)&h;
}
__device__ __forceinline__ void split2(float x0, float x1, uint32_t& hi, uint32_t& lo) {
    __half h0 = __float2half_rn(x0);
    __half h1 = __float2half_rn(x1);
    __half l0 = __float2half_rn(x0 - __half2float(h0));
    __half l1 = __float2half_rn(x1 - __half2float(h1));
    hi = pack_h2(h0, h1);
    lo = pack_h2(l0, l1);
}
__device__ __forceinline__ void mma_f16(float* c,
                                        uint32_t a0, uint32_t a1, uint32_t a2, uint32_t a3,
                                        uint32_t b0, uint32_t b1) {
    asm volatile(
        "mma.sync.aligned.m16n8k16.row.col.f32.f16.f16.f32 "
        "{%0,%1,%2,%3},{%4,%5,%6,%7},{%8,%9},{%0,%1,%2,%3};\n"
        : "+f"(c[0]), "+f"(c[1]), "+f"(c[2]), "+f"(c[3])
        : "r"(a0), "r"(a1), "r"(a2), "r"(a3), "r"(b0), "r"(b1));
}
#define LDSM4(r0, r1, r2, r3, addr) \
    asm volatile("ldmatrix.sync.aligned.m8n8.x4.shared.b16 {%0,%1,%2,%3},[%4];\n" \
                 : "=r"(r0), "=r"(r1), "=r"(r2), "=r"(r3) : "r"(addr))
#define LDSM4T(r0, r1, r2, r3, addr) \
    asm volatile("ldmatrix.sync.aligned.m8n8.x4.trans.shared.b16 {%0,%1,%2,%3},[%4];\n" \
                 : "=r"(r0), "=r"(r1), "=r"(r2), "=r"(r3) : "r"(addr))

// ---------------------------------------------------------------------------
// Tensor-core GEMM (NT): C[m,n] = sum_k A[m,k]*B[n,k].
// fp16 m16n8k16, hi/lo compensation (3 MMA). 128x128 tile, BK=16, 8 warps
// (2m x 4n), warp tile 64x32. ldmatrix fragment loads, 48B row stride
// (conflict-free), double-buffered dynamic smem (48KB).
// ---------------------------------------------------------------------------
#define GST 6144                         // bytes per stage per array (128*24*2)
#define G_AHI 0
#define G_ALO 12288
#define G_BHI 24576
#define G_BLO 36864
#define GEMM_SMEM 49152

__global__ __launch_bounds__(256) void tgemm_nt(const float* __restrict__ A,
                                                const float* __restrict__ Bm,
                                                float* __restrict__ C,
                                                int M, int N, int K) {
    extern __shared__ char sm[];
    const uint32_t sbase = cvta_s(sm);

    const int tid  = threadIdx.x;
    const int warp = tid >> 5, lane = tid & 31;
    const int g = lane >> 2, tig = lane & 3;
    const int wm = (warp >> 2) * 64;
    const int wn = (warp & 3) * 32;
    const int bm = blockIdx.y * 128, bn = blockIdx.x * 128;

    const int lr = tid >> 1;              // row 0..127
    const int lk = (tid & 1) * 8;         // k half-offset 0 or 8

    const float* Ag = A  + (size_t)(bm + lr) * K + lk;
    const float* Bg = Bm + (size_t)(bn + lr) * K + lk;

    // ldmatrix per-lane byte offsets (row stride = 48B)
    const uint32_t aoff = (uint32_t)((wm + (lane & 15)) * 48 + (lane >> 4) * 16);
    const uint32_t boff = (uint32_t)((wn + (lane & 7) + ((lane >> 4) << 3)) * 48 +
                                     ((lane >> 3) & 1) * 16);
    // store index (u32 units): row stride 12 u32
    const int sidx = lr * 12 + (lk >> 1);
    uint32_t* const pAhi = (uint32_t*)(sm + G_AHI);
    uint32_t* const pAlo = (uint32_t*)(sm + G_ALO);
    uint32_t* const pBhi = (uint32_t*)(sm + G_BHI);
    uint32_t* const pBlo = (uint32_t*)(sm + G_BLO);

    float acc[4][4][4];
#pragma unroll
    for (int mi = 0; mi < 4; ++mi)
#pragma unroll
        for (int ni = 0; ni < 4; ++ni)
#pragma unroll
            for (int r = 0; r < 4; ++r) acc[mi][ni][r] = 0.f;

    float4 a0 = *(const float4*)Ag;
    float4 a1 = *(const float4*)(Ag + 4);
    float4 b0 = *(const float4*)Bg;
    float4 b1 = *(const float4*)(Bg + 4);

    // fill stage 0
    {
        uint32_t h, l;
        split2(a0.x, a0.y, h, l); pAhi[sidx + 0] = h; pAlo[sidx + 0] = l;
        split2(a0.z, a0.w, h, l); pAhi[sidx + 1] = h; pAlo[sidx + 1] = l;
        split2(a1.x, a1.y, h, l); pAhi[sidx + 2] = h; pAlo[sidx + 2] = l;
        split2(a1.z, a1.w, h, l); pAhi[sidx + 3] = h; pAlo[sidx + 3] = l;
        split2(b0.x, b0.y, h, l); pBhi[sidx + 0] = h; pBlo[sidx + 0] = l;
        split2(b0.z, b0.w, h, l); pBhi[sidx + 1] = h; pBlo[sidx + 1] = l;
        split2(b1.x, b1.y, h, l); pBhi[sidx + 2] = h; pBlo[sidx + 2] = l;
        split2(b1.z, b1.w, h, l); pBhi[sidx + 3] = h; pBlo[sidx + 3] = l;
    }
    __syncthreads();

    const int nk = K >> 4;
    for (int kt = 0; kt < nk; ++kt) {
        const uint32_t so = (kt & 1) ? GST : 0;
        if (kt + 1 < nk) {
            const float* An = Ag + (size_t)(kt + 1) * 16;
            const float* Bn = Bg + (size_t)(kt + 1) * 16;
            a0 = *(const float4*)An;
            a1 = *(const float4*)(An + 4);
            b0 = *(const float4*)Bn;
            b1 = *(const float4*)(Bn + 4);
        }

        // B fragments via ldmatrix: 2 x4 per precision covers 4 n-octets
        uint32_t bh[4][2], bl[4][2];
#pragma unroll
        for (int nb = 0; nb < 2; ++nb) {
            uint32_t r0, r1, r2, r3;
            uint32_t ad = sbase + G_BHI + so + boff + nb * 768;
            LDSM4(r0, r1, r2, r3, ad);
            bh[nb * 2][0] = r0; bh[nb * 2][1] = r1;
            bh[nb * 2 + 1][0] = r2; bh[nb * 2 + 1][1] = r3;
            ad = sbase + G_BLO + so + boff + nb * 768;
            LDSM4(r0, r1, r2, r3, ad);
            bl[nb * 2][0] = r0; bl[nb * 2][1] = r1;
            bl[nb * 2 + 1][0] = r2; bl[nb * 2 + 1][1] = r3;
        }

#pragma unroll
        for (int mi = 0; mi < 4; ++mi) {
            uint32_t ah[4], al[4];
            LDSM4(ah[0], ah[1], ah[2], ah[3], sbase + G_AHI + so + aoff + mi * 768);
            LDSM4(al[0], al[1], al[2], al[3], sbase + G_ALO + so + aoff + mi * 768);
#pragma unroll
            for (int ni = 0; ni < 4; ++ni) {
                mma_f16(acc[mi][ni], ah[0], ah[1], ah[2], ah[3], bh[ni][0], bh[ni][1]);
                mma_f16(acc[mi][ni], ah[0], ah[1], ah[2], ah[3], bl[ni][0], bl[ni][1]);
                mma_f16(acc[mi][ni], al[0], al[1], al[2], al[3], bh[ni][0], bh[ni][1]);
            }
        }

        if (kt + 1 < nk) {
            uint32_t* qh = (uint32_t*)(sm + G_AHI + (so ^ GST));
            uint32_t* ql = (uint32_t*)(sm + G_ALO + (so ^ GST));
            uint32_t* rh = (uint32_t*)(sm + G_BHI + (so ^ GST));
            uint32_t* rl = (uint32_t*)(sm + G_BLO + (so ^ GST));
            uint32_t h, l;
            split2(a0.x, a0.y, h, l); qh[sidx + 0] = h; ql[sidx + 0] = l;
            split2(a0.z, a0.w, h, l); qh[sidx + 1] = h; ql[sidx + 1] = l;
            split2(a1.x, a1.y, h, l); qh[sidx + 2] = h; ql[sidx + 2] = l;
            split2(a1.z, a1.w, h, l); qh[sidx + 3] = h; ql[sidx + 3] = l;
            split2(b0.x, b0.y, h, l); rh[sidx + 0] = h; rl[sidx + 0] = l;
            split2(b0.z, b0.w, h, l); rh[sidx + 1] = h; rl[sidx + 1] = l;
            split2(b1.x, b1.y, h, l); rh[sidx + 2] = h; rl[sidx + 2] = l;
            split2(b1.z, b1.w, h, l); rh[sidx + 3] = h; rl[sidx + 3] = l;
        }
        __syncthreads();
    }

#pragma unroll
    for (int mi = 0; mi < 4; ++mi) {
        int ra = bm + wm + mi * 16 + g;
#pragma unroll
        for (int ni = 0; ni < 4; ++ni) {
            int col = bn + wn + ni * 8 + 2 * tig;
            float* c0 = C + (size_t)ra * N + col;
            float* c1 = C + (size_t)(ra + 8) * N + col;
            *(float2*)c0 = make_float2(acc[mi][ni][0], acc[mi][ni][1]);
            *(float2*)c1 = make_float2(acc[mi][ni][2], acc[mi][ni][3]);
        }
    }
}

// ---------------------------------------------------------------------------
// MMA flash attention. Grid (16 row tiles, 64 bh), 256 threads = 8 warps
// (2m x 4n). Scores: fp16 (uncompensated; error suppressed by SC scale).
// PV: hi/lo compensated (3 MMA). SW128-style XOR swizzle on all half tiles.
// Dynamic smem 68096 B.
// ---------------------------------------------------------------------------
#define S_QX 0
#define S_QG 8192
#define S_KX 16384
#define S_KG 24576
#define S_VH 32768
#define S_VL 40960
#define S_PH 49152
#define S_PL 57344
#define S_RM 65536
#define S_RS 66560
#define S_MS 67584
#define S_LS 67840
#define ATT_SMEM 68096

// store 8 fp32 -> 8 fp16 (hi) into swizzled tile; chunk = 8-half column block
__device__ __forceinline__ void st_chunk_hi(uint32_t* p, int row, int chunk,
                                            const float4& f0, const float4& f1) {
    int idx = row * 32 + ((chunk ^ (row & 7)) * 4);
    p[idx + 0] = pack_h2(__float2half_rn(f0.x), __float2half_rn(f0.y));
    p[idx + 1] = pack_h2(__float2half_rn(f0.z), __float2half_rn(f0.w));
    p[idx + 2] = pack_h2(__float2half_rn(f1.x), __float2half_rn(f1.y));
    p[idx + 3] = pack_h2(__float2half_rn(f1.z), __float2half_rn(f1.w));
}
__device__ __forceinline__ void st_chunk_hl(uint32_t* ph, uint32_t* pl, int row, int chunk,
                                            const float4& f0, const float4& f1) {
    int idx = row * 32 + ((chunk ^ (row & 7)) * 4);
    uint32_t h, l;
    split2(f0.x, f0.y, h, l); ph[idx + 0] = h; pl[idx + 0] = l;
    split2(f0.z, f0.w, h, l); ph[idx + 1] = h; pl[idx + 1] = l;
    split2(f1.x, f1.y, h, l); ph[idx + 2] = h; pl[idx + 2] = l;
    split2(f1.z, f1.w, h, l); ph[idx + 3] = h; pl[idx + 3] = l;
}

__global__ __launch_bounds__(256) void attn_mma(const float* __restrict__ qg_in,
                                                const float* __restrict__ kg_in,
                                                float* __restrict__ y) {
    extern __shared__ char sm[];
    const uint32_t sbase = cvta_s(sm);
    float* redM = (float*)(sm + S_RM);   // [4][64]
    float* redS = (float*)(sm + S_RS);   // [4][64]
    float* m_s  = (float*)(sm + S_MS);   // [64]
    float* l_s  = (float*)(sm + S_LS);   // [64]

    const int tid  = threadIdx.x;
    const int warp = tid >> 5, lane = tid & 31;
    const int wmr  = (warp >> 2) * 32;   // warp m base row
    const int wnc  = (warp & 3) * 16;    // warp n base col
    const int bh = blockIdx.y;
    const int b  = bh >> 4;
    const int h  = bh & 15;
    const int rt = blockIdx.x;

    const float SC = 0.125f / 6.931471805599453f;

    // ---- load Q tiles (x path from g_qkv, g path from input), hi only ----
    {
        int row = tid >> 2;
        int c0  = (tid & 3) * 2;             // first of two chunks
        const float* gq = g_qkv + ((size_t)b * L_ + rt * 64 + row) * D3_ + h * HD_ + c0 * 8;
        const float* gg = qg_in + ((size_t)b * L_ + rt * 64 + row) * D_  + h * HD_ + c0 * 8;
        uint32_t* pqx = (uint32_t*)(sm + S_QX);
        uint32_t* pqg = (uint32_t*)(sm + S_QG);
#pragma unroll
        for (int cc = 0; cc < 2; ++cc) {
            float4 f0 = *(const float4*)(gq + cc * 8);
            float4 f1 = *(const float4*)(gq + cc * 8 + 4);
            st_chunk_hi(pqx, row, c0 + cc, f0, f1);
            f0 = *(const float4*)(gg + cc * 8);
            f1 = *(const float4*)(gg + cc * 8 + 4);
            st_chunk_hi(pqg, row, c0 + cc, f0, f1);
        }
    }
    if (tid < 64) { m_s[tid] = -INFINITY; l_s[tid] = 0.f; }

    float oacc[2][2][4];
#pragma unroll
    for (int mi = 0; mi < 2; ++mi)
#pragma unroll
        for (int ni = 0; ni < 2; ++ni)
#pragma unroll
            for (int r = 0; r < 4; ++r) oacc[mi][ni][r] = 0.f;

    const int l4 = lane >> 2;      // 0..7
    const int l2 = lane & 3;       // 0..3

    for (int t = 0; t <= rt; ++t) {
        __syncthreads();   // (A) prev PV done; safe to overwrite K/V
        {
            int row = tid >> 2;
            int c0  = (tid & 3) * 2;
            const float* gk  = g_qkv + ((size_t)b * L_ + t * 64 + row) * D3_ + D_ + h * HD_ + c0 * 8;
            const float* gkg = kg_in + ((size_t)b * L_ + t * 64 + row) * D_  + h * HD_ + c0 * 8;
            const float* gv  = g_qkv + ((size_t)b * L_ + t * 64 + row) * D3_ + 2 * D_ + h * HD_ + c0 * 8;
            uint32_t* pkx = (uint32_t*)(sm + S_KX);
            uint32_t* pkg = (uint32_t*)(sm + S_KG);
            uint32_t* pvh = (uint32_t*)(sm + S_VH);
            uint32_t* pvl = (uint32_t*)(sm + S_VL);
#pragma unroll
            for (int cc = 0; cc < 2; ++cc) {
                float4 f0 = *(const float4*)(gk + cc * 8);
                float4 f1 = *(const float4*)(gk + cc * 8 + 4);
                st_chunk_hi(pkx, row, c0 + cc, f0, f1);
                f0 = *(const float4*)(gkg + cc * 8);
                f1 = *(const float4*)(gkg + cc * 8 + 4);
                st_chunk_hi(pkg, row, c0 + cc, f0, f1);
                f0 = *(const float4*)(gv + cc * 8);
                f1 = *(const float4*)(gv + cc * 8 + 4);
                st_chunk_hl(pvh, pvl, row, c0 + cc, f0, f1);
            }
        }
        __syncthreads();   // (B) K/V visible

        // ---- scores S = (Qx.Kx^T + Qg.Kg^T) ----
        float sacc[2][2][4];
#pragma unroll
        for (int mi = 0; mi < 2; ++mi)
#pragma unroll
            for (int ni = 0; ni < 2; ++ni)
#pragma unroll
                for (int r = 0; r < 4; ++r) sacc[mi][ni][r] = 0.f;

#pragma unroll
        for (int kc = 0; kc < 4; ++kc) {
            // B frags (K): rows = kv index
            int rowB = wnc + (lane & 7) + ((lane >> 4) << 3);
            int chB  = kc * 2 + ((lane >> 3) & 1);
            uint32_t adr = sbase + (uint32_t)(rowB * 128 + ((chB ^ (rowB & 7)) * 16));
            uint32_t kx0, kx1, kx2, kx3, kg0, kg1, kg2, kg3;
            LDSM4(kx0, kx1, kx2, kx3, adr + S_KX);
            LDSM4(kg0, kg1, kg2, kg3, adr + S_KG);
            // A frags (Q)
            int rowA = wmr + (lane & 15);
            int chA  = kc * 2 + (lane >> 4);
#pragma unroll
            for (int mi = 0; mi < 2; ++mi) {
                int rA = rowA + mi * 16;
                uint32_t ada = sbase + (uint32_t)(rA * 128 + ((chA ^ (rA & 7)) * 16));
                uint32_t qx[4], qg[4];
                LDSM4(qx[0], qx[1], qx[2], qx[3], ada + S_QX);
                LDSM4(qg[0], qg[1], qg[2], qg[3], ada + S_QG);
                mma_f16(sacc[mi][0], qx[0], qx[1], qx[2], qx[3], kx0, kx1);
                mma_f16(sacc[mi][1], qx[0], qx[1], qx[2], qx[3], kx2, kx3);
                mma_f16(sacc[mi][0], qg[0], qg[1], qg[2], qg[3], kg0, kg1);
                mma_f16(sacc[mi][1], qg[0], qg[1], qg[2], qg[3], kg2, kg3);
            }
        }

        // scale + causal mask
        const bool diag = (t == rt);
#pragma unroll
        for (int mi = 0; mi < 2; ++mi)
#pragma unroll
            for (int ni = 0; ni < 2; ++ni)
#pragma unroll
                for (int c = 0; c < 4; ++c) {
                    sacc[mi][ni][c] *= SC;
                    if (diag) {
                        int rowl = wmr + mi * 16 + l4 + ((c >> 1) & 1) * 8;
                        int coll = wnc + ni * 8 + 2 * l2 + (c & 1);
                        if (coll > rowl) sacc[mi][ni][c] = -INFINITY;
                    }
                }

        // per-warp row max -> redM[warp_n][row]
#pragma unroll
        for (int mi = 0; mi < 2; ++mi)
#pragma unroll
            for (int rh = 0; rh < 2; ++rh) {
                float mx = fmaxf(fmaxf(sacc[mi][0][rh * 2], sacc[mi][0][rh * 2 + 1]),
                                 fmaxf(sacc[mi][1][rh * 2], sacc[mi][1][rh * 2 + 1]));
                mx = fmaxf(mx, __shfl_xor_sync(0xffffffffu, mx, 1));
                mx = fmaxf(mx, __shfl_xor_sync(0xffffffffu, mx, 2));
                if (l2 == 0)
                    redM[(warp & 3) * 64 + wmr + mi * 16 + l4 + rh * 8] = mx;
            }
        __syncthreads();   // (C)

        // online softmax: p, rescale O, P store, row sums
        uint32_t* pph = (uint32_t*)(sm + S_PH);
        uint32_t* ppl = (uint32_t*)(sm + S_PL);
#pragma unroll
        for (int mi = 0; mi < 2; ++mi)
#pragma unroll
            for (int rh = 0; rh < 2; ++rh) {
                int row = wmr + mi * 16 + l4 + rh * 8;
                float tm = fmaxf(fmaxf(redM[row], redM[64 + row]),
                                 fmaxf(redM[128 + row], redM[192 + row]));
                float mo = m_s[row];
                float mn = fmaxf(mo, tm);
                float alpha = __expf(mo - mn);
                float psum = 0.f;
#pragma unroll
                for (int ni = 0; ni < 2; ++ni) {
                    float p0 = __expf(sacc[mi][ni][rh * 2]     - mn);
                    float p1 = __expf(sacc[mi][ni][rh * 2 + 1] - mn);
                    psum += p0 + p1;
                    // pack hi/lo, store at (row, colpair)
                    uint32_t hi, lo;
                    split2(p0, p1, hi, lo);
                    int col = wnc + ni * 8 + 2 * l2;
                    int idx = row * 32 + (((col >> 3) ^ (row & 7)) * 4) + ((col & 7) >> 1);
                    pph[idx] = hi;
                    ppl[idx] = lo;
                    oacc[mi][ni][rh * 2]     *= alpha;
                    oacc[mi][ni][rh * 2 + 1] *= alpha;
                }
                psum += __shfl_xor_sync(0xffffffffu, psum, 1);
                psum += __shfl_xor_sync(0xffffffffu, psum, 2);
                if (l2 == 0) redS[(warp & 3) * 64 + row] = psum;
            }
        __syncthreads();   // (D) P + redS visible

        // stats update (one thread per row)
        if (tid < 64) {
            int row = tid;
            float tm = fmaxf(fmaxf(redM[row], redM[64 + row]),
                             fmaxf(redM[128 + row], redM[192 + row]));
            float mo = m_s[row];
            float mn = fmaxf(mo, tm);
            float alpha = __expf(mo - mn);
            l_s[row] = l_s[row] * alpha +
                       (redS[row] + redS[64 + row] + redS[128 + row] + redS[192 + row]);
            m_s[row] = mn;
        }

        // ---- PV: O += P.V  (hi/lo compensated) ----
#pragma unroll
        for (int kc = 0; kc < 4; ++kc) {
            // B frags (V, trans): rows = s, chunks = d
            int rowV = kc * 16 + (lane & 7) + (((lane >> 3) & 1) << 3);
            int chV  = (wnc >> 3) + (lane >> 4);
            uint32_t adv = sbase + (uint32_t)(rowV * 128 + ((chV ^ (rowV & 7)) * 16));
            uint32_t vh0, vh1, vh2, vh3, vl0, vl1, vl2, vl3;
            LDSM4T(vh0, vh1, vh2, vh3, adv + S_VH);
            LDSM4T(vl0, vl1, vl2, vl3, adv + S_VL);
            // A frags (P)
            int rowA = wmr + (lane & 15);
            int chA  = kc * 2 + (lane >> 4);
#pragma unroll
            for (int mi = 0; mi < 2; ++mi) {
                int rA = rowA + mi * 16;
                uint32_t ada = sbase + (uint32_t)(rA * 128 + ((chA ^ (rA & 7)) * 16));
                uint32_t ph[4], pl[4];
                LDSM4(ph[0], ph[1], ph[2], ph[3], ada + S_PH);
                LDSM4(pl[0], pl[1], pl[2], pl[3], ada + S_PL);
                mma_f16(oacc[mi][0], ph[0], ph[1], ph[2], ph[3], vh0, vh1);
                mma_f16(oacc[mi][0], ph[0], ph[1], ph[2], ph[3], vl0, vl1);
                mma_f16(oacc[mi][0], pl[0], pl[1], pl[2], pl[3], vh0, vh1);
                mma_f16(oacc[mi][1], ph[0], ph[1], ph[2], ph[3], vh2, vh3);
                mma_f16(oacc[mi][1], ph[0], ph[1], ph[2], ph[3], vl2, vl3);
                mma_f16(oacc[mi][1], pl[0], pl[1], pl[2], pl[3], vh2, vh3);
            }
        }
    }

    __syncthreads();   // final stats visible

    // ---- epilogue: O / l, write y[b, rt*64+row, h*64+d] ----
#pragma unroll
    for (int mi = 0; mi < 2; ++mi)
#pragma unroll
        for (int rh = 0; rh < 2; ++rh) {
            int row = wmr + mi * 16 + l4 + rh * 8;
            float inv = 1.f / l_s[row];
            float* yr = g_y + ((size_t)b * L_ + rt * 64 + row) * D_ + h * HD_;
#pragma unroll
            for (int ni = 0; ni < 2; ++ni) {
                int col = wnc + ni * 8 + 2 * l2;
                *(float2*)(yr + col) = make_float2(oacc[mi][ni][rh * 2] * inv,
                                                   oacc[mi][ni][rh * 2 + 1] * inv);
            }
        }
}

// ---------------------------------------------------------------------------
extern "C" void kernel_launch(void* const* d_in, const int* in_sizes, int n_in,
                              void* d_out, int out_size) {
    const float* x    = (const float*)d_in[0];
    const float* q_g  = (const float*)d_in[1];
    const float* k_g  = (const float*)d_in[2];
    const float* Wqkv = (const float*)d_in[3];
    const float* Wout = (const float*)d_in[4];
    float* out = (float*)d_out;

    float *qkv, *y;
    cudaGetSymbolAddress((void**)&qkv, g_qkv);
    cudaGetSymbolAddress((void**)&y, g_y);

    cudaFuncSetAttribute(tgemm_nt, cudaFuncAttributeMaxDynamicSharedMemorySize, GEMM_SMEM);
    cudaFuncSetAttribute(attn_mma, cudaFuncAttributeMaxDynamicSharedMemorySize, ATT_SMEM);

    // 1) qkv = x @ Wqkv^T
    dim3 g1(D3_ / 128, (B_ * L_) / 128);
    tgemm_nt<<<g1, 256, GEMM_SMEM>>>(x, Wqkv, qkv, B_ * L_, D3_, D_);

    // 2) dual-path causal attention -> y
    attn_mma<<<dim3(16, B_ * H_), 256, ATT_SMEM>>>(q_g, k_g, y);

    // 3) out = y @ Wout^T
    dim3 g3(D_ / 128, (B_ * L_) / 128);
    tgemm_nt<<<g3, 256, GEMM_SMEM>>>(y, Wout, out, B_ * L_, D_, D_);
}

// round 6
// speedup vs baseline: 2.6136x; 1.0213x over previous
#include <cuda_runtime.h>
#include <cuda_fp16.h>
#include <math.h>
#include <stdint.h>

#define B_  4
#define L_  1024
#define D_  1024
#define H_  16
#define HD_ 64
#define D3_ 3072

// Scratch (allocation-free rule: device globals)
__device__ float g_qkv[(size_t)B_ * L_ * D3_];   // [B,L,3D]  q|k|v (fp32)
__device__ float g_y[(size_t)B_ * L_ * D_];      // [B,L,D]   attention out (fp32)
// fp16 hi/lo split buffers
__device__ __half g_xh[(size_t)B_ * L_ * D_],  g_xl[(size_t)B_ * L_ * D_];
__device__ __half g_wqh[(size_t)D3_ * D_],     g_wql[(size_t)D3_ * D_];
__device__ __half g_woh[(size_t)D_ * D_],      g_wol[(size_t)D_ * D_];
__device__ __half g_yh[(size_t)B_ * L_ * D_],  g_yl[(size_t)B_ * L_ * D_];

// ---------------------------------------------------------------------------
// helpers
// ---------------------------------------------------------------------------
__device__ __forceinline__ uint32_t cvta_s(const void* p) {
    return (uint32_t)__cvta_generic_to_shared(p);
}
__device__ __forceinline__ uint32_t pack_h2(__half a, __half b) {
    __half2 h = __halves2half2(a, b);
    return *(uint32_t*)&h;
}
__device__ __forceinline__ void split2(float x0, float x1, uint32_t& hi, uint32_t& lo) {
    __half h0 = __float2half_rn(x0);
    __half h1 = __float2half_rn(x1);
    __half l0 = __float2half_rn(x0 - __half2float(h0));
    __half l1 = __float2half_rn(x1 - __half2float(h1));
    hi = pack_h2(h0, h1);
    lo = pack_h2(l0, l1);
}
__device__ __forceinline__ void mma_f16(float* c,
                                        uint32_t a0, uint32_t a1, uint32_t a2, uint32_t a3,
                                        uint32_t b0, uint32_t b1) {
    asm volatile(
        "mma.sync.aligned.m16n8k16.row.col.f32.f16.f16.f32 "
        "{%0,%1,%2,%3},{%4,%5,%6,%7},{%8,%9},{%0,%1,%2,%3};\n"
        : "+f"(c[0]), "+f"(c[1]), "+f"(c[2]), "+f"(c[3])
        : "r"(a0), "r"(a1), "r"(a2), "r"(a3), "r"(b0), "r"(b1));
}
#define LDSM4(r0, r1, r2, r3, addr) \
    asm volatile("ldmatrix.sync.aligned.m8n8.x4.shared.b16 {%0,%1,%2,%3},[%4];\n" \
                 : "=r"(r0), "=r"(r1), "=r"(r2), "=r"(r3) : "r"(addr))
#define LDSM4T(r0, r1, r2, r3, addr) \
    asm volatile("ldmatrix.sync.aligned.m8n8.x4.trans.shared.b16 {%0,%1,%2,%3},[%4];\n" \
                 : "=r"(r0), "=r"(r1), "=r"(r2), "=r"(r3) : "r"(addr))
#define CP16(saddr, gptr) \
    asm volatile("cp.async.cg.shared.global [%0], [%1], 16;\n" :: "r"(saddr), "l"(gptr))
#define CP_COMMIT() asm volatile("cp.async.commit_group;\n")
#define CP_WAIT2()  asm volatile("cp.async.wait_group 2;\n")

// ---------------------------------------------------------------------------
// split fp32 -> fp16 hi + fp16 lo (residual), vectorized
// ---------------------------------------------------------------------------
__global__ __launch_bounds__(256) void split_kernel(const float4* __restrict__ in,
                                                    uint2* __restrict__ hi,
                                                    uint2* __restrict__ lo, int n4) {
    int i = blockIdx.x * blockDim.x + threadIdx.x;
    if (i >= n4) return;
    float4 v = in[i];
    uint32_t h0, l0, h1, l1;
    split2(v.x, v.y, h0, l0);
    split2(v.z, v.w, h1, l1);
    hi[i] = make_uint2(h0, h1);
    lo[i] = make_uint2(l0, l1);
}

// ---------------------------------------------------------------------------
// Tensor-core GEMM (NT) on pre-split fp16 hi/lo operands.
// C[m,n] = sum_k A[m,k]*B[n,k] with 3-MMA compensation.
// 128x128 tile, BK=16, 8 warps (2m x 4n) warp tile 64x32.
// cp.async 4-stage pipeline; XOR-swizzled 32B rows; ldmatrix reads.
// Stage layout: [stage 16KB][Ahi 4K | Alo 4K | Bhi 4K | Blo 4K]
// ---------------------------------------------------------------------------
#define STAGE_B 16384
#define GEMM_SMEM 65536

__global__ __launch_bounds__(256) void tgemm_h(const __half* __restrict__ Ah,
                                               const __half* __restrict__ Al,
                                               const __half* __restrict__ Bh,
                                               const __half* __restrict__ Bl,
                                               float* __restrict__ C,
                                               int M, int N, int K) {
    extern __shared__ char sm[];
    const uint32_t sbase = cvta_s(sm);

    const int tid  = threadIdx.x;
    const int warp = tid >> 5, lane = tid & 31;
    const int g = lane >> 2, tig = lane & 3;
    const int wm = (warp >> 2) * 64;
    const int wn = (warp & 3) * 32;
    const int bm = blockIdx.y * 128, bn = blockIdx.x * 128;

    // ---- cp.async assignments: arr = which operand array, 4 x 16B each ----
    const int arr = tid >> 6;            // 0 Ahi, 1 Alo, 2 Bhi, 3 Blo
    const int t2  = tid & 63;
    const __half* gsrc = (arr == 0) ? Ah + (size_t)bm * K :
                         (arr == 1) ? Al + (size_t)bm * K :
                         (arr == 2) ? Bh + (size_t)bn * K :
                                      Bl + (size_t)bn * K;
    int rows[4], csrc[4];
    uint32_t soff[4];
#pragma unroll
    for (int i = 0; i < 4; ++i) {
        int u = t2 + 64 * i;             // 0..255
        int r = u >> 1, c = u & 1;
        rows[i] = r; csrc[i] = c;
        soff[i] = (uint32_t)(arr * 4096 + r * 32 + ((c ^ ((r >> 2) & 1)) * 16));
    }

    // ---- ldmatrix offsets (stage-relative) ----
    uint32_t aoff[4];
#pragma unroll
    for (int mi = 0; mi < 4; ++mi) {
        int r = wm + mi * 16 + (lane & 15);
        int c = lane >> 4;
        aoff[mi] = (uint32_t)(r * 32 + ((c ^ ((r >> 2) & 1)) * 16));
    }
    uint32_t boff[2];
#pragma unroll
    for (int nb = 0; nb < 2; ++nb) {
        int r = wn + nb * 16 + (lane & 7) + ((lane >> 4) << 3);
        int c = (lane >> 3) & 1;
        boff[nb] = (uint32_t)(8192 + r * 32 + ((c ^ ((r >> 2) & 1)) * 16));
    }

    float acc[4][4][4];
#pragma unroll
    for (int mi = 0; mi < 4; ++mi)
#pragma unroll
        for (int ni = 0; ni < 4; ++ni)
#pragma unroll
            for (int r = 0; r < 4; ++r) acc[mi][ni][r] = 0.f;

    const int nk = K >> 4;

    // prologue: stages 0..2
#pragma unroll
    for (int s = 0; s < 3; ++s) {
        const uint32_t sb = sbase + s * STAGE_B;
#pragma unroll
        for (int i = 0; i < 4; ++i)
            CP16(sb + soff[i], gsrc + (size_t)rows[i] * K + s * 16 + csrc[i] * 8);
        CP_COMMIT();
    }
    CP_WAIT2();
    __syncthreads();

    for (int kt = 0; kt < nk; ++kt) {
        const uint32_t stg = sbase + (uint32_t)(kt & 3) * STAGE_B;

        // B fragments (hi+lo) for 4 n-octets
        uint32_t bh[4][2], bl[4][2];
#pragma unroll
        for (int nb = 0; nb < 2; ++nb) {
            uint32_t r0, r1, r2, r3;
            LDSM4(r0, r1, r2, r3, stg + boff[nb]);
            bh[nb * 2][0] = r0; bh[nb * 2][1] = r1;
            bh[nb * 2 + 1][0] = r2; bh[nb * 2 + 1][1] = r3;
            LDSM4(r0, r1, r2, r3, stg + boff[nb] + 4096);
            bl[nb * 2][0] = r0; bl[nb * 2][1] = r1;
            bl[nb * 2 + 1][0] = r2; bl[nb * 2 + 1][1] = r3;
        }

#pragma unroll
        for (int mi = 0; mi < 4; ++mi) {
            uint32_t ah[4], al[4];
            LDSM4(ah[0], ah[1], ah[2], ah[3], stg + aoff[mi]);
            LDSM4(al[0], al[1], al[2], al[3], stg + aoff[mi] + 4096);
#pragma unroll
            for (int ni = 0; ni < 4; ++ni) {
                mma_f16(acc[mi][ni], ah[0], ah[1], ah[2], ah[3], bh[ni][0], bh[ni][1]);
                mma_f16(acc[mi][ni], ah[0], ah[1], ah[2], ah[3], bl[ni][0], bl[ni][1]);
                mma_f16(acc[mi][ni], al[0], al[1], al[2], al[3], bh[ni][0], bh[ni][1]);
            }
        }

        // issue next chunk into the stage just freed
        if (kt + 3 < nk) {
            const uint32_t sb = sbase + (uint32_t)((kt + 3) & 3) * STAGE_B;
#pragma unroll
            for (int i = 0; i < 4; ++i)
                CP16(sb + soff[i], gsrc + (size_t)rows[i] * K + (kt + 3) * 16 + csrc[i] * 8);
        }
        CP_COMMIT();
        CP_WAIT2();
        __syncthreads();
    }

    // epilogue
#pragma unroll
    for (int mi = 0; mi < 4; ++mi) {
        int ra = bm + wm + mi * 16 + g;
#pragma unroll
        for (int ni = 0; ni < 4; ++ni) {
            int col = bn + wn + ni * 8 + 2 * tig;
            float* c0 = C + (size_t)ra * N + col;
            float* c1 = C + (size_t)(ra + 8) * N + col;
            *(float2*)c0 = make_float2(acc[mi][ni][0], acc[mi][ni][1]);
            *(float2*)c1 = make_float2(acc[mi][ni][2], acc[mi][ni][3]);
        }
    }
}

// ---------------------------------------------------------------------------
// MMA flash attention (unchanged from R5 passing version).
// ---------------------------------------------------------------------------
#define S_QX 0
#define S_QG 8192
#define S_KX 16384
#define S_KG 24576
#define S_VH 32768
#define S_VL 40960
#define S_PH 49152
#define S_PL 57344
#define S_RM 65536
#define S_RS 66560
#define S_MS 67584
#define S_LS 67840
#define ATT_SMEM 68096

__device__ __forceinline__ void st_chunk_hi(uint32_t* p, int row, int chunk,
                                            const float4& f0, const float4& f1) {
    int idx = row * 32 + ((chunk ^ (row & 7)) * 4);
    p[idx + 0] = pack_h2(__float2half_rn(f0.x), __float2half_rn(f0.y));
    p[idx + 1] = pack_h2(__float2half_rn(f0.z), __float2half_rn(f0.w));
    p[idx + 2] = pack_h2(__float2half_rn(f1.x), __float2half_rn(f1.y));
    p[idx + 3] = pack_h2(__float2half_rn(f1.z), __float2half_rn(f1.w));
}
__device__ __forceinline__ void st_chunk_hl(uint32_t* ph, uint32_t* pl, int row, int chunk,
                                            const float4& f0, const float4& f1) {
    int idx = row * 32 + ((chunk ^ (row & 7)) * 4);
    uint32_t h, l;
    split2(f0.x, f0.y, h, l); ph[idx + 0] = h; pl[idx + 0] = l;
    split2(f0.z, f0.w, h, l); ph[idx + 1] = h; pl[idx + 1] = l;
    split2(f1.x, f1.y, h, l); ph[idx + 2] = h; pl[idx + 2] = l;
    split2(f1.z, f1.w, h, l); ph[idx + 3] = h; pl[idx + 3] = l;
}

__global__ __launch_bounds__(256) void attn_mma(const float* __restrict__ qg_in,
                                                const float* __restrict__ kg_in,
                                                float* __restrict__ y) {
    extern __shared__ char sm[];
    const uint32_t sbase = cvta_s(sm);
    float* redM = (float*)(sm + S_RM);
    float* redS = (float*)(sm + S_RS);
    float* m_s  = (float*)(sm + S_MS);
    float* l_s  = (float*)(sm + S_LS);

    const int tid  = threadIdx.x;
    const int warp = tid >> 5, lane = tid & 31;
    const int wmr  = (warp >> 2) * 32;
    const int wnc  = (warp & 3) * 16;
    const int bh = blockIdx.y;
    const int b  = bh >> 4;
    const int h  = bh & 15;
    const int rt = blockIdx.x;

    const float SC = 0.125f / 6.931471805599453f;

    {
        int row = tid >> 2;
        int c0  = (tid & 3) * 2;
        const float* gq = g_qkv + ((size_t)b * L_ + rt * 64 + row) * D3_ + h * HD_ + c0 * 8;
        const float* gg = qg_in + ((size_t)b * L_ + rt * 64 + row) * D_  + h * HD_ + c0 * 8;
        uint32_t* pqx = (uint32_t*)(sm + S_QX);
        uint32_t* pqg = (uint32_t*)(sm + S_QG);
#pragma unroll
        for (int cc = 0; cc < 2; ++cc) {
            float4 f0 = *(const float4*)(gq + cc * 8);
            float4 f1 = *(const float4*)(gq + cc * 8 + 4);
            st_chunk_hi(pqx, row, c0 + cc, f0, f1);
            f0 = *(const float4*)(gg + cc * 8);
            f1 = *(const float4*)(gg + cc * 8 + 4);
            st_chunk_hi(pqg, row, c0 + cc, f0, f1);
        }
    }
    if (tid < 64) { m_s[tid] = -INFINITY; l_s[tid] = 0.f; }

    float oacc[2][2][4];
#pragma unroll
    for (int mi = 0; mi < 2; ++mi)
#pragma unroll
        for (int ni = 0; ni < 2; ++ni)
#pragma unroll
            for (int r = 0; r < 4; ++r) oacc[mi][ni][r] = 0.f;

    const int l4 = lane >> 2;
    const int l2 = lane & 3;

    for (int t = 0; t <= rt; ++t) {
        __syncthreads();
        {
            int row = tid >> 2;
            int c0  = (tid & 3) * 2;
            const float* gk  = g_qkv + ((size_t)b * L_ + t * 64 + row) * D3_ + D_ + h * HD_ + c0 * 8;
            const float* gkg = kg_in + ((size_t)b * L_ + t * 64 + row) * D_  + h * HD_ + c0 * 8;
            const float* gv  = g_qkv + ((size_t)b * L_ + t * 64 + row) * D3_ + 2 * D_ + h * HD_ + c0 * 8;
            uint32_t* pkx = (uint32_t*)(sm + S_KX);
            uint32_t* pkg = (uint32_t*)(sm + S_KG);
            uint32_t* pvh = (uint32_t*)(sm + S_VH);
            uint32_t* pvl = (uint32_t*)(sm + S_VL);
#pragma unroll
            for (int cc = 0; cc < 2; ++cc) {
                float4 f0 = *(const float4*)(gk + cc * 8);
                float4 f1 = *(const float4*)(gk + cc * 8 + 4);
                st_chunk_hi(pkx, row, c0 + cc, f0, f1);
                f0 = *(const float4*)(gkg + cc * 8);
                f1 = *(const float4*)(gkg + cc * 8 + 4);
                st_chunk_hi(pkg, row, c0 + cc, f0, f1);
                f0 = *(const float4*)(gv + cc * 8);
                f1 = *(const float4*)(gv + cc * 8 + 4);
                st_chunk_hl(pvh, pvl, row, c0 + cc, f0, f1);
            }
        }
        __syncthreads();

        float sacc[2][2][4];
#pragma unroll
        for (int mi = 0; mi < 2; ++mi)
#pragma unroll
            for (int ni = 0; ni < 2; ++ni)
#pragma unroll
                for (int r = 0; r < 4; ++r) sacc[mi][ni][r] = 0.f;

#pragma unroll
        for (int kc = 0; kc < 4; ++kc) {
            int rowB = wnc + (lane & 7) + ((lane >> 4) << 3);
            int chB  = kc * 2 + ((lane >> 3) & 1);
            uint32_t adr = sbase + (uint32_t)(rowB * 128 + ((chB ^ (rowB & 7)) * 16));
            uint32_t kx0, kx1, kx2, kx3, kg0, kg1, kg2, kg3;
            LDSM4(kx0, kx1, kx2, kx3, adr + S_KX);
            LDSM4(kg0, kg1, kg2, kg3, adr + S_KG);
            int rowA = wmr + (lane & 15);
            int chA  = kc * 2 + (lane >> 4);
#pragma unroll
            for (int mi = 0; mi < 2; ++mi) {
                int rA = rowA + mi * 16;
                uint32_t ada = sbase + (uint32_t)(rA * 128 + ((chA ^ (rA & 7)) * 16));
                uint32_t qx[4], qg[4];
                LDSM4(qx[0], qx[1], qx[2], qx[3], ada + S_QX);
                LDSM4(qg[0], qg[1], qg[2], qg[3], ada + S_QG);
                mma_f16(sacc[mi][0], qx[0], qx[1], qx[2], qx[3], kx0, kx1);
                mma_f16(sacc[mi][1], qx[0], qx[1], qx[2], qx[3], kx2, kx3);
                mma_f16(sacc[mi][0], qg[0], qg[1], qg[2], qg[3], kg0, kg1);
                mma_f16(sacc[mi][1], qg[0], qg[1], qg[2], qg[3], kg2, kg3);
            }
        }

        const bool diag = (t == rt);
#pragma unroll
        for (int mi = 0; mi < 2; ++mi)
#pragma unroll
            for (int ni = 0; ni < 2; ++ni)
#pragma unroll
                for (int c = 0; c < 4; ++c) {
                    sacc[mi][ni][c] *= SC;
                    if (diag) {
                        int rowl = wmr + mi * 16 + l4 + ((c >> 1) & 1) * 8;
                        int coll = wnc + ni * 8 + 2 * l2 + (c & 1);
                        if (coll > rowl) sacc[mi][ni][c] = -INFINITY;
                    }
                }

#pragma unroll
        for (int mi = 0; mi < 2; ++mi)
#pragma unroll
            for (int rh = 0; rh < 2; ++rh) {
                float mx = fmaxf(fmaxf(sacc[mi][0][rh * 2], sacc[mi][0][rh * 2 + 1]),
                                 fmaxf(sacc[mi][1][rh * 2], sacc[mi][1][rh * 2 + 1]));
                mx = fmaxf(mx, __shfl_xor_sync(0xffffffffu, mx, 1));
                mx = fmaxf(mx, __shfl_xor_sync(0xffffffffu, mx, 2));
                if (l2 == 0)
                    redM[(warp & 3) * 64 + wmr + mi * 16 + l4 + rh * 8] = mx;
            }
        __syncthreads();

        uint32_t* pph = (uint32_t*)(sm + S_PH);
        uint32_t* ppl = (uint32_t*)(sm + S_PL);
#pragma unroll
        for (int mi = 0; mi < 2; ++mi)
#pragma unroll
            for (int rh = 0; rh < 2; ++rh) {
                int row = wmr + mi * 16 + l4 + rh * 8;
                float tm = fmaxf(fmaxf(redM[row], redM[64 + row]),
                                 fmaxf(redM[128 + row], redM[192 + row]));
                float mo = m_s[row];
                float mn = fmaxf(mo, tm);
                float alpha = __expf(mo - mn);
                float psum = 0.f;
#pragma unroll
                for (int ni = 0; ni < 2; ++ni) {
                    float p0 = __expf(sacc[mi][ni][rh * 2]     - mn);
                    float p1 = __expf(sacc[mi][ni][rh * 2 + 1] - mn);
                    psum += p0 + p1;
                    uint32_t hi, lo;
                    split2(p0, p1, hi, lo);
                    int col = wnc + ni * 8 + 2 * l2;
                    int idx = row * 32 + (((col >> 3) ^ (row & 7)) * 4) + ((col & 7) >> 1);
                    pph[idx] = hi;
                    ppl[idx] = lo;
                    oacc[mi][ni][rh * 2]     *= alpha;
                    oacc[mi][ni][rh * 2 + 1] *= alpha;
                }
                psum += __shfl_xor_sync(0xffffffffu, psum, 1);
                psum += __shfl_xor_sync(0xffffffffu, psum, 2);
                if (l2 == 0) redS[(warp & 3) * 64 + row] = psum;
            }
        __syncthreads();

        if (tid < 64) {
            int row = tid;
            float tm = fmaxf(fmaxf(redM[row], redM[64 + row]),
                             fmaxf(redM[128 + row], redM[192 + row]));
            float mo = m_s[row];
            float mn = fmaxf(mo, tm);
            float alpha = __expf(mo - mn);
            l_s[row] = l_s[row] * alpha +
                       (redS[row] + redS[64 + row] + redS[128 + row] + redS[192 + row]);
            m_s[row] = mn;
        }

#pragma unroll
        for (int kc = 0; kc < 4; ++kc) {
            int rowV = kc * 16 + (lane & 7) + (((lane >> 3) & 1) << 3);
            int chV  = (wnc >> 3) + (lane >> 4);
            uint32_t adv = sbase + (uint32_t)(rowV * 128 + ((chV ^ (rowV & 7)) * 16));
            uint32_t vh0, vh1, vh2, vh3, vl0, vl1, vl2, vl3;
            LDSM4T(vh0, vh1, vh2, vh3, adv + S_VH);
            LDSM4T(vl0, vl1, vl2, vl3, adv + S_VL);
            int rowA = wmr + (lane & 15);
            int chA  = kc * 2 + (lane >> 4);
#pragma unroll
            for (int mi = 0; mi < 2; ++mi) {
                int rA = rowA + mi * 16;
                uint32_t ada = sbase + (uint32_t)(rA * 128 + ((chA ^ (rA & 7)) * 16));
                uint32_t ph[4], pl[4];
                LDSM4(ph[0], ph[1], ph[2], ph[3], ada + S_PH);
                LDSM4(pl[0], pl[1], pl[2], pl[3], ada + S_PL);
                mma_f16(oacc[mi][0], ph[0], ph[1], ph[2], ph[3], vh0, vh1);
                mma_f16(oacc[mi][0], ph[0], ph[1], ph[2], ph[3], vl0, vl1);
                mma_f16(oacc[mi][0], pl[0], pl[1], pl[2], pl[3], vh0, vh1);
                mma_f16(oacc[mi][1], ph[0], ph[1], ph[2], ph[3], vh2, vh3);
                mma_f16(oacc[mi][1], ph[0], ph[1], ph[2], ph[3], vl2, vl3);
                mma_f16(oacc[mi][1], pl[0], pl[1], pl[2], pl[3], vh2, vh3);
            }
        }
    }

    __syncthreads();

#pragma unroll
    for (int mi = 0; mi < 2; ++mi)
#pragma unroll
        for (int rh = 0; rh < 2; ++rh) {
            int row = wmr + mi * 16 + l4 + rh * 8;
            float inv = 1.f / l_s[row];
            float* yr = y + ((size_t)b * L_ + rt * 64 + row) * D_ + h * HD_;
#pragma unroll
            for (int ni = 0; ni < 2; ++ni) {
                int col = wnc + ni * 8 + 2 * l2;
                *(float2*)(yr + col) = make_float2(oacc[mi][ni][rh * 2] * inv,
                                                   oacc[mi][ni][rh * 2 + 1] * inv);
            }
        }
}

// ---------------------------------------------------------------------------
extern "C" void kernel_launch(void* const* d_in, const int* in_sizes, int n_in,
                              void* d_out, int out_size) {
    const float* x    = (const float*)d_in[0];
    const float* q_g  = (const float*)d_in[1];
    const float* k_g  = (const float*)d_in[2];
    const float* Wqkv = (const float*)d_in[3];
    const float* Wout = (const float*)d_in[4];
    float* out = (float*)d_out;

    float *qkv, *y;
    __half *xh, *xl, *wqh, *wql, *woh, *wol, *yh, *yl;
    cudaGetSymbolAddress((void**)&qkv, g_qkv);
    cudaGetSymbolAddress((void**)&y,   g_y);
    cudaGetSymbolAddress((void**)&xh,  g_xh);
    cudaGetSymbolAddress((void**)&xl,  g_xl);
    cudaGetSymbolAddress((void**)&wqh, g_wqh);
    cudaGetSymbolAddress((void**)&wql, g_wql);
    cudaGetSymbolAddress((void**)&woh, g_woh);
    cudaGetSymbolAddress((void**)&wol, g_wol);
    cudaGetSymbolAddress((void**)&yh,  g_yh);
    cudaGetSymbolAddress((void**)&yl,  g_yl);

    cudaFuncSetAttribute(tgemm_h, cudaFuncAttributeMaxDynamicSharedMemorySize, GEMM_SMEM);
    cudaFuncSetAttribute(attn_mma, cudaFuncAttributeMaxDynamicSharedMemorySize, ATT_SMEM);

    const int NX = B_ * L_ * D_ / 4;      // 1M float4
    const int NWQ = D3_ * D_ / 4;
    const int NWO = D_ * D_ / 4;

    // 0) splits for projection 1
    split_kernel<<<(NX + 255) / 256, 256>>>((const float4*)x, (uint2*)xh, (uint2*)xl, NX);
    split_kernel<<<(NWQ + 255) / 256, 256>>>((const float4*)Wqkv, (uint2*)wqh, (uint2*)wql, NWQ);

    // 1) qkv = x @ Wqkv^T
    dim3 g1(D3_ / 128, (B_ * L_) / 128);
    tgemm_h<<<g1, 256, GEMM_SMEM>>>(xh, xl, wqh, wql, qkv, B_ * L_, D3_, D_);

    // 2) dual-path causal attention -> y
    attn_mma<<<dim3(16, B_ * H_), 256, ATT_SMEM>>>(q_g, k_g, y);

    // 3) splits for projection 2
    split_kernel<<<(NX + 255) / 256, 256>>>((const float4*)y, (uint2*)yh, (uint2*)yl, NX);
    split_kernel<<<(NWO + 255) / 256, 256>>>((const float4*)Wout, (uint2*)woh, (uint2*)wol, NWO);

    // 4) out = y @ Wout^T
    dim3 g3(D_ / 128, (B_ * L_) / 128);
    tgemm_h<<<g3, 256, GEMM_SMEM>>>(yh, yl, woh, wol, out, B_ * L_, D_, D_);
}

// round 8
// speedup vs baseline: 3.1533x; 1.2065x over previous
#include <cuda_runtime.h>
#include <cuda_fp16.h>
#include <math.h>
#include <stdint.h>

#define B_  4
#define L_  1024
#define D_  1024
#define H_  16
#define HD_ 64
#define D3_ 3072

// ---------------------------------------------------------------------------
// Scratch (device globals; no allocation)
// ---------------------------------------------------------------------------
__device__ __half g_xh[(size_t)B_ * L_ * D_],  g_xl[(size_t)B_ * L_ * D_];
__device__ __half g_wqh[(size_t)D3_ * D_],     g_wql[(size_t)D3_ * D_];
__device__ __half g_woh[(size_t)D_ * D_],      g_wol[(size_t)D_ * D_];
__device__ __half g_qh[(size_t)B_ * L_ * D_];
__device__ __half g_kh[(size_t)B_ * L_ * D_];
__device__ __half g_vh[(size_t)B_ * L_ * D_],  g_vl[(size_t)B_ * L_ * D_];
__device__ __half g_qgh[(size_t)B_ * L_ * D_], g_kgh[(size_t)B_ * L_ * D_];
__device__ __half g_yh[(size_t)B_ * L_ * D_],  g_yl[(size_t)B_ * L_ * D_];

// ---------------------------------------------------------------------------
// helpers
// ---------------------------------------------------------------------------
__device__ __forceinline__ uint32_t cvta_s(const void* p) {
    return (uint32_t)__cvta_generic_to_shared(p);
}
__device__ __forceinline__ uint32_t pack_h2(__half a, __half b) {
    __half2 h = __halves2half2(a, b);
    return *(uint32_t*)&h;
}
__device__ __forceinline__ void split2(float x0, float x1, uint32_t& hi, uint32_t& lo) {
    __half h0 = __float2half_rn(x0);
    __half h1 = __float2half_rn(x1);
    __half l0 = __float2half_rn(x0 - __half2float(h0));
    __half l1 = __float2half_rn(x1 - __half2float(h1));
    hi = pack_h2(h0, h1);
    lo = pack_h2(l0, l1);
}
__device__ __forceinline__ void mma_f16(float* c,
                                        uint32_t a0, uint32_t a1, uint32_t a2, uint32_t a3,
                                        uint32_t b0, uint32_t b1) {
    asm volatile(
        "mma.sync.aligned.m16n8k16.row.col.f32.f16.f16.f32 "
        "{%0,%1,%2,%3},{%4,%5,%6,%7},{%8,%9},{%0,%1,%2,%3};\n"
        : "+f"(c[0]), "+f"(c[1]), "+f"(c[2]), "+f"(c[3])
        : "r"(a0), "r"(a1), "r"(a2), "r"(a3), "r"(b0), "r"(b1));
}
#define LDSM4(r0, r1, r2, r3, addr) \
    asm volatile("ldmatrix.sync.aligned.m8n8.x4.shared.b16 {%0,%1,%2,%3},[%4];\n" \
                 : "=r"(r0), "=r"(r1), "=r"(r2), "=r"(r3) : "r"(addr))
#define LDSM4T(r0, r1, r2, r3, addr) \
    asm volatile("ldmatrix.sync.aligned.m8n8.x4.trans.shared.b16 {%0,%1,%2,%3},[%4];\n" \
                 : "=r"(r0), "=r"(r1), "=r"(r2), "=r"(r3) : "r"(addr))
#define CP16(saddr, gptr) \
    asm volatile("cp.async.cg.shared.global [%0], [%1], 16;\n" :: "r"(saddr), "l"(gptr))
#define CP_COMMIT() asm volatile("cp.async.commit_group;\n")
#define CP_WAIT0()  asm volatile("cp.async.wait_group 0;\n")
#define CP_WAIT2()  asm volatile("cp.async.wait_group 2;\n")

// ---------------------------------------------------------------------------
// split kernels
// ---------------------------------------------------------------------------
__global__ __launch_bounds__(256) void split_kernel(const float4* __restrict__ in,
                                                    uint2* __restrict__ hi,
                                                    uint2* __restrict__ lo, int n4) {
    int i = blockIdx.x * blockDim.x + threadIdx.x;
    if (i >= n4) return;
    float4 v = in[i];
    uint32_t h0, l0, h1, l1;
    split2(v.x, v.y, h0, l0);
    split2(v.z, v.w, h1, l1);
    hi[i] = make_uint2(h0, h1);
    lo[i] = make_uint2(l0, l1);
}
__global__ __launch_bounds__(256) void split_hi_kernel(const float4* __restrict__ in,
                                                       uint2* __restrict__ hi, int n4) {
    int i = blockIdx.x * blockDim.x + threadIdx.x;
    if (i >= n4) return;
    float4 v = in[i];
    hi[i] = make_uint2(pack_h2(__float2half_rn(v.x), __float2half_rn(v.y)),
                       pack_h2(__float2half_rn(v.z), __float2half_rn(v.w)));
}

// ---------------------------------------------------------------------------
// Tensor-core GEMM (NT) on pre-split fp16 hi/lo. 3-MMA compensation.
// 128x128 tile, BK=16, 8 warps (2m x 4n). cp.async 4-stage, swizzled rows.
// MODE 0: write fp32 C. MODE 1: qkv-split epilogue (q,k hi fp16; v hi+lo).
// ---------------------------------------------------------------------------
#define STAGE_B 16384
#define GEMM_SMEM 65536

template <int MODE>
__global__ __launch_bounds__(256) void tgemm_h(const __half* __restrict__ Ah,
                                               const __half* __restrict__ Al,
                                               const __half* __restrict__ Bh,
                                               const __half* __restrict__ Bl,
                                               float* __restrict__ C,
                                               __half* __restrict__ Qo,
                                               __half* __restrict__ Ko,
                                               __half* __restrict__ Vho,
                                               __half* __restrict__ Vlo,
                                               int M, int N, int K) {
    extern __shared__ char sm[];
    const uint32_t sbase = cvta_s(sm);

    const int tid  = threadIdx.x;
    const int warp = tid >> 5, lane = tid & 31;
    const int g = lane >> 2, tig = lane & 3;
    const int wm = (warp >> 2) * 64;
    const int wn = (warp & 3) * 32;
    const int bm = blockIdx.y * 128, bn = blockIdx.x * 128;

    const int arr = tid >> 6;
    const int t2  = tid & 63;
    const __half* gsrc = (arr == 0) ? Ah + (size_t)bm * K :
                         (arr == 1) ? Al + (size_t)bm * K :
                         (arr == 2) ? Bh + (size_t)bn * K :
                                      Bl + (size_t)bn * K;
    int rows[4], csrc[4];
    uint32_t soff[4];
#pragma unroll
    for (int i = 0; i < 4; ++i) {
        int u = t2 + 64 * i;
        int r = u >> 1, c = u & 1;
        rows[i] = r; csrc[i] = c;
        soff[i] = (uint32_t)(arr * 4096 + r * 32 + ((c ^ ((r >> 2) & 1)) * 16));
    }

    uint32_t aoff[4];
#pragma unroll
    for (int mi = 0; mi < 4; ++mi) {
        int r = wm + mi * 16 + (lane & 15);
        int c = lane >> 4;
        aoff[mi] = (uint32_t)(r * 32 + ((c ^ ((r >> 2) & 1)) * 16));
    }
    uint32_t boff[2];
#pragma unroll
    for (int nb = 0; nb < 2; ++nb) {
        int r = wn + nb * 16 + (lane & 7) + ((lane >> 4) << 3);
        int c = (lane >> 3) & 1;
        boff[nb] = (uint32_t)(8192 + r * 32 + ((c ^ ((r >> 2) & 1)) * 16));
    }

    float acc[4][4][4];
#pragma unroll
    for (int mi = 0; mi < 4; ++mi)
#pragma unroll
        for (int ni = 0; ni < 4; ++ni)
#pragma unroll
            for (int r = 0; r < 4; ++r) acc[mi][ni][r] = 0.f;

    const int nk = K >> 4;
#pragma unroll
    for (int s = 0; s < 3; ++s) {
        const uint32_t sb = sbase + s * STAGE_B;
#pragma unroll
        for (int i = 0; i < 4; ++i)
            CP16(sb + soff[i], gsrc + (size_t)rows[i] * K + s * 16 + csrc[i] * 8);
        CP_COMMIT();
    }
    CP_WAIT2();
    __syncthreads();

    for (int kt = 0; kt < nk; ++kt) {
        const uint32_t stg = sbase + (uint32_t)(kt & 3) * STAGE_B;

        uint32_t bh[4][2], bl[4][2];
#pragma unroll
        for (int nb = 0; nb < 2; ++nb) {
            uint32_t r0, r1, r2, r3;
            LDSM4(r0, r1, r2, r3, stg + boff[nb]);
            bh[nb * 2][0] = r0; bh[nb * 2][1] = r1;
            bh[nb * 2 + 1][0] = r2; bh[nb * 2 + 1][1] = r3;
            LDSM4(r0, r1, r2, r3, stg + boff[nb] + 4096);
            bl[nb * 2][0] = r0; bl[nb * 2][1] = r1;
            bl[nb * 2 + 1][0] = r2; bl[nb * 2 + 1][1] = r3;
        }

#pragma unroll
        for (int mi = 0; mi < 4; ++mi) {
            uint32_t ah[4], al[4];
            LDSM4(ah[0], ah[1], ah[2], ah[3], stg + aoff[mi]);
            LDSM4(al[0], al[1], al[2], al[3], stg + aoff[mi] + 4096);
#pragma unroll
            for (int ni = 0; ni < 4; ++ni) {
                mma_f16(acc[mi][ni], ah[0], ah[1], ah[2], ah[3], bh[ni][0], bh[ni][1]);
                mma_f16(acc[mi][ni], ah[0], ah[1], ah[2], ah[3], bl[ni][0], bl[ni][1]);
                mma_f16(acc[mi][ni], al[0], al[1], al[2], al[3], bh[ni][0], bh[ni][1]);
            }
        }

        if (kt + 3 < nk) {
            const uint32_t sb = sbase + (uint32_t)((kt + 3) & 3) * STAGE_B;
#pragma unroll
            for (int i = 0; i < 4; ++i)
                CP16(sb + soff[i], gsrc + (size_t)rows[i] * K + (kt + 3) * 16 + csrc[i] * 8);
        }
        CP_COMMIT();
        CP_WAIT2();
        __syncthreads();
    }

#pragma unroll
    for (int mi = 0; mi < 4; ++mi) {
#pragma unroll
        for (int ni = 0; ni < 4; ++ni) {
            int col = bn + wn + ni * 8 + 2 * tig;
#pragma unroll
            for (int rs = 0; rs < 2; ++rs) {
                int row = bm + wm + mi * 16 + g + rs * 8;
                float v0 = acc[mi][ni][rs * 2], v1 = acc[mi][ni][rs * 2 + 1];
                if (MODE == 0) {
                    *(float2*)(C + (size_t)row * N + col) = make_float2(v0, v1);
                } else {
                    int path = col >> 10, lcol = col & 1023;
                    size_t off = (size_t)row * D_ + lcol;
                    if (path == 0) {
                        *(uint32_t*)(Qo + off) = pack_h2(__float2half_rn(v0), __float2half_rn(v1));
                    } else if (path == 1) {
                        *(uint32_t*)(Ko + off) = pack_h2(__float2half_rn(v0), __float2half_rn(v1));
                    } else {
                        uint32_t hi, lo;
                        split2(v0, v1, hi, lo);
                        *(uint32_t*)(Vho + off) = hi;
                        *(uint32_t*)(Vlo + off) = lo;
                    }
                }
            }
        }
    }
}

// ---------------------------------------------------------------------------
// FA2-style dual-path causal attention.
// Br=128 rows/CTA, Bc=64. 8 warps, each owns 16 rows x all 64 cols:
// warp-local softmax (quad shuffles), P in registers, PV hi/lo compensated.
// K/V via cp.async double buffer; one __syncthreads per KV tile.
// smem: Qx 16K | Qg 16K | 2 stages x {Kx 8K, Kg 8K, Vh 8K, Vl 8K} = 96KB.
// ---------------------------------------------------------------------------
#define AS_QX 0
#define AS_QG 16384
#define AS_KV 32768
#define ATT_SMEM 98304

__global__ __launch_bounds__(256) void attn_fa(
    const __half* __restrict__ qh,  const __half* __restrict__ kh,
    const __half* __restrict__ vh,  const __half* __restrict__ vl,
    const __half* __restrict__ qgh, const __half* __restrict__ kgh,
    __half* __restrict__ yh, __half* __restrict__ yl) {
    extern __shared__ char sm[];
    const uint32_t sb = cvta_s(sm);
    const int tid  = threadIdx.x;
    const int warp = tid >> 5, lane = tid & 31;
    const int wmr  = warp * 16;
    const int bh = blockIdx.y, b = bh >> 4, h = bh & 15;
    const int rt = blockIdx.x;
    const int l4 = lane >> 2, l2 = lane & 3;
    const float SC = 0.125f / 6.931471805599453f;

    // Q loads (Qx, Qg): 128 rows x 8 chunks, swizzled
    {
        const size_t qbase = ((size_t)b * L_ + (size_t)rt * 128) * D_ + h * HD_;
#pragma unroll
        for (int i = 0; i < 4; ++i) {
            int u = tid + 256 * i;
            int r = u >> 3, c = u & 7;
            uint32_t off = (uint32_t)(r * 128 + ((c ^ (r & 7)) * 16));
            CP16(sb + AS_QX + off, qh  + qbase + (size_t)r * D_ + c * 8);
            CP16(sb + AS_QG + off, qgh + qbase + (size_t)r * D_ + c * 8);
        }
    }

    // KV loader setup: 4 arrays x 64 threads, 8 chunks each
    const int arr = tid >> 6, t2 = tid & 63;
    const __half* kvsrc = (arr == 0) ? kh : (arr == 1) ? kgh : (arr == 2) ? vh : vl;
    const uint32_t kvdst = sb + AS_KV + (uint32_t)arr * 8192;
    const size_t bhbase = (size_t)b * L_ * D_ + h * HD_;

#define LOAD_KV(t, s)                                                              \
    do {                                                                           \
        const size_t kb = bhbase + (size_t)(t) * 64 * D_;                          \
        const uint32_t db = kvdst + (uint32_t)(s) * 32768;                         \
        _Pragma("unroll") for (int i = 0; i < 8; ++i) {                            \
            int u = t2 + 64 * i;                                                   \
            int r = u >> 3, c = u & 7;                                             \
            CP16(db + (uint32_t)(r * 128 + ((c ^ (r & 7)) * 16)),                  \
                 kvsrc + kb + (size_t)r * D_ + c * 8);                             \
        }                                                                          \
    } while (0)

    LOAD_KV(0, 0);
    CP_COMMIT();

    float m0 = -INFINITY, m1 = -INFINITY, l0 = 0.f, l1 = 0.f;
    float oacc[8][4];
#pragma unroll
    for (int ni = 0; ni < 8; ++ni)
#pragma unroll
        for (int r = 0; r < 4; ++r) oacc[ni][r] = 0.f;

    const int nt = 2 * rt + 2;
    for (int t = 0; t < nt; ++t) {
        CP_WAIT0();
        __syncthreads();
        if (t + 1 < nt) {
            LOAD_KV(t + 1, (t + 1) & 1);
            CP_COMMIT();
        }
        const uint32_t stg = sb + AS_KV + (uint32_t)(t & 1) * 32768;

        const bool skip = (t * 64) > (rt * 128 + wmr + 15);
        if (!skip) {
            // ---- scores ----
            float sacc[8][4];
#pragma unroll
            for (int ni = 0; ni < 8; ++ni)
#pragma unroll
                for (int r = 0; r < 4; ++r) sacc[ni][r] = 0.f;

#pragma unroll
            for (int kc = 0; kc < 4; ++kc) {
                int rA = wmr + (lane & 15);
                int cA = kc * 2 + (lane >> 4);
                uint32_t ada = sb + (uint32_t)(rA * 128 + ((cA ^ (rA & 7)) * 16));
                uint32_t qx[4], qg[4];
                LDSM4(qx[0], qx[1], qx[2], qx[3], ada + AS_QX);
                LDSM4(qg[0], qg[1], qg[2], qg[3], ada + AS_QG);

                int rB = (lane & 7) + ((lane >> 4) << 3);
                int cB = kc * 2 + ((lane >> 3) & 1);
#pragma unroll
                for (int nb = 0; nb < 4; ++nb) {
                    int r = nb * 16 + rB;
                    uint32_t adb = stg + (uint32_t)(r * 128 + ((cB ^ (r & 7)) * 16));
                    uint32_t k0, k1, k2, k3;
                    LDSM4(k0, k1, k2, k3, adb);            // Kx
                    mma_f16(sacc[nb * 2],     qx[0], qx[1], qx[2], qx[3], k0, k1);
                    mma_f16(sacc[nb * 2 + 1], qx[0], qx[1], qx[2], qx[3], k2, k3);
                    LDSM4(k0, k1, k2, k3, adb + 8192);     // Kg
                    mma_f16(sacc[nb * 2],     qg[0], qg[1], qg[2], qg[3], k0, k1);
                    mma_f16(sacc[nb * 2 + 1], qg[0], qg[1], qg[2], qg[3], k2, k3);
                }
            }

            // ---- scale + mask ----
            const int rowg0 = rt * 128 + wmr + l4;
            const bool maskneed = (t * 64 + 63) > (rt * 128 + wmr);
#pragma unroll
            for (int ni = 0; ni < 8; ++ni)
#pragma unroll
                for (int c = 0; c < 4; ++c) {
                    sacc[ni][c] *= SC;
                    if (maskneed) {
                        int colg = t * 64 + ni * 8 + 2 * l2 + (c & 1);
                        int rowg = rowg0 + ((c >> 1) & 1) * 8;
                        if (colg > rowg) sacc[ni][c] = -INFINITY;
                    }
                }

            // ---- warp-local online softmax ----
            float mx0 = -INFINITY, mx1 = -INFINITY;
#pragma unroll
            for (int ni = 0; ni < 8; ++ni) {
                mx0 = fmaxf(mx0, fmaxf(sacc[ni][0], sacc[ni][1]));
                mx1 = fmaxf(mx1, fmaxf(sacc[ni][2], sacc[ni][3]));
            }
            mx0 = fmaxf(mx0, __shfl_xor_sync(0xffffffffu, mx0, 1));
            mx0 = fmaxf(mx0, __shfl_xor_sync(0xffffffffu, mx0, 2));
            mx1 = fmaxf(mx1, __shfl_xor_sync(0xffffffffu, mx1, 1));
            mx1 = fmaxf(mx1, __shfl_xor_sync(0xffffffffu, mx1, 2));
            float mn0 = fmaxf(m0, mx0), mn1 = fmaxf(m1, mx1);
            float al0 = __expf(m0 - mn0), al1 = __expf(m1 - mn1);
            m0 = mn0; m1 = mn1;

            uint32_t ph[8][2], pl[8][2];
            float ps0 = 0.f, ps1 = 0.f;
#pragma unroll
            for (int ni = 0; ni < 8; ++ni) {
                float p0 = __expf(sacc[ni][0] - mn0);
                float p1 = __expf(sacc[ni][1] - mn0);
                float p2 = __expf(sacc[ni][2] - mn1);
                float p3 = __expf(sacc[ni][3] - mn1);
                ps0 += p0 + p1; ps1 += p2 + p3;
                split2(p0, p1, ph[ni][0], pl[ni][0]);
                split2(p2, p3, ph[ni][1], pl[ni][1]);
                oacc[ni][0] *= al0; oacc[ni][1] *= al0;
                oacc[ni][2] *= al1; oacc[ni][3] *= al1;
            }
            ps0 += __shfl_xor_sync(0xffffffffu, ps0, 1);
            ps0 += __shfl_xor_sync(0xffffffffu, ps0, 2);
            ps1 += __shfl_xor_sync(0xffffffffu, ps1, 1);
            ps1 += __shfl_xor_sync(0xffffffffu, ps1, 2);
            l0 = l0 * al0 + ps0;
            l1 = l1 * al1 + ps1;

            // ---- PV (compensated), A frags from registers ----
#pragma unroll
            for (int kc = 0; kc < 4; ++kc) {
                uint32_t a0 = ph[2 * kc][0], a1 = ph[2 * kc][1];
                uint32_t a2 = ph[2 * kc + 1][0], a3 = ph[2 * kc + 1][1];
                uint32_t c0 = pl[2 * kc][0], c1 = pl[2 * kc][1];
                uint32_t c2 = pl[2 * kc + 1][0], c3 = pl[2 * kc + 1][1];
                int rV = kc * 16 + (lane & 7) + (((lane >> 3) & 1) << 3);
#pragma unroll
                for (int db = 0; db < 4; ++db) {
                    int cV = db * 2 + (lane >> 4);
                    uint32_t adv = stg + 16384 + (uint32_t)(rV * 128 + ((cV ^ (rV & 7)) * 16));
                    uint32_t vh0, vh1, vh2, vh3, vl0, vl1, vl2, vl3;
                    LDSM4T(vh0, vh1, vh2, vh3, adv);
                    LDSM4T(vl0, vl1, vl2, vl3, adv + 8192);
                    mma_f16(oacc[db * 2],     a0, a1, a2, a3, vh0, vh1);
                    mma_f16(oacc[db * 2],     a0, a1, a2, a3, vl0, vl1);
                    mma_f16(oacc[db * 2],     c0, c1, c2, c3, vh0, vh1);
                    mma_f16(oacc[db * 2 + 1], a0, a1, a2, a3, vh2, vh3);
                    mma_f16(oacc[db * 2 + 1], a0, a1, a2, a3, vl2, vl3);
                    mma_f16(oacc[db * 2 + 1], c0, c1, c2, c3, vh2, vh3);
                }
            }
        }
    }

    // ---- epilogue: O/l -> fp16 hi/lo y ----
    const float inv0 = 1.f / l0, inv1 = 1.f / l1;
#pragma unroll
    for (int rh = 0; rh < 2; ++rh) {
        int row = wmr + l4 + rh * 8;
        float inv = rh ? inv1 : inv0;
        size_t base = ((size_t)b * L_ + (size_t)rt * 128 + row) * D_ + h * HD_;
#pragma unroll
        for (int ni = 0; ni < 8; ++ni) {
            int col = ni * 8 + 2 * l2;
            uint32_t hi, lo;
            split2(oacc[ni][rh * 2] * inv, oacc[ni][rh * 2 + 1] * inv, hi, lo);
            *(uint32_t*)(yh + base + col) = hi;
            *(uint32_t*)(yl + base + col) = lo;
        }
    }
}

// ---------------------------------------------------------------------------
extern "C" void kernel_launch(void* const* d_in, const int* in_sizes, int n_in,
                              void* d_out, int out_size) {
    const float* x    = (const float*)d_in[0];
    const float* q_g  = (const float*)d_in[1];
    const float* k_g  = (const float*)d_in[2];
    const float* Wqkv = (const float*)d_in[3];
    const float* Wout = (const float*)d_in[4];
    float* out = (float*)d_out;

    __half *xh, *xl, *wqh, *wql, *woh, *wol;
    __half *qh, *kh, *vh, *vl, *qgh, *kgh, *yh, *yl;
    cudaGetSymbolAddress((void**)&xh,  g_xh);
    cudaGetSymbolAddress((void**)&xl,  g_xl);
    cudaGetSymbolAddress((void**)&wqh, g_wqh);
    cudaGetSymbolAddress((void**)&wql, g_wql);
    cudaGetSymbolAddress((void**)&woh, g_woh);
    cudaGetSymbolAddress((void**)&wol, g_wol);
    cudaGetSymbolAddress((void**)&qh,  g_qh);
    cudaGetSymbolAddress((void**)&kh,  g_kh);
    cudaGetSymbolAddress((void**)&vh,  g_vh);
    cudaGetSymbolAddress((void**)&vl,  g_vl);
    cudaGetSymbolAddress((void**)&qgh, g_qgh);
    cudaGetSymbolAddress((void**)&kgh, g_kgh);
    cudaGetSymbolAddress((void**)&yh,  g_yh);
    cudaGetSymbolAddress((void**)&yl,  g_yl);

    cudaFuncSetAttribute(tgemm_h<0>, cudaFuncAttributeMaxDynamicSharedMemorySize, GEMM_SMEM);
    cudaFuncSetAttribute(tgemm_h<1>, cudaFuncAttributeMaxDynamicSharedMemorySize, GEMM_SMEM);
    cudaFuncSetAttribute(attn_fa, cudaFuncAttributeMaxDynamicSharedMemorySize, ATT_SMEM);

    const int NX  = B_ * L_ * D_ / 4;
    const int NWQ = D3_ * D_ / 4;
    const int NWO = D_ * D_ / 4;

    split_kernel<<<(NX + 255) / 256, 256>>>((const float4*)x, (uint2*)xh, (uint2*)xl, NX);
    split_kernel<<<(NWQ + 255) / 256, 256>>>((const float4*)Wqkv, (uint2*)wqh, (uint2*)wql, NWQ);
    split_kernel<<<(NWO + 255) / 256, 256>>>((const float4*)Wout, (uint2*)woh, (uint2*)wol, NWO);
    split_hi_kernel<<<(NX + 255) / 256, 256>>>((const float4*)q_g, (uint2*)qgh, NX);
    split_hi_kernel<<<(NX + 255) / 256, 256>>>((const float4*)k_g, (uint2*)kgh, NX);

    // 1) qkv projection -> fp16 q,k (hi) and v (hi+lo)
    dim3 g1(D3_ / 128, (B_ * L_) / 128);
    tgemm_h<1><<<g1, 256, GEMM_SMEM>>>(xh, xl, wqh, wql, nullptr,
                                       qh, kh, vh, vl, B_ * L_, D3_, D_);

    // 2) attention -> fp16 y (hi+lo)
    attn_fa<<<dim3(L_ / 128, B_ * H_), 256, ATT_SMEM>>>(qh, kh, vh, vl, qgh, kgh, yh, yl);

    // 3) out projection -> fp32 out
    dim3 g3(D_ / 128, (B_ * L_) / 128);
    tgemm_h<0><<<g3, 256, GEMM_SMEM>>>(yh, yl, woh, wol, out,
                                       nullptr, nullptr, nullptr, nullptr, B_ * L_, D_, D_);
}

// round 12
// speedup vs baseline: 3.7014x; 1.1738x over previous
#include <cuda_runtime.h>
#include <cuda_fp16.h>
#include <math.h>
#include <stdint.h>

#define B_  4
#define L_  1024
#define D_  1024
#define H_  16
#define HD_ 64
#define D3_ 3072

// ---------------------------------------------------------------------------
// Scratch (device globals; no allocation)
// ---------------------------------------------------------------------------
__device__ __half g_xh[(size_t)B_ * L_ * D_],  g_xl[(size_t)B_ * L_ * D_];
__device__ __half g_wqh[(size_t)D3_ * D_],     g_wql[(size_t)D3_ * D_];
__device__ __half g_woh[(size_t)D_ * D_],      g_wol[(size_t)D_ * D_];
__device__ __half g_qh[(size_t)B_ * L_ * D_];
__device__ __half g_kh[(size_t)B_ * L_ * D_];
__device__ __half g_vh[(size_t)B_ * L_ * D_],  g_vl[(size_t)B_ * L_ * D_];
__device__ __half g_qgh[(size_t)B_ * L_ * D_], g_kgh[(size_t)B_ * L_ * D_];
__device__ __half g_yh[(size_t)B_ * L_ * D_],  g_yl[(size_t)B_ * L_ * D_];

// ---------------------------------------------------------------------------
// helpers
// ---------------------------------------------------------------------------
__device__ __forceinline__ uint32_t cvta_s(const void* p) {
    return (uint32_t)__cvta_generic_to_shared(p);
}
__device__ __forceinline__ uint32_t pack_h2(__half a, __half b) {
    __half2 h = __halves2half2(a, b);
    return *(uint32_t*)&h;
}
__device__ __forceinline__ void split2(float x0, float x1, uint32_t& hi, uint32_t& lo) {
    __half h0 = __float2half_rn(x0);
    __half h1 = __float2half_rn(x1);
    __half l0 = __float2half_rn(x0 - __half2float(h0));
    __half l1 = __float2half_rn(x1 - __half2float(h1));
    hi = pack_h2(h0, h1);
    lo = pack_h2(l0, l1);
}
__device__ __forceinline__ void mma_f16(float* c,
                                        uint32_t a0, uint32_t a1, uint32_t a2, uint32_t a3,
                                        uint32_t b0, uint32_t b1) {
    asm volatile(
        "mma.sync.aligned.m16n8k16.row.col.f32.f16.f16.f32 "
        "{%0,%1,%2,%3},{%4,%5,%6,%7},{%8,%9},{%0,%1,%2,%3};\n"
        : "+f"(c[0]), "+f"(c[1]), "+f"(c[2]), "+f"(c[3])
        : "r"(a0), "r"(a1), "r"(a2), "r"(a3), "r"(b0), "r"(b1));
}
#define LDSM4(r0, r1, r2, r3, addr) \
    asm volatile("ldmatrix.sync.aligned.m8n8.x4.shared.b16 {%0,%1,%2,%3},[%4];\n" \
                 : "=r"(r0), "=r"(r1), "=r"(r2), "=r"(r3) : "r"(addr))
#define LDSM4T(r0, r1, r2, r3, addr) \
    asm volatile("ldmatrix.sync.aligned.m8n8.x4.trans.shared.b16 {%0,%1,%2,%3},[%4];\n" \
                 : "=r"(r0), "=r"(r1), "=r"(r2), "=r"(r3) : "r"(addr))
#define CP16(saddr, gptr) \
    asm volatile("cp.async.cg.shared.global [%0], [%1], 16;\n" :: "r"(saddr), "l"(gptr))
#define CP_COMMIT() asm volatile("cp.async.commit_group;\n")
#define CP_WAIT0()  asm volatile("cp.async.wait_group 0;\n")
#define CP_WAIT2()  asm volatile("cp.async.wait_group 2;\n")

// ---------------------------------------------------------------------------
// split kernels
// ---------------------------------------------------------------------------
__global__ __launch_bounds__(256) void split_kernel(const float4* __restrict__ in,
                                                    uint2* __restrict__ hi,
                                                    uint2* __restrict__ lo, int n4) {
    int i = blockIdx.x * blockDim.x + threadIdx.x;
    if (i >= n4) return;
    float4 v = in[i];
    uint32_t h0, l0, h1, l1;
    split2(v.x, v.y, h0, l0);
    split2(v.z, v.w, h1, l1);
    hi[i] = make_uint2(h0, h1);
    lo[i] = make_uint2(l0, l1);
}
__global__ __launch_bounds__(256) void split_hi_kernel(const float4* __restrict__ in,
                                                       uint2* __restrict__ hi, int n4) {
    int i = blockIdx.x * blockDim.x + threadIdx.x;
    if (i >= n4) return;
    float4 v = in[i];
    hi[i] = make_uint2(pack_h2(__float2half_rn(v.x), __float2half_rn(v.y)),
                       pack_h2(__float2half_rn(v.z), __float2half_rn(v.w)));
}

// ---------------------------------------------------------------------------
// Tensor-core GEMM (NT) on pre-split fp16 hi/lo.
// COMP=true : 3-MMA hi/lo compensation.
// COMP=false: hi-only (1 MMA), lo operands never loaded.
// 128x128 tile, BK=16, 8 warps (2m x 4n). cp.async 4-stage, swizzled rows.
// MODE 0: write fp32 C. MODE 1: qkv-split epilogue (q,k hi fp16; v hi+lo).
// bn0: global column offset of this launch's N-range.
// ---------------------------------------------------------------------------
#define STAGE_B 16384
#define GEMM_SMEM 65536

template <int MODE, bool COMP>
__global__ __launch_bounds__(256) void tgemm_h(const __half* __restrict__ Ah,
                                               const __half* __restrict__ Al,
                                               const __half* __restrict__ Bh,
                                               const __half* __restrict__ Bl,
                                               float* __restrict__ C,
                                               __half* __restrict__ Qo,
                                               __half* __restrict__ Ko,
                                               __half* __restrict__ Vho,
                                               __half* __restrict__ Vlo,
                                               int M, int N, int K, int bn0) {
    extern __shared__ char sm[];
    const uint32_t sbase = cvta_s(sm);

    const int tid  = threadIdx.x;
    const int warp = tid >> 5, lane = tid & 31;
    const int g = lane >> 2, tig = lane & 3;
    const int wm = (warp >> 2) * 64;
    const int wn = (warp & 3) * 32;
    const int bm = blockIdx.y * 128, bn = bn0 + blockIdx.x * 128;

    const int arr = tid >> 6;
    const int t2  = tid & 63;
    const bool loader = COMP || (arr == 0) || (arr == 2);
    const __half* gsrc = (arr == 0) ? Ah + (size_t)bm * K :
                         (arr == 1) ? Al + (size_t)bm * K :
                         (arr == 2) ? Bh + (size_t)bn * K :
                                      Bl + (size_t)bn * K;
    int rows[4], csrc[4];
    uint32_t soff[4];
#pragma unroll
    for (int i = 0; i < 4; ++i) {
        int u = t2 + 64 * i;
        int r = u >> 1, c = u & 1;
        rows[i] = r; csrc[i] = c;
        soff[i] = (uint32_t)(arr * 4096 + r * 32 + ((c ^ ((r >> 2) & 1)) * 16));
    }

    uint32_t aoff[4];
#pragma unroll
    for (int mi = 0; mi < 4; ++mi) {
        int r = wm + mi * 16 + (lane & 15);
        int c = lane >> 4;
        aoff[mi] = (uint32_t)(r * 32 + ((c ^ ((r >> 2) & 1)) * 16));
    }
    uint32_t boff[2];
#pragma unroll
    for (int nb = 0; nb < 2; ++nb) {
        int r = wn + nb * 16 + (lane & 7) + ((lane >> 4) << 3);
        int c = (lane >> 3) & 1;
        boff[nb] = (uint32_t)(8192 + r * 32 + ((c ^ ((r >> 2) & 1)) * 16));
    }

    float acc[4][4][4];
#pragma unroll
    for (int mi = 0; mi < 4; ++mi)
#pragma unroll
        for (int ni = 0; ni < 4; ++ni)
#pragma unroll
            for (int r = 0; r < 4; ++r) acc[mi][ni][r] = 0.f;

    const int nk = K >> 4;
#pragma unroll
    for (int s = 0; s < 3; ++s) {
        const uint32_t sb = sbase + s * STAGE_B;
        if (loader) {
#pragma unroll
            for (int i = 0; i < 4; ++i)
                CP16(sb + soff[i], gsrc + (size_t)rows[i] * K + s * 16 + csrc[i] * 8);
        }
        CP_COMMIT();
    }
    CP_WAIT2();
    __syncthreads();

    for (int kt = 0; kt < nk; ++kt) {
        const uint32_t stg = sbase + (uint32_t)(kt & 3) * STAGE_B;

        uint32_t bh[4][2], bl[4][2];
#pragma unroll
        for (int nb = 0; nb < 2; ++nb) {
            uint32_t r0, r1, r2, r3;
            LDSM4(r0, r1, r2, r3, stg + boff[nb]);
            bh[nb * 2][0] = r0; bh[nb * 2][1] = r1;
            bh[nb * 2 + 1][0] = r2; bh[nb * 2 + 1][1] = r3;
            if (COMP) {
                LDSM4(r0, r1, r2, r3, stg + boff[nb] + 4096);
                bl[nb * 2][0] = r0; bl[nb * 2][1] = r1;
                bl[nb * 2 + 1][0] = r2; bl[nb * 2 + 1][1] = r3;
            }
        }

#pragma unroll
        for (int mi = 0; mi < 4; ++mi) {
            uint32_t ah[4], al[4];
            LDSM4(ah[0], ah[1], ah[2], ah[3], stg + aoff[mi]);
            if (COMP)
                LDSM4(al[0], al[1], al[2], al[3], stg + aoff[mi] + 4096);
#pragma unroll
            for (int ni = 0; ni < 4; ++ni) {
                mma_f16(acc[mi][ni], ah[0], ah[1], ah[2], ah[3], bh[ni][0], bh[ni][1]);
                if (COMP) {
                    mma_f16(acc[mi][ni], ah[0], ah[1], ah[2], ah[3], bl[ni][0], bl[ni][1]);
                    mma_f16(acc[mi][ni], al[0], al[1], al[2], al[3], bh[ni][0], bh[ni][1]);
                }
            }
        }

        if (kt + 3 < nk) {
            const uint32_t sb = sbase + (uint32_t)((kt + 3) & 3) * STAGE_B;
            if (loader) {
#pragma unroll
                for (int i = 0; i < 4; ++i)
                    CP16(sb + soff[i], gsrc + (size_t)rows[i] * K + (kt + 3) * 16 + csrc[i] * 8);
            }
        }
        CP_COMMIT();
        CP_WAIT2();
        __syncthreads();
    }

#pragma unroll
    for (int mi = 0; mi < 4; ++mi) {
#pragma unroll
        for (int ni = 0; ni < 4; ++ni) {
            int col = bn + wn + ni * 8 + 2 * tig;
#pragma unroll
            for (int rs = 0; rs < 2; ++rs) {
                int row = bm + wm + mi * 16 + g + rs * 8;
                float v0 = acc[mi][ni][rs * 2], v1 = acc[mi][ni][rs * 2 + 1];
                if (MODE == 0) {
                    *(float2*)(C + (size_t)row * N + col) = make_float2(v0, v1);
                } else {
                    int path = col >> 10, lcol = col & 1023;
                    size_t off = (size_t)row * D_ + lcol;
                    if (path == 0) {
                        *(uint32_t*)(Qo + off) = pack_h2(__float2half_rn(v0), __float2half_rn(v1));
                    } else if (path == 1) {
                        *(uint32_t*)(Ko + off) = pack_h2(__float2half_rn(v0), __float2half_rn(v1));
                    } else {
                        uint32_t hi, lo;
                        split2(v0, v1, hi, lo);
                        *(uint32_t*)(Vho + off) = hi;
                        *(uint32_t*)(Vlo + off) = lo;
                    }
                }
            }
        }
    }
}

// ---------------------------------------------------------------------------
// FA2-style dual-path causal attention (unchanged from R8 passing version).
// ---------------------------------------------------------------------------
#define AS_QX 0
#define AS_QG 16384
#define AS_KV 32768
#define ATT_SMEM 98304

__global__ __launch_bounds__(256) void attn_fa(
    const __half* __restrict__ qh,  const __half* __restrict__ kh,
    const __half* __restrict__ vh,  const __half* __restrict__ vl,
    const __half* __restrict__ qgh, const __half* __restrict__ kgh,
    __half* __restrict__ yh, __half* __restrict__ yl) {
    extern __shared__ char sm[];
    const uint32_t sb = cvta_s(sm);
    const int tid  = threadIdx.x;
    const int warp = tid >> 5, lane = tid & 31;
    const int wmr  = warp * 16;
    const int bh = blockIdx.y, b = bh >> 4, h = bh & 15;
    const int rt = blockIdx.x;
    const int l4 = lane >> 2, l2 = lane & 3;
    const float SC = 0.125f / 6.931471805599453f;

    {
        const size_t qbase = ((size_t)b * L_ + (size_t)rt * 128) * D_ + h * HD_;
#pragma unroll
        for (int i = 0; i < 4; ++i) {
            int u = tid + 256 * i;
            int r = u >> 3, c = u & 7;
            uint32_t off = (uint32_t)(r * 128 + ((c ^ (r & 7)) * 16));
            CP16(sb + AS_QX + off, qh  + qbase + (size_t)r * D_ + c * 8);
            CP16(sb + AS_QG + off, qgh + qbase + (size_t)r * D_ + c * 8);
        }
    }

    const int arr = tid >> 6, t2 = tid & 63;
    const __half* kvsrc = (arr == 0) ? kh : (arr == 1) ? kgh : (arr == 2) ? vh : vl;
    const uint32_t kvdst = sb + AS_KV + (uint32_t)arr * 8192;
    const size_t bhbase = (size_t)b * L_ * D_ + h * HD_;

#define LOAD_KV(t, s)                                                              \
    do {                                                                           \
        const size_t kb = bhbase + (size_t)(t) * 64 * D_;                          \
        const uint32_t db = kvdst + (uint32_t)(s) * 32768;                         \
        _Pragma("unroll") for (int i = 0; i < 8; ++i) {                            \
            int u = t2 + 64 * i;                                                   \
            int r = u >> 3, c = u & 7;                                             \
            CP16(db + (uint32_t)(r * 128 + ((c ^ (r & 7)) * 16)),                  \
                 kvsrc + kb + (size_t)r * D_ + c * 8);                             \
        }                                                                          \
    } while (0)

    LOAD_KV(0, 0);
    CP_COMMIT();

    float m0 = -INFINITY, m1 = -INFINITY, l0 = 0.f, l1 = 0.f;
    float oacc[8][4];
#pragma unroll
    for (int ni = 0; ni < 8; ++ni)
#pragma unroll
        for (int r = 0; r < 4; ++r) oacc[ni][r] = 0.f;

    const int nt = 2 * rt + 2;
    for (int t = 0; t < nt; ++t) {
        CP_WAIT0();
        __syncthreads();
        if (t + 1 < nt) {
            LOAD_KV(t + 1, (t + 1) & 1);
            CP_COMMIT();
        }
        const uint32_t stg = sb + AS_KV + (uint32_t)(t & 1) * 32768;

        const bool skip = (t * 64) > (rt * 128 + wmr + 15);
        if (!skip) {
            float sacc[8][4];
#pragma unroll
            for (int ni = 0; ni < 8; ++ni)
#pragma unroll
                for (int r = 0; r < 4; ++r) sacc[ni][r] = 0.f;

#pragma unroll
            for (int kc = 0; kc < 4; ++kc) {
                int rA = wmr + (lane & 15);
                int cA = kc * 2 + (lane >> 4);
                uint32_t ada = sb + (uint32_t)(rA * 128 + ((cA ^ (rA & 7)) * 16));
                uint32_t qx[4], qg[4];
                LDSM4(qx[0], qx[1], qx[2], qx[3], ada + AS_QX);
                LDSM4(qg[0], qg[1], qg[2], qg[3], ada + AS_QG);

                int rB = (lane & 7) + ((lane >> 4) << 3);
                int cB = kc * 2 + ((lane >> 3) & 1);
#pragma unroll
                for (int nb = 0; nb < 4; ++nb) {
                    int r = nb * 16 + rB;
                    uint32_t adb = stg + (uint32_t)(r * 128 + ((cB ^ (r & 7)) * 16));
                    uint32_t k0, k1, k2, k3;
                    LDSM4(k0, k1, k2, k3, adb);
                    mma_f16(sacc[nb * 2],     qx[0], qx[1], qx[2], qx[3], k0, k1);
                    mma_f16(sacc[nb * 2 + 1], qx[0], qx[1], qx[2], qx[3], k2, k3);
                    LDSM4(k0, k1, k2, k3, adb + 8192);
                    mma_f16(sacc[nb * 2],     qg[0], qg[1], qg[2], qg[3], k0, k1);
                    mma_f16(sacc[nb * 2 + 1], qg[0], qg[1], qg[2], qg[3], k2, k3);
                }
            }

            const int rowg0 = rt * 128 + wmr + l4;
            const bool maskneed = (t * 64 + 63) > (rt * 128 + wmr);
#pragma unroll
            for (int ni = 0; ni < 8; ++ni)
#pragma unroll
                for (int c = 0; c < 4; ++c) {
                    sacc[ni][c] *= SC;
                    if (maskneed) {
                        int colg = t * 64 + ni * 8 + 2 * l2 + (c & 1);
                        int rowg = rowg0 + ((c >> 1) & 1) * 8;
                        if (colg > rowg) sacc[ni][c] = -INFINITY;
                    }
                }

            float mx0 = -INFINITY, mx1 = -INFINITY;
#pragma unroll
            for (int ni = 0; ni < 8; ++ni) {
                mx0 = fmaxf(mx0, fmaxf(sacc[ni][0], sacc[ni][1]));
                mx1 = fmaxf(mx1, fmaxf(sacc[ni][2], sacc[ni][3]));
            }
            mx0 = fmaxf(mx0, __shfl_xor_sync(0xffffffffu, mx0, 1));
            mx0 = fmaxf(mx0, __shfl_xor_sync(0xffffffffu, mx0, 2));
            mx1 = fmaxf(mx1, __shfl_xor_sync(0xffffffffu, mx1, 1));
            mx1 = fmaxf(mx1, __shfl_xor_sync(0xffffffffu, mx1, 2));
            float mn0 = fmaxf(m0, mx0), mn1 = fmaxf(m1, mx1);
            float al0 = __expf(m0 - mn0), al1 = __expf(m1 - mn1);
            m0 = mn0; m1 = mn1;

            uint32_t ph[8][2], pl[8][2];
            float ps0 = 0.f, ps1 = 0.f;
#pragma unroll
            for (int ni = 0; ni < 8; ++ni) {
                float p0 = __expf(sacc[ni][0] - mn0);
                float p1 = __expf(sacc[ni][1] - mn0);
                float p2 = __expf(sacc[ni][2] - mn1);
                float p3 = __expf(sacc[ni][3] - mn1);
                ps0 += p0 + p1; ps1 += p2 + p3;
                split2(p0, p1, ph[ni][0], pl[ni][0]);
                split2(p2, p3, ph[ni][1], pl[ni][1]);
                oacc[ni][0] *= al0; oacc[ni][1] *= al0;
                oacc[ni][2] *= al1; oacc[ni][3] *= al1;
            }
            ps0 += __shfl_xor_sync(0xffffffffu, ps0, 1);
            ps0 += __shfl_xor_sync(0xffffffffu, ps0, 2);
            ps1 += __shfl_xor_sync(0xffffffffu, ps1, 1);
            ps1 += __shfl_xor_sync(0xffffffffu, ps1, 2);
            l0 = l0 * al0 + ps0;
            l1 = l1 * al1 + ps1;

#pragma unroll
            for (int kc = 0; kc < 4; ++kc) {
                uint32_t a0 = ph[2 * kc][0], a1 = ph[2 * kc][1];
                uint32_t a2 = ph[2 * kc + 1][0], a3 = ph[2 * kc + 1][1];
                uint32_t c0 = pl[2 * kc][0], c1 = pl[2 * kc][1];
                uint32_t c2 = pl[2 * kc + 1][0], c3 = pl[2 * kc + 1][1];
                int rV = kc * 16 + (lane & 7) + (((lane >> 3) & 1) << 3);
#pragma unroll
                for (int db = 0; db < 4; ++db) {
                    int cV = db * 2 + (lane >> 4);
                    uint32_t adv = stg + 16384 + (uint32_t)(rV * 128 + ((cV ^ (rV & 7)) * 16));
                    uint32_t vh0, vh1, vh2, vh3, vl0, vl1, vl2, vl3;
                    LDSM4T(vh0, vh1, vh2, vh3, adv);
                    LDSM4T(vl0, vl1, vl2, vl3, adv + 8192);
                    mma_f16(oacc[db * 2],     a0, a1, a2, a3, vh0, vh1);
                    mma_f16(oacc[db * 2],     a0, a1, a2, a3, vl0, vl1);
                    mma_f16(oacc[db * 2],     c0, c1, c2, c3, vh0, vh1);
                    mma_f16(oacc[db * 2 + 1], a0, a1, a2, a3, vh2, vh3);
                    mma_f16(oacc[db * 2 + 1], a0, a1, a2, a3, vl2, vl3);
                    mma_f16(oacc[db * 2 + 1], c0, c1, c2, c3, vh2, vh3);
                }
            }
        }
    }

    const float inv0 = 1.f / l0, inv1 = 1.f / l1;
#pragma unroll
    for (int rh = 0; rh < 2; ++rh) {
        int row = wmr + l4 + rh * 8;
        float inv = rh ? inv1 : inv0;
        size_t base = ((size_t)b * L_ + (size_t)rt * 128 + row) * D_ + h * HD_;
#pragma unroll
        for (int ni = 0; ni < 8; ++ni) {
            int col = ni * 8 + 2 * l2;
            uint32_t hi, lo;
            split2(oacc[ni][rh * 2] * inv, oacc[ni][rh * 2 + 1] * inv, hi, lo);
            *(uint32_t*)(yh + base + col) = hi;
            *(uint32_t*)(yl + base + col) = lo;
        }
    }
}

// ---------------------------------------------------------------------------
extern "C" void kernel_launch(void* const* d_in, const int* in_sizes, int n_in,
                              void* d_out, int out_size) {
    const float* x    = (const float*)d_in[0];
    const float* q_g  = (const float*)d_in[1];
    const float* k_g  = (const float*)d_in[2];
    const float* Wqkv = (const float*)d_in[3];
    const float* Wout = (const float*)d_in[4];
    float* out = (float*)d_out;

    __half *xh, *xl, *wqh, *wql, *woh, *wol;
    __half *qh, *kh, *vh, *vl, *qgh, *kgh, *yh, *yl;
    cudaGetSymbolAddress((void**)&xh,  g_xh);
    cudaGetSymbolAddress((void**)&xl,  g_xl);
    cudaGetSymbolAddress((void**)&wqh, g_wqh);
    cudaGetSymbolAddress((void**)&wql, g_wql);
    cudaGetSymbolAddress((void**)&woh, g_woh);
    cudaGetSymbolAddress((void**)&wol, g_wol);
    cudaGetSymbolAddress((void**)&qh,  g_qh);
    cudaGetSymbolAddress((void**)&kh,  g_kh);
    cudaGetSymbolAddress((void**)&vh,  g_vh);
    cudaGetSymbolAddress((void**)&vl,  g_vl);
    cudaGetSymbolAddress((void**)&qgh, g_qgh);
    cudaGetSymbolAddress((void**)&kgh, g_kgh);
    cudaGetSymbolAddress((void**)&yh,  g_yh);
    cudaGetSymbolAddress((void**)&yl,  g_yl);

    cudaFuncSetAttribute(tgemm_h<0, true>,
                         cudaFuncAttributeMaxDynamicSharedMemorySize, GEMM_SMEM);
    cudaFuncSetAttribute(tgemm_h<1, true>,
                         cudaFuncAttributeMaxDynamicSharedMemorySize, GEMM_SMEM);
    cudaFuncSetAttribute(tgemm_h<1, false>,
                         cudaFuncAttributeMaxDynamicSharedMemorySize, GEMM_SMEM);
    cudaFuncSetAttribute(attn_fa,
                         cudaFuncAttributeMaxDynamicSharedMemorySize, ATT_SMEM);

    const int NX  = B_ * L_ * D_ / 4;
    const int NWQ = D3_ * D_ / 4;
    const int NWO = D_ * D_ / 4;

    split_kernel<<<(NX + 255) / 256, 256>>>((const float4*)x, (uint2*)xh, (uint2*)xl, NX);
    split_kernel<<<(NWQ + 255) / 256, 256>>>((const float4*)Wqkv, (uint2*)wqh, (uint2*)wql, NWQ);
    split_kernel<<<(NWO + 255) / 256, 256>>>((const float4*)Wout, (uint2*)woh, (uint2*)wol, NWO);
    split_hi_kernel<<<(NX + 255) / 256, 256>>>((const float4*)q_g, (uint2*)qgh, NX);
    split_hi_kernel<<<(NX + 255) / 256, 256>>>((const float4*)k_g, (uint2*)kgh, NX);

    // 1a) q,k columns [0, 2048): hi-only (q,k get rounded to fp16 anyway)
    tgemm_h<1, false><<<dim3(16, 32), 256, GEMM_SMEM>>>(
        xh, xl, wqh, wql, nullptr, qh, kh, vh, vl, B_ * L_, D3_, D_, 0);
    // 1b) v columns [2048, 3072): compensated (feeds y directly)
    tgemm_h<1, true><<<dim3(8, 32), 256, GEMM_SMEM>>>(
        xh, xl, wqh, wql, nullptr, qh, kh, vh, vl, B_ * L_, D3_, D_, 2048);

    // 2) attention -> fp16 y (hi+lo)
    attn_fa<<<dim3(L_ / 128, B_ * H_), 256, ATT_SMEM>>>(qh, kh, vh, vl, qgh, kgh, yh, yl);

    // 3) out projection -> fp32 out (compensated)
    tgemm_h<0, true><<<dim3(8, 32), 256, GEMM_SMEM>>>(
        yh, yl, woh, wol, out, nullptr, nullptr, nullptr, nullptr, B_ * L_, D_, D_, 0);
}

// round 14
// speedup vs baseline: 4.2047x; 1.1360x over previous
#include <cuda_runtime.h>
#include <cuda_fp16.h>
#include <math.h>
#include <stdint.h>

#define B_  4
#define L_  1024
#define D_  1024
#define H_  16
#define HD_ 64
#define D3_ 3072

// ---------------------------------------------------------------------------
// Scratch (device globals; no allocation)
// ---------------------------------------------------------------------------
__device__ __half g_xh[(size_t)B_ * L_ * D_],  g_xl[(size_t)B_ * L_ * D_];
__device__ __half g_wqh[(size_t)D3_ * D_],     g_wql[(size_t)D3_ * D_];
__device__ __half g_woh[(size_t)D_ * D_];
__device__ __half g_qh[(size_t)B_ * L_ * D_];
__device__ __half g_kh[(size_t)B_ * L_ * D_];
__device__ __half g_vh[(size_t)B_ * L_ * D_],  g_vl[(size_t)B_ * L_ * D_];
__device__ __half g_qgh[(size_t)B_ * L_ * D_], g_kgh[(size_t)B_ * L_ * D_];
__device__ __half g_yh[(size_t)B_ * L_ * D_];

// ---------------------------------------------------------------------------
// helpers
// ---------------------------------------------------------------------------
__device__ __forceinline__ uint32_t cvta_s(const void* p) {
    return (uint32_t)__cvta_generic_to_shared(p);
}
__device__ __forceinline__ uint32_t pack_h2(__half a, __half b) {
    __half2 h = __halves2half2(a, b);
    return *(uint32_t*)&h;
}
__device__ __forceinline__ void split2(float x0, float x1, uint32_t& hi, uint32_t& lo) {
    __half h0 = __float2half_rn(x0);
    __half h1 = __float2half_rn(x1);
    __half l0 = __float2half_rn(x0 - __half2float(h0));
    __half l1 = __float2half_rn(x1 - __half2float(h1));
    hi = pack_h2(h0, h1);
    lo = pack_h2(l0, l1);
}
__device__ __forceinline__ void mma_f16(float* c,
                                        uint32_t a0, uint32_t a1, uint32_t a2, uint32_t a3,
                                        uint32_t b0, uint32_t b1) {
    asm volatile(
        "mma.sync.aligned.m16n8k16.row.col.f32.f16.f16.f32 "
        "{%0,%1,%2,%3},{%4,%5,%6,%7},{%8,%9},{%0,%1,%2,%3};\n"
        : "+f"(c[0]), "+f"(c[1]), "+f"(c[2]), "+f"(c[3])
        : "r"(a0), "r"(a1), "r"(a2), "r"(a3), "r"(b0), "r"(b1));
}
#define LDSM4(r0, r1, r2, r3, addr) \
    asm volatile("ldmatrix.sync.aligned.m8n8.x4.shared.b16 {%0,%1,%2,%3},[%4];\n" \
                 : "=r"(r0), "=r"(r1), "=r"(r2), "=r"(r3) : "r"(addr))
#define LDSM4T(r0, r1, r2, r3, addr) \
    asm volatile("ldmatrix.sync.aligned.m8n8.x4.trans.shared.b16 {%0,%1,%2,%3},[%4];\n" \
                 : "=r"(r0), "=r"(r1), "=r"(r2), "=r"(r3) : "r"(addr))
#define CP16(saddr, gptr) \
    asm volatile("cp.async.cg.shared.global [%0], [%1], 16;\n" :: "r"(saddr), "l"(gptr))
#define CP_COMMIT() asm volatile("cp.async.commit_group;\n")
#define CP_WAIT0()  asm volatile("cp.async.wait_group 0;\n")
#define CP_WAIT2()  asm volatile("cp.async.wait_group 2;\n")

// ---------------------------------------------------------------------------
// split kernels
// ---------------------------------------------------------------------------
__global__ __launch_bounds__(256) void split_kernel(const float4* __restrict__ in,
                                                    uint2* __restrict__ hi,
                                                    uint2* __restrict__ lo, int n4) {
    int i = blockIdx.x * blockDim.x + threadIdx.x;
    if (i >= n4) return;
    float4 v = in[i];
    uint32_t h0, l0, h1, l1;
    split2(v.x, v.y, h0, l0);
    split2(v.z, v.w, h1, l1);
    hi[i] = make_uint2(h0, h1);
    lo[i] = make_uint2(l0, l1);
}
__global__ __launch_bounds__(256) void split_hi_kernel(const float4* __restrict__ in,
                                                       uint2* __restrict__ hi, int n4) {
    int i = blockIdx.x * blockDim.x + threadIdx.x;
    if (i >= n4) return;
    float4 v = in[i];
    hi[i] = make_uint2(pack_h2(__float2half_rn(v.x), __float2half_rn(v.y)),
                       pack_h2(__float2half_rn(v.z), __float2half_rn(v.w)));
}

// ---------------------------------------------------------------------------
// Tensor-core GEMM (NT) on pre-split fp16 hi/lo.
// COMP=true : 3-MMA hi/lo compensation.
// COMP=false: hi-only (1 MMA), lo operands never loaded.
// 128x128 tile, BK=16, 8 warps (2m x 4n). cp.async 4-stage, swizzled rows.
// MODE 0: write fp32 C. MODE 1: qkv-split epilogue (q,k hi fp16; v hi+lo).
// bn0: global column offset of this launch's N-range.
// ---------------------------------------------------------------------------
#define STAGE_B 16384
#define GEMM_SMEM 65536

template <int MODE, bool COMP>
__global__ __launch_bounds__(256) void tgemm_h(const __half* __restrict__ Ah,
                                               const __half* __restrict__ Al,
                                               const __half* __restrict__ Bh,
                                               const __half* __restrict__ Bl,
                                               float* __restrict__ C,
                                               __half* __restrict__ Qo,
                                               __half* __restrict__ Ko,
                                               __half* __restrict__ Vho,
                                               __half* __restrict__ Vlo,
                                               int M, int N, int K, int bn0) {
    extern __shared__ char sm[];
    const uint32_t sbase = cvta_s(sm);

    const int tid  = threadIdx.x;
    const int warp = tid >> 5, lane = tid & 31;
    const int g = lane >> 2, tig = lane & 3;
    const int wm = (warp >> 2) * 64;
    const int wn = (warp & 3) * 32;
    const int bm = blockIdx.y * 128, bn = bn0 + blockIdx.x * 128;

    const int arr = tid >> 6;
    const int t2  = tid & 63;
    const bool loader = COMP || (arr == 0) || (arr == 2);
    const __half* gsrc = (arr == 0) ? Ah + (size_t)bm * K :
                         (arr == 1) ? Al + (size_t)bm * K :
                         (arr == 2) ? Bh + (size_t)bn * K :
                                      Bl + (size_t)bn * K;
    int rows[4], csrc[4];
    uint32_t soff[4];
#pragma unroll
    for (int i = 0; i < 4; ++i) {
        int u = t2 + 64 * i;
        int r = u >> 1, c = u & 1;
        rows[i] = r; csrc[i] = c;
        soff[i] = (uint32_t)(arr * 4096 + r * 32 + ((c ^ ((r >> 2) & 1)) * 16));
    }

    uint32_t aoff[4];
#pragma unroll
    for (int mi = 0; mi < 4; ++mi) {
        int r = wm + mi * 16 + (lane & 15);
        int c = lane >> 4;
        aoff[mi] = (uint32_t)(r * 32 + ((c ^ ((r >> 2) & 1)) * 16));
    }
    uint32_t boff[2];
#pragma unroll
    for (int nb = 0; nb < 2; ++nb) {
        int r = wn + nb * 16 + (lane & 7) + ((lane >> 4) << 3);
        int c = (lane >> 3) & 1;
        boff[nb] = (uint32_t)(8192 + r * 32 + ((c ^ ((r >> 2) & 1)) * 16));
    }

    float acc[4][4][4];
#pragma unroll
    for (int mi = 0; mi < 4; ++mi)
#pragma unroll
        for (int ni = 0; ni < 4; ++ni)
#pragma unroll
            for (int r = 0; r < 4; ++r) acc[mi][ni][r] = 0.f;

    const int nk = K >> 4;
#pragma unroll
    for (int s = 0; s < 3; ++s) {
        const uint32_t sb = sbase + s * STAGE_B;
        if (loader) {
#pragma unroll
            for (int i = 0; i < 4; ++i)
                CP16(sb + soff[i], gsrc + (size_t)rows[i] * K + s * 16 + csrc[i] * 8);
        }
        CP_COMMIT();
    }
    CP_WAIT2();
    __syncthreads();

    for (int kt = 0; kt < nk; ++kt) {
        const uint32_t stg = sbase + (uint32_t)(kt & 3) * STAGE_B;

        uint32_t bh[4][2], bl[4][2];
#pragma unroll
        for (int nb = 0; nb < 2; ++nb) {
            uint32_t r0, r1, r2, r3;
            LDSM4(r0, r1, r2, r3, stg + boff[nb]);
            bh[nb * 2][0] = r0; bh[nb * 2][1] = r1;
            bh[nb * 2 + 1][0] = r2; bh[nb * 2 + 1][1] = r3;
            if (COMP) {
                LDSM4(r0, r1, r2, r3, stg + boff[nb] + 4096);
                bl[nb * 2][0] = r0; bl[nb * 2][1] = r1;
                bl[nb * 2 + 1][0] = r2; bl[nb * 2 + 1][1] = r3;
            }
        }

#pragma unroll
        for (int mi = 0; mi < 4; ++mi) {
            uint32_t ah[4], al[4];
            LDSM4(ah[0], ah[1], ah[2], ah[3], stg + aoff[mi]);
            if (COMP)
                LDSM4(al[0], al[1], al[2], al[3], stg + aoff[mi] + 4096);
#pragma unroll
            for (int ni = 0; ni < 4; ++ni) {
                mma_f16(acc[mi][ni], ah[0], ah[1], ah[2], ah[3], bh[ni][0], bh[ni][1]);
                if (COMP) {
                    mma_f16(acc[mi][ni], ah[0], ah[1], ah[2], ah[3], bl[ni][0], bl[ni][1]);
                    mma_f16(acc[mi][ni], al[0], al[1], al[2], al[3], bh[ni][0], bh[ni][1]);
                }
            }
        }

        if (kt + 3 < nk) {
            const uint32_t sb = sbase + (uint32_t)((kt + 3) & 3) * STAGE_B;
            if (loader) {
#pragma unroll
                for (int i = 0; i < 4; ++i)
                    CP16(sb + soff[i], gsrc + (size_t)rows[i] * K + (kt + 3) * 16 + csrc[i] * 8);
            }
        }
        CP_COMMIT();
        CP_WAIT2();
        __syncthreads();
    }

#pragma unroll
    for (int mi = 0; mi < 4; ++mi) {
#pragma unroll
        for (int ni = 0; ni < 4; ++ni) {
            int col = bn + wn + ni * 8 + 2 * tig;
#pragma unroll
            for (int rs = 0; rs < 2; ++rs) {
                int row = bm + wm + mi * 16 + g + rs * 8;
                float v0 = acc[mi][ni][rs * 2], v1 = acc[mi][ni][rs * 2 + 1];
                if (MODE == 0) {
                    *(float2*)(C + (size_t)row * N + col) = make_float2(v0, v1);
                } else {
                    int path = col >> 10, lcol = col & 1023;
                    size_t off = (size_t)row * D_ + lcol;
                    if (path == 0) {
                        *(uint32_t*)(Qo + off) = pack_h2(__float2half_rn(v0), __float2half_rn(v1));
                    } else if (path == 1) {
                        *(uint32_t*)(Ko + off) = pack_h2(__float2half_rn(v0), __float2half_rn(v1));
                    } else {
                        uint32_t hi, lo;
                        split2(v0, v1, hi, lo);
                        *(uint32_t*)(Vho + off) = hi;
                        *(uint32_t*)(Vlo + off) = lo;
                    }
                }
            }
        }
    }
}

// ---------------------------------------------------------------------------
// FA2-style dual-path causal attention. Same as R12 passing version except
// the epilogue writes y as fp16 hi ONLY (out-proj is now uncompensated).
// ---------------------------------------------------------------------------
#define AS_QX 0
#define AS_QG 16384
#define AS_KV 32768
#define ATT_SMEM 98304

__global__ __launch_bounds__(256) void attn_fa(
    const __half* __restrict__ qh,  const __half* __restrict__ kh,
    const __half* __restrict__ vh,  const __half* __restrict__ vl,
    const __half* __restrict__ qgh, const __half* __restrict__ kgh,
    __half* __restrict__ yh) {
    extern __shared__ char sm[];
    const uint32_t sb = cvta_s(sm);
    const int tid  = threadIdx.x;
    const int warp = tid >> 5, lane = tid & 31;
    const int wmr  = warp * 16;
    const int bh = blockIdx.y, b = bh >> 4, h = bh & 15;
    const int rt = blockIdx.x;
    const int l4 = lane >> 2, l2 = lane & 3;
    const float SC = 0.125f / 6.931471805599453f;

    {
        const size_t qbase = ((size_t)b * L_ + (size_t)rt * 128) * D_ + h * HD_;
#pragma unroll
        for (int i = 0; i < 4; ++i) {
            int u = tid + 256 * i;
            int r = u >> 3, c = u & 7;
            uint32_t off = (uint32_t)(r * 128 + ((c ^ (r & 7)) * 16));
            CP16(sb + AS_QX + off, qh  + qbase + (size_t)r * D_ + c * 8);
            CP16(sb + AS_QG + off, qgh + qbase + (size_t)r * D_ + c * 8);
        }
    }

    const int arr = tid >> 6, t2 = tid & 63;
    const __half* kvsrc = (arr == 0) ? kh : (arr == 1) ? kgh : (arr == 2) ? vh : vl;
    const uint32_t kvdst = sb + AS_KV + (uint32_t)arr * 8192;
    const size_t bhbase = (size_t)b * L_ * D_ + h * HD_;

#define LOAD_KV(t, s)                                                              \
    do {                                                                           \
        const size_t kb = bhbase + (size_t)(t) * 64 * D_;                          \
        const uint32_t db = kvdst + (uint32_t)(s) * 32768;                         \
        _Pragma("unroll") for (int i = 0; i < 8; ++i) {                            \
            int u = t2 + 64 * i;                                                   \
            int r = u >> 3, c = u & 7;                                             \
            CP16(db + (uint32_t)(r * 128 + ((c ^ (r & 7)) * 16)),                  \
                 kvsrc + kb + (size_t)r * D_ + c * 8);                             \
        }                                                                          \
    } while (0)

    LOAD_KV(0, 0);
    CP_COMMIT();

    float m0 = -INFINITY, m1 = -INFINITY, l0 = 0.f, l1 = 0.f;
    float oacc[8][4];
#pragma unroll
    for (int ni = 0; ni < 8; ++ni)
#pragma unroll
        for (int r = 0; r < 4; ++r) oacc[ni][r] = 0.f;

    const int nt = 2 * rt + 2;
    for (int t = 0; t < nt; ++t) {
        CP_WAIT0();
        __syncthreads();
        if (t + 1 < nt) {
            LOAD_KV(t + 1, (t + 1) & 1);
            CP_COMMIT();
        }
        const uint32_t stg = sb + AS_KV + (uint32_t)(t & 1) * 32768;

        const bool skip = (t * 64) > (rt * 128 + wmr + 15);
        if (!skip) {
            float sacc[8][4];
#pragma unroll
            for (int ni = 0; ni < 8; ++ni)
#pragma unroll
                for (int r = 0; r < 4; ++r) sacc[ni][r] = 0.f;

#pragma unroll
            for (int kc = 0; kc < 4; ++kc) {
                int rA = wmr + (lane & 15);
                int cA = kc * 2 + (lane >> 4);
                uint32_t ada = sb + (uint32_t)(rA * 128 + ((cA ^ (rA & 7)) * 16));
                uint32_t qx[4], qg[4];
                LDSM4(qx[0], qx[1], qx[2], qx[3], ada + AS_QX);
                LDSM4(qg[0], qg[1], qg[2], qg[3], ada + AS_QG);

                int rB = (lane & 7) + ((lane >> 4) << 3);
                int cB = kc * 2 + ((lane >> 3) & 1);
#pragma unroll
                for (int nb = 0; nb < 4; ++nb) {
                    int r = nb * 16 + rB;
                    uint32_t adb = stg + (uint32_t)(r * 128 + ((cB ^ (r & 7)) * 16));
                    uint32_t k0, k1, k2, k3;
                    LDSM4(k0, k1, k2, k3, adb);
                    mma_f16(sacc[nb * 2],     qx[0], qx[1], qx[2], qx[3], k0, k1);
                    mma_f16(sacc[nb * 2 + 1], qx[0], qx[1], qx[2], qx[3], k2, k3);
                    LDSM4(k0, k1, k2, k3, adb + 8192);
                    mma_f16(sacc[nb * 2],     qg[0], qg[1], qg[2], qg[3], k0, k1);
                    mma_f16(sacc[nb * 2 + 1], qg[0], qg[1], qg[2], qg[3], k2, k3);
                }
            }

            const int rowg0 = rt * 128 + wmr + l4;
            const bool maskneed = (t * 64 + 63) > (rt * 128 + wmr);
#pragma unroll
            for (int ni = 0; ni < 8; ++ni)
#pragma unroll
                for (int c = 0; c < 4; ++c) {
                    sacc[ni][c] *= SC;
                    if (maskneed) {
                        int colg = t * 64 + ni * 8 + 2 * l2 + (c & 1);
                        int rowg = rowg0 + ((c >> 1) & 1) * 8;
                        if (colg > rowg) sacc[ni][c] = -INFINITY;
                    }
                }

            float mx0 = -INFINITY, mx1 = -INFINITY;
#pragma unroll
            for (int ni = 0; ni < 8; ++ni) {
                mx0 = fmaxf(mx0, fmaxf(sacc[ni][0], sacc[ni][1]));
                mx1 = fmaxf(mx1, fmaxf(sacc[ni][2], sacc[ni][3]));
            }
            mx0 = fmaxf(mx0, __shfl_xor_sync(0xffffffffu, mx0, 1));
            mx0 = fmaxf(mx0, __shfl_xor_sync(0xffffffffu, mx0, 2));
            mx1 = fmaxf(mx1, __shfl_xor_sync(0xffffffffu, mx1, 1));
            mx1 = fmaxf(mx1, __shfl_xor_sync(0xffffffffu, mx1, 2));
            float mn0 = fmaxf(m0, mx0), mn1 = fmaxf(m1, mx1);
            float al0 = __expf(m0 - mn0), al1 = __expf(m1 - mn1);
            m0 = mn0; m1 = mn1;

            uint32_t ph[8][2], pl[8][2];
            float ps0 = 0.f, ps1 = 0.f;
#pragma unroll
            for (int ni = 0; ni < 8; ++ni) {
                float p0 = __expf(sacc[ni][0] - mn0);
                float p1 = __expf(sacc[ni][1] - mn0);
                float p2 = __expf(sacc[ni][2] - mn1);
                float p3 = __expf(sacc[ni][3] - mn1);
                ps0 += p0 + p1; ps1 += p2 + p3;
                split2(p0, p1, ph[ni][0], pl[ni][0]);
                split2(p2, p3, ph[ni][1], pl[ni][1]);
                oacc[ni][0] *= al0; oacc[ni][1] *= al0;
                oacc[ni][2] *= al1; oacc[ni][3] *= al1;
            }
            ps0 += __shfl_xor_sync(0xffffffffu, ps0, 1);
            ps0 += __shfl_xor_sync(0xffffffffu, ps0, 2);
            ps1 += __shfl_xor_sync(0xffffffffu, ps1, 1);
            ps1 += __shfl_xor_sync(0xffffffffu, ps1, 2);
            l0 = l0 * al0 + ps0;
            l1 = l1 * al1 + ps1;

#pragma unroll
            for (int kc = 0; kc < 4; ++kc) {
                uint32_t a0 = ph[2 * kc][0], a1 = ph[2 * kc][1];
                uint32_t a2 = ph[2 * kc + 1][0], a3 = ph[2 * kc + 1][1];
                uint32_t c0 = pl[2 * kc][0], c1 = pl[2 * kc][1];
                uint32_t c2 = pl[2 * kc + 1][0], c3 = pl[2 * kc + 1][1];
                int rV = kc * 16 + (lane & 7) + (((lane >> 3) & 1) << 3);
#pragma unroll
                for (int db = 0; db < 4; ++db) {
                    int cV = db * 2 + (lane >> 4);
                    uint32_t adv = stg + 16384 + (uint32_t)(rV * 128 + ((cV ^ (rV & 7)) * 16));
                    uint32_t vh0, vh1, vh2, vh3, vl0, vl1, vl2, vl3;
                    LDSM4T(vh0, vh1, vh2, vh3, adv);
                    LDSM4T(vl0, vl1, vl2, vl3, adv + 8192);
                    mma_f16(oacc[db * 2],     a0, a1, a2, a3, vh0, vh1);
                    mma_f16(oacc[db * 2],     a0, a1, a2, a3, vl0, vl1);
                    mma_f16(oacc[db * 2],     c0, c1, c2, c3, vh0, vh1);
                    mma_f16(oacc[db * 2 + 1], a0, a1, a2, a3, vh2, vh3);
                    mma_f16(oacc[db * 2 + 1], a0, a1, a2, a3, vl2, vl3);
                    mma_f16(oacc[db * 2 + 1], c0, c1, c2, c3, vh2, vh3);
                }
            }
        }
    }

    const float inv0 = 1.f / l0, inv1 = 1.f / l1;
#pragma unroll
    for (int rh = 0; rh < 2; ++rh) {
        int row = wmr + l4 + rh * 8;
        float inv = rh ? inv1 : inv0;
        size_t base = ((size_t)b * L_ + (size_t)rt * 128 + row) * D_ + h * HD_;
#pragma unroll
        for (int ni = 0; ni < 8; ++ni) {
            int col = ni * 8 + 2 * l2;
            *(uint32_t*)(yh + base + col) =
                pack_h2(__float2half_rn(oacc[ni][rh * 2] * inv),
                        __float2half_rn(oacc[ni][rh * 2 + 1] * inv));
        }
    }
}

// ---------------------------------------------------------------------------
extern "C" void kernel_launch(void* const* d_in, const int* in_sizes, int n_in,
                              void* d_out, int out_size) {
    const float* x    = (const float*)d_in[0];
    const float* q_g  = (const float*)d_in[1];
    const float* k_g  = (const float*)d_in[2];
    const float* Wqkv = (const float*)d_in[3];
    const float* Wout = (const float*)d_in[4];
    float* out = (float*)d_out;

    __half *xh, *xl, *wqh, *wql, *woh;
    __half *qh, *kh, *vh, *vl, *qgh, *kgh, *yh;
    cudaGetSymbolAddress((void**)&xh,  g_xh);
    cudaGetSymbolAddress((void**)&xl,  g_xl);
    cudaGetSymbolAddress((void**)&wqh, g_wqh);
    cudaGetSymbolAddress((void**)&wql, g_wql);
    cudaGetSymbolAddress((void**)&woh, g_woh);
    cudaGetSymbolAddress((void**)&qh,  g_qh);
    cudaGetSymbolAddress((void**)&kh,  g_kh);
    cudaGetSymbolAddress((void**)&vh,  g_vh);
    cudaGetSymbolAddress((void**)&vl,  g_vl);
    cudaGetSymbolAddress((void**)&qgh, g_qgh);
    cudaGetSymbolAddress((void**)&kgh, g_kgh);
    cudaGetSymbolAddress((void**)&yh,  g_yh);

    cudaFuncSetAttribute(tgemm_h<0, false>,
                         cudaFuncAttributeMaxDynamicSharedMemorySize, GEMM_SMEM);
    cudaFuncSetAttribute(tgemm_h<1, true>,
                         cudaFuncAttributeMaxDynamicSharedMemorySize, GEMM_SMEM);
    cudaFuncSetAttribute(tgemm_h<1, false>,
                         cudaFuncAttributeMaxDynamicSharedMemorySize, GEMM_SMEM);
    cudaFuncSetAttribute(attn_fa,
                         cudaFuncAttributeMaxDynamicSharedMemorySize, ATT_SMEM);

    const int NX  = B_ * L_ * D_ / 4;
    const int NWQ = D3_ * D_ / 4;
    const int NWO = D_ * D_ / 4;

    split_kernel<<<(NX + 255) / 256, 256>>>((const float4*)x, (uint2*)xh, (uint2*)xl, NX);
    split_kernel<<<(NWQ + 255) / 256, 256>>>((const float4*)Wqkv, (uint2*)wqh, (uint2*)wql, NWQ);
    split_hi_kernel<<<(NWO + 255) / 256, 256>>>((const float4*)Wout, (uint2*)woh, NWO);
    split_hi_kernel<<<(NX + 255) / 256, 256>>>((const float4*)q_g, (uint2*)qgh, NX);
    split_hi_kernel<<<(NX + 255) / 256, 256>>>((const float4*)k_g, (uint2*)kgh, NX);

    // 1a) q,k columns [0, 2048): hi-only (q,k get rounded to fp16 anyway)
    tgemm_h<1, false><<<dim3(16, 32), 256, GEMM_SMEM>>>(
        xh, xl, wqh, wql, nullptr, qh, kh, vh, vl, B_ * L_, D3_, D_, 0);
    // 1b) v columns [2048, 3072): compensated (feeds y directly)
    tgemm_h<1, true><<<dim3(8, 32), 256, GEMM_SMEM>>>(
        xh, xl, wqh, wql, nullptr, qh, kh, vh, vl, B_ * L_, D3_, D_, 2048);

    // 2) attention -> fp16 y (hi only)
    attn_fa<<<dim3(L_ / 128, B_ * H_), 256, ATT_SMEM>>>(qh, kh, vh, vl, qgh, kgh, yh);

    // 3) out projection -> fp32 out (hi-only, uncompensated)
    tgemm_h<0, false><<<dim3(8, 32), 256, GEMM_SMEM>>>(
        yh, nullptr, woh, nullptr, out, nullptr, nullptr, nullptr, nullptr,
        B_ * L_, D_, D_, 0);
}

// round 15
// speedup vs baseline: 4.8055x; 1.1429x over previous
#include <cuda_runtime.h>
#include <cuda_fp16.h>
#include <math.h>
#include <stdint.h>

#define B_  4
#define L_  1024
#define D_  1024
#define H_  16
#define HD_ 64
#define D3_ 3072

// ---------------------------------------------------------------------------
// Scratch (device globals; no allocation)
// ---------------------------------------------------------------------------
__device__ __half g_xh[(size_t)B_ * L_ * D_];
__device__ __half g_wqh[(size_t)D3_ * D_];
__device__ __half g_woh[(size_t)D_ * D_];
__device__ __half g_qh[(size_t)B_ * L_ * D_];
__device__ __half g_kh[(size_t)B_ * L_ * D_];
__device__ __half g_vh[(size_t)B_ * L_ * D_],  g_vl[(size_t)B_ * L_ * D_];
__device__ __half g_qgh[(size_t)B_ * L_ * D_], g_kgh[(size_t)B_ * L_ * D_];
__device__ __half g_yh[(size_t)B_ * L_ * D_];

// ---------------------------------------------------------------------------
// helpers
// ---------------------------------------------------------------------------
__device__ __forceinline__ uint32_t cvta_s(const void* p) {
    return (uint32_t)__cvta_generic_to_shared(p);
}
__device__ __forceinline__ uint32_t pack_h2(__half a, __half b) {
    __half2 h = __halves2half2(a, b);
    return *(uint32_t*)&h;
}
__device__ __forceinline__ void split2(float x0, float x1, uint32_t& hi, uint32_t& lo) {
    __half h0 = __float2half_rn(x0);
    __half h1 = __float2half_rn(x1);
    __half l0 = __float2half_rn(x0 - __half2float(h0));
    __half l1 = __float2half_rn(x1 - __half2float(h1));
    hi = pack_h2(h0, h1);
    lo = pack_h2(l0, l1);
}
__device__ __forceinline__ void mma_f16(float* c,
                                        uint32_t a0, uint32_t a1, uint32_t a2, uint32_t a3,
                                        uint32_t b0, uint32_t b1) {
    asm volatile(
        "mma.sync.aligned.m16n8k16.row.col.f32.f16.f16.f32 "
        "{%0,%1,%2,%3},{%4,%5,%6,%7},{%8,%9},{%0,%1,%2,%3};\n"
        : "+f"(c[0]), "+f"(c[1]), "+f"(c[2]), "+f"(c[3])
        : "r"(a0), "r"(a1), "r"(a2), "r"(a3), "r"(b0), "r"(b1));
}
#define LDSM4(r0, r1, r2, r3, addr) \
    asm volatile("ldmatrix.sync.aligned.m8n8.x4.shared.b16 {%0,%1,%2,%3},[%4];\n" \
                 : "=r"(r0), "=r"(r1), "=r"(r2), "=r"(r3) : "r"(addr))
#define LDSM4T(r0, r1, r2, r3, addr) \
    asm volatile("ldmatrix.sync.aligned.m8n8.x4.trans.shared.b16 {%0,%1,%2,%3},[%4];\n" \
                 : "=r"(r0), "=r"(r1), "=r"(r2), "=r"(r3) : "r"(addr))
#define CP16(saddr, gptr) \
    asm volatile("cp.async.cg.shared.global [%0], [%1], 16;\n" :: "r"(saddr), "l"(gptr))
#define CP_COMMIT() asm volatile("cp.async.commit_group;\n")
#define CP_WAIT0()  asm volatile("cp.async.wait_group 0;\n")
#define CP_WAIT2()  asm volatile("cp.async.wait_group 2;\n")

// ---------------------------------------------------------------------------
// split kernel (hi only)
// ---------------------------------------------------------------------------
__global__ __launch_bounds__(256) void split_hi_kernel(const float4* __restrict__ in,
                                                       uint2* __restrict__ hi, int n4) {
    int i = blockIdx.x * blockDim.x + threadIdx.x;
    if (i >= n4) return;
    float4 v = in[i];
    hi[i] = make_uint2(pack_h2(__float2half_rn(v.x), __float2half_rn(v.y)),
                       pack_h2(__float2half_rn(v.z), __float2half_rn(v.w)));
}

// ---------------------------------------------------------------------------
// Tensor-core GEMM (NT) on fp16 hi operands, 1 MMA (uncompensated).
// 128x128 tile, BK=16, 8 warps (2m x 4n). cp.async 4-stage, swizzled rows.
// MODE 0: write fp32 C. MODE 1: qkv epilogue (q,k fp16-hi; v fp32->hi+lo).
// Smem stage: A 4K @0, B 4K @8192 (offsets match prior layout; lo slots unused).
// ---------------------------------------------------------------------------
#define STAGE_B 16384
#define GEMM_SMEM 65536

template <int MODE>
__global__ __launch_bounds__(256) void tgemm_h(const __half* __restrict__ Ah,
                                               const __half* __restrict__ Bh,
                                               float* __restrict__ C,
                                               __half* __restrict__ Qo,
                                               __half* __restrict__ Ko,
                                               __half* __restrict__ Vho,
                                               __half* __restrict__ Vlo,
                                               int M, int N, int K, int bn0) {
    extern __shared__ char sm[];
    const uint32_t sbase = cvta_s(sm);

    const int tid  = threadIdx.x;
    const int warp = tid >> 5, lane = tid & 31;
    const int g = lane >> 2, tig = lane & 3;
    const int wm = (warp >> 2) * 64;
    const int wn = (warp & 3) * 32;
    const int bm = blockIdx.y * 128, bn = bn0 + blockIdx.x * 128;

    // loaders: arr 0 -> A (128 rows), arr 2 -> B (128 rows); arr 1,3 idle
    const int arr = tid >> 6;
    const int t2  = tid & 63;
    const bool loader = (arr == 0) || (arr == 2);
    const __half* gsrc = (arr == 2) ? Bh + (size_t)bn * K : Ah + (size_t)bm * K;
    int rows[4], csrc[4];
    uint32_t soff[4];
#pragma unroll
    for (int i = 0; i < 4; ++i) {
        int u = t2 + 64 * i;
        int r = u >> 1, c = u & 1;
        rows[i] = r; csrc[i] = c;
        soff[i] = (uint32_t)(((arr == 2) ? 8192 : 0) + r * 32 + ((c ^ ((r >> 2) & 1)) * 16));
    }

    uint32_t aoff[4];
#pragma unroll
    for (int mi = 0; mi < 4; ++mi) {
        int r = wm + mi * 16 + (lane & 15);
        int c = lane >> 4;
        aoff[mi] = (uint32_t)(r * 32 + ((c ^ ((r >> 2) & 1)) * 16));
    }
    uint32_t boff[2];
#pragma unroll
    for (int nb = 0; nb < 2; ++nb) {
        int r = wn + nb * 16 + (lane & 7) + ((lane >> 4) << 3);
        int c = (lane >> 3) & 1;
        boff[nb] = (uint32_t)(8192 + r * 32 + ((c ^ ((r >> 2) & 1)) * 16));
    }

    float acc[4][4][4];
#pragma unroll
    for (int mi = 0; mi < 4; ++mi)
#pragma unroll
        for (int ni = 0; ni < 4; ++ni)
#pragma unroll
            for (int r = 0; r < 4; ++r) acc[mi][ni][r] = 0.f;

    const int nk = K >> 4;
#pragma unroll
    for (int s = 0; s < 3; ++s) {
        const uint32_t sb = sbase + s * STAGE_B;
        if (loader) {
#pragma unroll
            for (int i = 0; i < 4; ++i)
                CP16(sb + soff[i], gsrc + (size_t)rows[i] * K + s * 16 + csrc[i] * 8);
        }
        CP_COMMIT();
    }
    CP_WAIT2();
    __syncthreads();

    for (int kt = 0; kt < nk; ++kt) {
        const uint32_t stg = sbase + (uint32_t)(kt & 3) * STAGE_B;

        uint32_t bh[4][2];
#pragma unroll
        for (int nb = 0; nb < 2; ++nb) {
            uint32_t r0, r1, r2, r3;
            LDSM4(r0, r1, r2, r3, stg + boff[nb]);
            bh[nb * 2][0] = r0; bh[nb * 2][1] = r1;
            bh[nb * 2 + 1][0] = r2; bh[nb * 2 + 1][1] = r3;
        }

#pragma unroll
        for (int mi = 0; mi < 4; ++mi) {
            uint32_t ah[4];
            LDSM4(ah[0], ah[1], ah[2], ah[3], stg + aoff[mi]);
#pragma unroll
            for (int ni = 0; ni < 4; ++ni)
                mma_f16(acc[mi][ni], ah[0], ah[1], ah[2], ah[3], bh[ni][0], bh[ni][1]);
        }

        if (kt + 3 < nk) {
            const uint32_t sb = sbase + (uint32_t)((kt + 3) & 3) * STAGE_B;
            if (loader) {
#pragma unroll
                for (int i = 0; i < 4; ++i)
                    CP16(sb + soff[i], gsrc + (size_t)rows[i] * K + (kt + 3) * 16 + csrc[i] * 8);
            }
        }
        CP_COMMIT();
        CP_WAIT2();
        __syncthreads();
    }

#pragma unroll
    for (int mi = 0; mi < 4; ++mi) {
#pragma unroll
        for (int ni = 0; ni < 4; ++ni) {
            int col = bn + wn + ni * 8 + 2 * tig;
#pragma unroll
            for (int rs = 0; rs < 2; ++rs) {
                int row = bm + wm + mi * 16 + g + rs * 8;
                float v0 = acc[mi][ni][rs * 2], v1 = acc[mi][ni][rs * 2 + 1];
                if (MODE == 0) {
                    *(float2*)(C + (size_t)row * N + col) = make_float2(v0, v1);
                } else {
                    int path = col >> 10, lcol = col & 1023;
                    size_t off = (size_t)row * D_ + lcol;
                    if (path == 0) {
                        *(uint32_t*)(Qo + off) = pack_h2(__float2half_rn(v0), __float2half_rn(v1));
                    } else if (path == 1) {
                        *(uint32_t*)(Ko + off) = pack_h2(__float2half_rn(v0), __float2half_rn(v1));
                    } else {
                        uint32_t hi, lo;
                        split2(v0, v1, hi, lo);
                        *(uint32_t*)(Vho + off) = hi;
                        *(uint32_t*)(Vlo + off) = lo;
                    }
                }
            }
        }
    }
}

// ---------------------------------------------------------------------------
// FA2-style dual-path causal attention (unchanged from R14 passing version:
// PV hi/lo compensated, y written as fp16 hi only).
// ---------------------------------------------------------------------------
#define AS_QX 0
#define AS_QG 16384
#define AS_KV 32768
#define ATT_SMEM 98304

__global__ __launch_bounds__(256) void attn_fa(
    const __half* __restrict__ qh,  const __half* __restrict__ kh,
    const __half* __restrict__ vh,  const __half* __restrict__ vl,
    const __half* __restrict__ qgh, const __half* __restrict__ kgh,
    __half* __restrict__ yh) {
    extern __shared__ char sm[];
    const uint32_t sb = cvta_s(sm);
    const int tid  = threadIdx.x;
    const int warp = tid >> 5, lane = tid & 31;
    const int wmr  = warp * 16;
    const int bh = blockIdx.y, b = bh >> 4, h = bh & 15;
    const int rt = blockIdx.x;
    const int l4 = lane >> 2, l2 = lane & 3;
    const float SC = 0.125f / 6.931471805599453f;

    {
        const size_t qbase = ((size_t)b * L_ + (size_t)rt * 128) * D_ + h * HD_;
#pragma unroll
        for (int i = 0; i < 4; ++i) {
            int u = tid + 256 * i;
            int r = u >> 3, c = u & 7;
            uint32_t off = (uint32_t)(r * 128 + ((c ^ (r & 7)) * 16));
            CP16(sb + AS_QX + off, qh  + qbase + (size_t)r * D_ + c * 8);
            CP16(sb + AS_QG + off, qgh + qbase + (size_t)r * D_ + c * 8);
        }
    }

    const int arr = tid >> 6, t2 = tid & 63;
    const __half* kvsrc = (arr == 0) ? kh : (arr == 1) ? kgh : (arr == 2) ? vh : vl;
    const uint32_t kvdst = sb + AS_KV + (uint32_t)arr * 8192;
    const size_t bhbase = (size_t)b * L_ * D_ + h * HD_;

#define LOAD_KV(t, s)                                                              \
    do {                                                                           \
        const size_t kb = bhbase + (size_t)(t) * 64 * D_;                          \
        const uint32_t db = kvdst + (uint32_t)(s) * 32768;                         \
        _Pragma("unroll") for (int i = 0; i < 8; ++i) {                            \
            int u = t2 + 64 * i;                                                   \
            int r = u >> 3, c = u & 7;                                             \
            CP16(db + (uint32_t)(r * 128 + ((c ^ (r & 7)) * 16)),                  \
                 kvsrc + kb + (size_t)r * D_ + c * 8);                             \
        }                                                                          \
    } while (0)

    LOAD_KV(0, 0);
    CP_COMMIT();

    float m0 = -INFINITY, m1 = -INFINITY, l0 = 0.f, l1 = 0.f;
    float oacc[8][4];
#pragma unroll
    for (int ni = 0; ni < 8; ++ni)
#pragma unroll
        for (int r = 0; r < 4; ++r) oacc[ni][r] = 0.f;

    const int nt = 2 * rt + 2;
    for (int t = 0; t < nt; ++t) {
        CP_WAIT0();
        __syncthreads();
        if (t + 1 < nt) {
            LOAD_KV(t + 1, (t + 1) & 1);
            CP_COMMIT();
        }
        const uint32_t stg = sb + AS_KV + (uint32_t)(t & 1) * 32768;

        const bool skip = (t * 64) > (rt * 128 + wmr + 15);
        if (!skip) {
            float sacc[8][4];
#pragma unroll
            for (int ni = 0; ni < 8; ++ni)
#pragma unroll
                for (int r = 0; r < 4; ++r) sacc[ni][r] = 0.f;

#pragma unroll
            for (int kc = 0; kc < 4; ++kc) {
                int rA = wmr + (lane & 15);
                int cA = kc * 2 + (lane >> 4);
                uint32_t ada = sb + (uint32_t)(rA * 128 + ((cA ^ (rA & 7)) * 16));
                uint32_t qx[4], qg[4];
                LDSM4(qx[0], qx[1], qx[2], qx[3], ada + AS_QX);
                LDSM4(qg[0], qg[1], qg[2], qg[3], ada + AS_QG);

                int rB = (lane & 7) + ((lane >> 4) << 3);
                int cB = kc * 2 + ((lane >> 3) & 1);
#pragma unroll
                for (int nb = 0; nb < 4; ++nb) {
                    int r = nb * 16 + rB;
                    uint32_t adb = stg + (uint32_t)(r * 128 + ((cB ^ (r & 7)) * 16));
                    uint32_t k0, k1, k2, k3;
                    LDSM4(k0, k1, k2, k3, adb);
                    mma_f16(sacc[nb * 2],     qx[0], qx[1], qx[2], qx[3], k0, k1);
                    mma_f16(sacc[nb * 2 + 1], qx[0], qx[1], qx[2], qx[3], k2, k3);
                    LDSM4(k0, k1, k2, k3, adb + 8192);
                    mma_f16(sacc[nb * 2],     qg[0], qg[1], qg[2], qg[3], k0, k1);
                    mma_f16(sacc[nb * 2 + 1], qg[0], qg[1], qg[2], qg[3], k2, k3);
                }
            }

            const int rowg0 = rt * 128 + wmr + l4;
            const bool maskneed = (t * 64 + 63) > (rt * 128 + wmr);
#pragma unroll
            for (int ni = 0; ni < 8; ++ni)
#pragma unroll
                for (int c = 0; c < 4; ++c) {
                    sacc[ni][c] *= SC;
                    if (maskneed) {
                        int colg = t * 64 + ni * 8 + 2 * l2 + (c & 1);
                        int rowg = rowg0 + ((c >> 1) & 1) * 8;
                        if (colg > rowg) sacc[ni][c] = -INFINITY;
                    }
                }

            float mx0 = -INFINITY, mx1 = -INFINITY;
#pragma unroll
            for (int ni = 0; ni < 8; ++ni) {
                mx0 = fmaxf(mx0, fmaxf(sacc[ni][0], sacc[ni][1]));
                mx1 = fmaxf(mx1, fmaxf(sacc[ni][2], sacc[ni][3]));
            }
            mx0 = fmaxf(mx0, __shfl_xor_sync(0xffffffffu, mx0, 1));
            mx0 = fmaxf(mx0, __shfl_xor_sync(0xffffffffu, mx0, 2));
            mx1 = fmaxf(mx1, __shfl_xor_sync(0xffffffffu, mx1, 1));
            mx1 = fmaxf(mx1, __shfl_xor_sync(0xffffffffu, mx1, 2));
            float mn0 = fmaxf(m0, mx0), mn1 = fmaxf(m1, mx1);
            float al0 = __expf(m0 - mn0), al1 = __expf(m1 - mn1);
            m0 = mn0; m1 = mn1;

            uint32_t ph[8][2], pl[8][2];
            float ps0 = 0.f, ps1 = 0.f;
#pragma unroll
            for (int ni = 0; ni < 8; ++ni) {
                float p0 = __expf(sacc[ni][0] - mn0);
                float p1 = __expf(sacc[ni][1] - mn0);
                float p2 = __expf(sacc[ni][2] - mn1);
                float p3 = __expf(sacc[ni][3] - mn1);
                ps0 += p0 + p1; ps1 += p2 + p3;
                split2(p0, p1, ph[ni][0], pl[ni][0]);
                split2(p2, p3, ph[ni][1], pl[ni][1]);
                oacc[ni][0] *= al0; oacc[ni][1] *= al0;
                oacc[ni][2] *= al1; oacc[ni][3] *= al1;
            }
            ps0 += __shfl_xor_sync(0xffffffffu, ps0, 1);
            ps0 += __shfl_xor_sync(0xffffffffu, ps0, 2);
            ps1 += __shfl_xor_sync(0xffffffffu, ps1, 1);
            ps1 += __shfl_xor_sync(0xffffffffu, ps1, 2);
            l0 = l0 * al0 + ps0;
            l1 = l1 * al1 + ps1;

#pragma unroll
            for (int kc = 0; kc < 4; ++kc) {
                uint32_t a0 = ph[2 * kc][0], a1 = ph[2 * kc][1];
                uint32_t a2 = ph[2 * kc + 1][0], a3 = ph[2 * kc + 1][1];
                uint32_t c0 = pl[2 * kc][0], c1 = pl[2 * kc][1];
                uint32_t c2 = pl[2 * kc + 1][0], c3 = pl[2 * kc + 1][1];
                int rV = kc * 16 + (lane & 7) + (((lane >> 3) & 1) << 3);
#pragma unroll
                for (int db = 0; db < 4; ++db) {
                    int cV = db * 2 + (lane >> 4);
                    uint32_t adv = stg + 16384 + (uint32_t)(rV * 128 + ((cV ^ (rV & 7)) * 16));
                    uint32_t vh0, vh1, vh2, vh3, vl0, vl1, vl2, vl3;
                    LDSM4T(vh0, vh1, vh2, vh3, adv);
                    LDSM4T(vl0, vl1, vl2, vl3, adv + 8192);
                    mma_f16(oacc[db * 2],     a0, a1, a2, a3, vh0, vh1);
                    mma_f16(oacc[db * 2],     a0, a1, a2, a3, vl0, vl1);
                    mma_f16(oacc[db * 2],     c0, c1, c2, c3, vh0, vh1);
                    mma_f16(oacc[db * 2 + 1], a0, a1, a2, a3, vh2, vh3);
                    mma_f16(oacc[db * 2 + 1], a0, a1, a2, a3, vl2, vl3);
                    mma_f16(oacc[db * 2 + 1], c0, c1, c2, c3, vh2, vh3);
                }
            }
        }
    }

    const float inv0 = 1.f / l0, inv1 = 1.f / l1;
#pragma unroll
    for (int rh = 0; rh < 2; ++rh) {
        int row = wmr + l4 + rh * 8;
        float inv = rh ? inv1 : inv0;
        size_t base = ((size_t)b * L_ + (size_t)rt * 128 + row) * D_ + h * HD_;
#pragma unroll
        for (int ni = 0; ni < 8; ++ni) {
            int col = ni * 8 + 2 * l2;
            *(uint32_t*)(yh + base + col) =
                pack_h2(__float2half_rn(oacc[ni][rh * 2] * inv),
                        __float2half_rn(oacc[ni][rh * 2 + 1] * inv));
        }
    }
}

// ---------------------------------------------------------------------------
extern "C" void kernel_launch(void* const* d_in, const int* in_sizes, int n_in,
                              void* d_out, int out_size) {
    const float* x    = (const float*)d_in[0];
    const float* q_g  = (const float*)d_in[1];
    const float* k_g  = (const float*)d_in[2];
    const float* Wqkv = (const float*)d_in[3];
    const float* Wout = (const float*)d_in[4];
    float* out = (float*)d_out;

    __half *xh, *wqh, *woh;
    __half *qh, *kh, *vh, *vl, *qgh, *kgh, *yh;
    cudaGetSymbolAddress((void**)&xh,  g_xh);
    cudaGetSymbolAddress((void**)&wqh, g_wqh);
    cudaGetSymbolAddress((void**)&woh, g_woh);
    cudaGetSymbolAddress((void**)&qh,  g_qh);
    cudaGetSymbolAddress((void**)&kh,  g_kh);
    cudaGetSymbolAddress((void**)&vh,  g_vh);
    cudaGetSymbolAddress((void**)&vl,  g_vl);
    cudaGetSymbolAddress((void**)&qgh, g_qgh);
    cudaGetSymbolAddress((void**)&kgh, g_kgh);
    cudaGetSymbolAddress((void**)&yh,  g_yh);

    cudaFuncSetAttribute(tgemm_h<0>,
                         cudaFuncAttributeMaxDynamicSharedMemorySize, GEMM_SMEM);
    cudaFuncSetAttribute(tgemm_h<1>,
                         cudaFuncAttributeMaxDynamicSharedMemorySize, GEMM_SMEM);
    cudaFuncSetAttribute(attn_fa,
                         cudaFuncAttributeMaxDynamicSharedMemorySize, ATT_SMEM);

    const int NX  = B_ * L_ * D_ / 4;
    const int NWQ = D3_ * D_ / 4;
    const int NWO = D_ * D_ / 4;

    split_hi_kernel<<<(NX + 255) / 256, 256>>>((const float4*)x, (uint2*)xh, NX);
    split_hi_kernel<<<(NWQ + 255) / 256, 256>>>((const float4*)Wqkv, (uint2*)wqh, NWQ);
    split_hi_kernel<<<(NWO + 255) / 256, 256>>>((const float4*)Wout, (uint2*)woh, NWO);
    split_hi_kernel<<<(NX + 255) / 256, 256>>>((const float4*)q_g, (uint2*)qgh, NX);
    split_hi_kernel<<<(NX + 255) / 256, 256>>>((const float4*)k_g, (uint2*)kgh, NX);

    // 1) qkv projection, single hi-only launch over all 3072 columns.
    //    q,k stored fp16-hi; v stored as hi+lo split of the fp32 accumulator.
    tgemm_h<1><<<dim3(24, 32), 256, GEMM_SMEM>>>(
        xh, wqh, nullptr, qh, kh, vh, vl, B_ * L_, D3_, D_, 0);

    // 2) attention -> fp16 y (hi only); PV stays hi/lo compensated
    attn_fa<<<dim3(L_ / 128, B_ * H_), 256, ATT_SMEM>>>(qh, kh, vh, vl, qgh, kgh, yh);

    // 3) out projection -> fp32 out (hi-only)
    tgemm_h<0><<<dim3(8, 32), 256, GEMM_SMEM>>>(
        yh, woh, out, nullptr, nullptr, nullptr, nullptr, B_ * L_, D_, D_, 0);
}

// round 16
// speedup vs baseline: 5.3918x; 1.1220x over previous
#include <cuda_runtime.h>
#include <cuda_fp16.h>
#include <math.h>
#include <stdint.h>

#define B_  4
#define L_  1024
#define D_  1024
#define H_  16
#define HD_ 64
#define D3_ 3072

// ---------------------------------------------------------------------------
// Scratch (device globals; no allocation)
// ---------------------------------------------------------------------------
__device__ __half g_xh[(size_t)B_ * L_ * D_];
__device__ __half g_wqh[(size_t)D3_ * D_];
__device__ __half g_woh[(size_t)D_ * D_];
__device__ __half g_qh[(size_t)B_ * L_ * D_];
__device__ __half g_kh[(size_t)B_ * L_ * D_];
__device__ __half g_vh[(size_t)B_ * L_ * D_];
__device__ __half g_qgh[(size_t)B_ * L_ * D_], g_kgh[(size_t)B_ * L_ * D_];
__device__ __half g_yh[(size_t)B_ * L_ * D_];

// ---------------------------------------------------------------------------
// helpers
// ---------------------------------------------------------------------------
__device__ __forceinline__ uint32_t cvta_s(const void* p) {
    return (uint32_t)__cvta_generic_to_shared(p);
}
__device__ __forceinline__ uint32_t pack_h2(__half a, __half b) {
    __half2 h = __halves2half2(a, b);
    return *(uint32_t*)&h;
}
__device__ __forceinline__ void mma_f16(float* c,
                                        uint32_t a0, uint32_t a1, uint32_t a2, uint32_t a3,
                                        uint32_t b0, uint32_t b1) {
    asm volatile(
        "mma.sync.aligned.m16n8k16.row.col.f32.f16.f16.f32 "
        "{%0,%1,%2,%3},{%4,%5,%6,%7},{%8,%9},{%0,%1,%2,%3};\n"
        : "+f"(c[0]), "+f"(c[1]), "+f"(c[2]), "+f"(c[3])
        : "r"(a0), "r"(a1), "r"(a2), "r"(a3), "r"(b0), "r"(b1));
}
#define LDSM4(r0, r1, r2, r3, addr) \
    asm volatile("ldmatrix.sync.aligned.m8n8.x4.shared.b16 {%0,%1,%2,%3},[%4];\n" \
                 : "=r"(r0), "=r"(r1), "=r"(r2), "=r"(r3) : "r"(addr))
#define LDSM4T(r0, r1, r2, r3, addr) \
    asm volatile("ldmatrix.sync.aligned.m8n8.x4.trans.shared.b16 {%0,%1,%2,%3},[%4];\n" \
                 : "=r"(r0), "=r"(r1), "=r"(r2), "=r"(r3) : "r"(addr))
#define CP16(saddr, gptr) \
    asm volatile("cp.async.cg.shared.global [%0], [%1], 16;\n" :: "r"(saddr), "l"(gptr))
#define CP_COMMIT() asm volatile("cp.async.commit_group;\n")
#define CP_WAIT0()  asm volatile("cp.async.wait_group 0;\n")
#define CP_WAIT2()  asm volatile("cp.async.wait_group 2;\n")

// ---------------------------------------------------------------------------
// split kernel (hi only)
// ---------------------------------------------------------------------------
__global__ __launch_bounds__(256) void split_hi_kernel(const float4* __restrict__ in,
                                                       uint2* __restrict__ hi, int n4) {
    int i = blockIdx.x * blockDim.x + threadIdx.x;
    if (i >= n4) return;
    float4 v = in[i];
    hi[i] = make_uint2(pack_h2(__float2half_rn(v.x), __float2half_rn(v.y)),
                       pack_h2(__float2half_rn(v.z), __float2half_rn(v.w)));
}

// ---------------------------------------------------------------------------
// Tensor-core GEMM (NT) on fp16 operands, 1 MMA (uncompensated).
// 128x128 tile, BK=16, 8 warps (2m x 4n). cp.async 4-stage, swizzled rows.
// MODE 0: write fp32 C. MODE 1: qkv epilogue (q,k,v all fp16-hi).
// ---------------------------------------------------------------------------
#define STAGE_B 16384
#define GEMM_SMEM 65536

template <int MODE>
__global__ __launch_bounds__(256) void tgemm_h(const __half* __restrict__ Ah,
                                               const __half* __restrict__ Bh,
                                               float* __restrict__ C,
                                               __half* __restrict__ Qo,
                                               __half* __restrict__ Ko,
                                               __half* __restrict__ Vo,
                                               int M, int N, int K, int bn0) {
    extern __shared__ char sm[];
    const uint32_t sbase = cvta_s(sm);

    const int tid  = threadIdx.x;
    const int warp = tid >> 5, lane = tid & 31;
    const int g = lane >> 2, tig = lane & 3;
    const int wm = (warp >> 2) * 64;
    const int wn = (warp & 3) * 32;
    const int bm = blockIdx.y * 128, bn = bn0 + blockIdx.x * 128;

    // loaders: arr 0 -> A rows, arr 2 -> B rows; arr 1,3 idle
    const int arr = tid >> 6;
    const int t2  = tid & 63;
    const bool loader = (arr == 0) || (arr == 2);
    const __half* gsrc = (arr == 2) ? Bh + (size_t)bn * K : Ah + (size_t)bm * K;
    int rows[4], csrc[4];
    uint32_t soff[4];
#pragma unroll
    for (int i = 0; i < 4; ++i) {
        int u = t2 + 64 * i;
        int r = u >> 1, c = u & 1;
        rows[i] = r; csrc[i] = c;
        soff[i] = (uint32_t)(((arr == 2) ? 8192 : 0) + r * 32 + ((c ^ ((r >> 2) & 1)) * 16));
    }

    uint32_t aoff[4];
#pragma unroll
    for (int mi = 0; mi < 4; ++mi) {
        int r = wm + mi * 16 + (lane & 15);
        int c = lane >> 4;
        aoff[mi] = (uint32_t)(r * 32 + ((c ^ ((r >> 2) & 1)) * 16));
    }
    uint32_t boff[2];
#pragma unroll
    for (int nb = 0; nb < 2; ++nb) {
        int r = wn + nb * 16 + (lane & 7) + ((lane >> 4) << 3);
        int c = (lane >> 3) & 1;
        boff[nb] = (uint32_t)(8192 + r * 32 + ((c ^ ((r >> 2) & 1)) * 16));
    }

    float acc[4][4][4];
#pragma unroll
    for (int mi = 0; mi < 4; ++mi)
#pragma unroll
        for (int ni = 0; ni < 4; ++ni)
#pragma unroll
            for (int r = 0; r < 4; ++r) acc[mi][ni][r] = 0.f;

    const int nk = K >> 4;
#pragma unroll
    for (int s = 0; s < 3; ++s) {
        const uint32_t sb = sbase + s * STAGE_B;
        if (loader) {
#pragma unroll
            for (int i = 0; i < 4; ++i)
                CP16(sb + soff[i], gsrc + (size_t)rows[i] * K + s * 16 + csrc[i] * 8);
        }
        CP_COMMIT();
    }
    CP_WAIT2();
    __syncthreads();

    for (int kt = 0; kt < nk; ++kt) {
        const uint32_t stg = sbase + (uint32_t)(kt & 3) * STAGE_B;

        uint32_t bh[4][2];
#pragma unroll
        for (int nb = 0; nb < 2; ++nb) {
            uint32_t r0, r1, r2, r3;
            LDSM4(r0, r1, r2, r3, stg + boff[nb]);
            bh[nb * 2][0] = r0; bh[nb * 2][1] = r1;
            bh[nb * 2 + 1][0] = r2; bh[nb * 2 + 1][1] = r3;
        }

#pragma unroll
        for (int mi = 0; mi < 4; ++mi) {
            uint32_t ah[4];
            LDSM4(ah[0], ah[1], ah[2], ah[3], stg + aoff[mi]);
#pragma unroll
            for (int ni = 0; ni < 4; ++ni)
                mma_f16(acc[mi][ni], ah[0], ah[1], ah[2], ah[3], bh[ni][0], bh[ni][1]);
        }

        if (kt + 3 < nk) {
            const uint32_t sb = sbase + (uint32_t)((kt + 3) & 3) * STAGE_B;
            if (loader) {
#pragma unroll
                for (int i = 0; i < 4; ++i)
                    CP16(sb + soff[i], gsrc + (size_t)rows[i] * K + (kt + 3) * 16 + csrc[i] * 8);
            }
        }
        CP_COMMIT();
        CP_WAIT2();
        __syncthreads();
    }

#pragma unroll
    for (int mi = 0; mi < 4; ++mi) {
#pragma unroll
        for (int ni = 0; ni < 4; ++ni) {
            int col = bn + wn + ni * 8 + 2 * tig;
#pragma unroll
            for (int rs = 0; rs < 2; ++rs) {
                int row = bm + wm + mi * 16 + g + rs * 8;
                float v0 = acc[mi][ni][rs * 2], v1 = acc[mi][ni][rs * 2 + 1];
                if (MODE == 0) {
                    *(float2*)(C + (size_t)row * N + col) = make_float2(v0, v1);
                } else {
                    int path = col >> 10, lcol = col & 1023;
                    size_t off = (size_t)row * D_ + lcol;
                    __half* dst = (path == 0) ? Qo : (path == 1) ? Ko : Vo;
                    *(uint32_t*)(dst + off) = pack_h2(__float2half_rn(v0), __float2half_rn(v1));
                }
            }
        }
    }
}

// ---------------------------------------------------------------------------
// FA2-style dual-path causal attention, fully fp16 (no compensation).
// Br=128, Bc=64, 8 warps each owning 16 rows. KV stage: Kx 8K | Kg 8K | Vh 8K
// = 24KB x 2 stages. smem total 80KB.
// ---------------------------------------------------------------------------
#define AS_QX 0
#define AS_QG 16384
#define AS_KV 32768
#define KV_STAGE 24576
#define ATT_SMEM (32768 + 2 * KV_STAGE)

__global__ __launch_bounds__(256) void attn_fa(
    const __half* __restrict__ qh,  const __half* __restrict__ kh,
    const __half* __restrict__ vh,
    const __half* __restrict__ qgh, const __half* __restrict__ kgh,
    __half* __restrict__ yh) {
    extern __shared__ char sm[];
    const uint32_t sb = cvta_s(sm);
    const int tid  = threadIdx.x;
    const int warp = tid >> 5, lane = tid & 31;
    const int wmr  = warp * 16;
    const int bh = blockIdx.y, b = bh >> 4, h = bh & 15;
    const int rt = blockIdx.x;
    const int l4 = lane >> 2, l2 = lane & 3;
    const float SC = 0.125f / 6.931471805599453f;

    {
        const size_t qbase = ((size_t)b * L_ + (size_t)rt * 128) * D_ + h * HD_;
#pragma unroll
        for (int i = 0; i < 4; ++i) {
            int u = tid + 256 * i;
            int r = u >> 3, c = u & 7;
            uint32_t off = (uint32_t)(r * 128 + ((c ^ (r & 7)) * 16));
            CP16(sb + AS_QX + off, qh  + qbase + (size_t)r * D_ + c * 8);
            CP16(sb + AS_QG + off, qgh + qbase + (size_t)r * D_ + c * 8);
        }
    }

    // KV loaders: arr 0 -> Kx, 1 -> Kg, 2 -> Vh, 3 -> idle
    const int arr = tid >> 6, t2 = tid & 63;
    const bool kvload = (arr < 3);
    const __half* kvsrc = (arr == 0) ? kh : (arr == 1) ? kgh : vh;
    const uint32_t kvdst = sb + AS_KV + (uint32_t)arr * 8192;
    const size_t bhbase = (size_t)b * L_ * D_ + h * HD_;

#define LOAD_KV(t, s)                                                              \
    do {                                                                           \
        if (kvload) {                                                              \
            const size_t kb = bhbase + (size_t)(t) * 64 * D_;                      \
            const uint32_t db = kvdst + (uint32_t)(s) * KV_STAGE;                  \
            _Pragma("unroll") for (int i = 0; i < 8; ++i) {                        \
                int u = t2 + 64 * i;                                               \
                int r = u >> 3, c = u & 7;                                         \
                CP16(db + (uint32_t)(r * 128 + ((c ^ (r & 7)) * 16)),              \
                     kvsrc + kb + (size_t)r * D_ + c * 8);                         \
            }                                                                      \
        }                                                                          \
    } while (0)

    LOAD_KV(0, 0);
    CP_COMMIT();

    float m0 = -INFINITY, m1 = -INFINITY, l0 = 0.f, l1 = 0.f;
    float oacc[8][4];
#pragma unroll
    for (int ni = 0; ni < 8; ++ni)
#pragma unroll
        for (int r = 0; r < 4; ++r) oacc[ni][r] = 0.f;

    const int nt = 2 * rt + 2;
    for (int t = 0; t < nt; ++t) {
        CP_WAIT0();
        __syncthreads();
        if (t + 1 < nt) {
            LOAD_KV(t + 1, (t + 1) & 1);
            CP_COMMIT();
        }
        const uint32_t stg = sb + AS_KV + (uint32_t)(t & 1) * KV_STAGE;

        const bool skip = (t * 64) > (rt * 128 + wmr + 15);
        if (!skip) {
            float sacc[8][4];
#pragma unroll
            for (int ni = 0; ni < 8; ++ni)
#pragma unroll
                for (int r = 0; r < 4; ++r) sacc[ni][r] = 0.f;

#pragma unroll
            for (int kc = 0; kc < 4; ++kc) {
                int rA = wmr + (lane & 15);
                int cA = kc * 2 + (lane >> 4);
                uint32_t ada = sb + (uint32_t)(rA * 128 + ((cA ^ (rA & 7)) * 16));
                uint32_t qx[4], qg[4];
                LDSM4(qx[0], qx[1], qx[2], qx[3], ada + AS_QX);
                LDSM4(qg[0], qg[1], qg[2], qg[3], ada + AS_QG);

                int rB = (lane & 7) + ((lane >> 4) << 3);
                int cB = kc * 2 + ((lane >> 3) & 1);
#pragma unroll
                for (int nb = 0; nb < 4; ++nb) {
                    int r = nb * 16 + rB;
                    uint32_t adb = stg + (uint32_t)(r * 128 + ((cB ^ (r & 7)) * 16));
                    uint32_t k0, k1, k2, k3;
                    LDSM4(k0, k1, k2, k3, adb);
                    mma_f16(sacc[nb * 2],     qx[0], qx[1], qx[2], qx[3], k0, k1);
                    mma_f16(sacc[nb * 2 + 1], qx[0], qx[1], qx[2], qx[3], k2, k3);
                    LDSM4(k0, k1, k2, k3, adb + 8192);
                    mma_f16(sacc[nb * 2],     qg[0], qg[1], qg[2], qg[3], k0, k1);
                    mma_f16(sacc[nb * 2 + 1], qg[0], qg[1], qg[2], qg[3], k2, k3);
                }
            }

            const int rowg0 = rt * 128 + wmr + l4;
            const bool maskneed = (t * 64 + 63) > (rt * 128 + wmr);
#pragma unroll
            for (int ni = 0; ni < 8; ++ni)
#pragma unroll
                for (int c = 0; c < 4; ++c) {
                    sacc[ni][c] *= SC;
                    if (maskneed) {
                        int colg = t * 64 + ni * 8 + 2 * l2 + (c & 1);
                        int rowg = rowg0 + ((c >> 1) & 1) * 8;
                        if (colg > rowg) sacc[ni][c] = -INFINITY;
                    }
                }

            float mx0 = -INFINITY, mx1 = -INFINITY;
#pragma unroll
            for (int ni = 0; ni < 8; ++ni) {
                mx0 = fmaxf(mx0, fmaxf(sacc[ni][0], sacc[ni][1]));
                mx1 = fmaxf(mx1, fmaxf(sacc[ni][2], sacc[ni][3]));
            }
            mx0 = fmaxf(mx0, __shfl_xor_sync(0xffffffffu, mx0, 1));
            mx0 = fmaxf(mx0, __shfl_xor_sync(0xffffffffu, mx0, 2));
            mx1 = fmaxf(mx1, __shfl_xor_sync(0xffffffffu, mx1, 1));
            mx1 = fmaxf(mx1, __shfl_xor_sync(0xffffffffu, mx1, 2));
            float mn0 = fmaxf(m0, mx0), mn1 = fmaxf(m1, mx1);
            float al0 = __expf(m0 - mn0), al1 = __expf(m1 - mn1);
            m0 = mn0; m1 = mn1;

            uint32_t ph[8][2];
            float ps0 = 0.f, ps1 = 0.f;
#pragma unroll
            for (int ni = 0; ni < 8; ++ni) {
                float p0 = __expf(sacc[ni][0] - mn0);
                float p1 = __expf(sacc[ni][1] - mn0);
                float p2 = __expf(sacc[ni][2] - mn1);
                float p3 = __expf(sacc[ni][3] - mn1);
                ps0 += p0 + p1; ps1 += p2 + p3;
                ph[ni][0] = pack_h2(__float2half_rn(p0), __float2half_rn(p1));
                ph[ni][1] = pack_h2(__float2half_rn(p2), __float2half_rn(p3));
                oacc[ni][0] *= al0; oacc[ni][1] *= al0;
                oacc[ni][2] *= al1; oacc[ni][3] *= al1;
            }
            ps0 += __shfl_xor_sync(0xffffffffu, ps0, 1);
            ps0 += __shfl_xor_sync(0xffffffffu, ps0, 2);
            ps1 += __shfl_xor_sync(0xffffffffu, ps1, 1);
            ps1 += __shfl_xor_sync(0xffffffffu, ps1, 2);
            l0 = l0 * al0 + ps0;
            l1 = l1 * al1 + ps1;

#pragma unroll
            for (int kc = 0; kc < 4; ++kc) {
                uint32_t a0 = ph[2 * kc][0], a1 = ph[2 * kc][1];
                uint32_t a2 = ph[2 * kc + 1][0], a3 = ph[2 * kc + 1][1];
                int rV = kc * 16 + (lane & 7) + (((lane >> 3) & 1) << 3);
#pragma unroll
                for (int db = 0; db < 4; ++db) {
                    int cV = db * 2 + (lane >> 4);
                    uint32_t adv = stg + 16384 + (uint32_t)(rV * 128 + ((cV ^ (rV & 7)) * 16));
                    uint32_t vh0, vh1, vh2, vh3;
                    LDSM4T(vh0, vh1, vh2, vh3, adv);
                    mma_f16(oacc[db * 2],     a0, a1, a2, a3, vh0, vh1);
                    mma_f16(oacc[db * 2 + 1], a0, a1, a2, a3, vh2, vh3);
                }
            }
        }
    }

    const float inv0 = 1.f / l0, inv1 = 1.f / l1;
#pragma unroll
    for (int rh = 0; rh < 2; ++rh) {
        int row = wmr + l4 + rh * 8;
        float inv = rh ? inv1 : inv0;
        size_t base = ((size_t)b * L_ + (size_t)rt * 128 + row) * D_ + h * HD_;
#pragma unroll
        for (int ni = 0; ni < 8; ++ni) {
            int col = ni * 8 + 2 * l2;
            *(uint32_t*)(yh + base + col) =
                pack_h2(__float2half_rn(oacc[ni][rh * 2] * inv),
                        __float2half_rn(oacc[ni][rh * 2 + 1] * inv));
        }
    }
}

// ---------------------------------------------------------------------------
extern "C" void kernel_launch(void* const* d_in, const int* in_sizes, int n_in,
                              void* d_out, int out_size) {
    const float* x    = (const float*)d_in[0];
    const float* q_g  = (const float*)d_in[1];
    const float* k_g  = (const float*)d_in[2];
    const float* Wqkv = (const float*)d_in[3];
    const float* Wout = (const float*)d_in[4];
    float* out = (float*)d_out;

    __half *xh, *wqh, *woh;
    __half *qh, *kh, *vh, *qgh, *kgh, *yh;
    cudaGetSymbolAddress((void**)&xh,  g_xh);
    cudaGetSymbolAddress((void**)&wqh, g_wqh);
    cudaGetSymbolAddress((void**)&woh, g_woh);
    cudaGetSymbolAddress((void**)&qh,  g_qh);
    cudaGetSymbolAddress((void**)&kh,  g_kh);
    cudaGetSymbolAddress((void**)&vh,  g_vh);
    cudaGetSymbolAddress((void**)&qgh, g_qgh);
    cudaGetSymbolAddress((void**)&kgh, g_kgh);
    cudaGetSymbolAddress((void**)&yh,  g_yh);

    cudaFuncSetAttribute(tgemm_h<0>,
                         cudaFuncAttributeMaxDynamicSharedMemorySize, GEMM_SMEM);
    cudaFuncSetAttribute(tgemm_h<1>,
                         cudaFuncAttributeMaxDynamicSharedMemorySize, GEMM_SMEM);
    cudaFuncSetAttribute(attn_fa,
                         cudaFuncAttributeMaxDynamicSharedMemorySize, ATT_SMEM);

    const int NX  = B_ * L_ * D_ / 4;
    const int NWQ = D3_ * D_ / 4;
    const int NWO = D_ * D_ / 4;

    split_hi_kernel<<<(NX + 255) / 256, 256>>>((const float4*)x, (uint2*)xh, NX);
    split_hi_kernel<<<(NWQ + 255) / 256, 256>>>((const float4*)Wqkv, (uint2*)wqh, NWQ);
    split_hi_kernel<<<(NWO + 255) / 256, 256>>>((const float4*)Wout, (uint2*)woh, NWO);
    split_hi_kernel<<<(NX + 255) / 256, 256>>>((const float4*)q_g, (uint2*)qgh, NX);
    split_hi_kernel<<<(NX + 255) / 256, 256>>>((const float4*)k_g, (uint2*)kgh, NX);

    // 1) qkv projection, single hi-only launch; q,k,v all stored fp16-hi
    tgemm_h<1><<<dim3(24, 32), 256, GEMM_SMEM>>>(
        xh, wqh, nullptr, qh, kh, vh, B_ * L_, D3_, D_, 0);

    // 2) attention (fully fp16) -> fp16 y
    attn_fa<<<dim3(L_ / 128, B_ * H_), 256, ATT_SMEM>>>(qh, kh, vh, qgh, kgh, yh);

    // 3) out projection -> fp32 out (hi-only)
    tgemm_h<0><<<dim3(8, 32), 256, GEMM_SMEM>>>(
        yh, woh, out, nullptr, nullptr, nullptr, B_ * L_, D_, D_, 0);
}

// round 17
// speedup vs baseline: 6.2446x; 1.1582x over previous
#include <cuda_runtime.h>
#include <cuda_fp16.h>
#include <math.h>
#include <stdint.h>

#define B_  4
#define L_  1024
#define D_  1024
#define H_  16
#define HD_ 64
#define D3_ 3072

// ---------------------------------------------------------------------------
// Scratch (device globals; no allocation)
// ---------------------------------------------------------------------------
__device__ __half g_xh[(size_t)B_ * L_ * D_];
__device__ __half g_wqh[(size_t)D3_ * D_];
__device__ __half g_woh[(size_t)D_ * D_];
__device__ __half g_qh[(size_t)B_ * L_ * D_];
__device__ __half g_kh[(size_t)B_ * L_ * D_];
__device__ __half g_vh[(size_t)B_ * L_ * D_];
__device__ __half g_qgh[(size_t)B_ * L_ * D_], g_kgh[(size_t)B_ * L_ * D_];
__device__ __half g_yh[(size_t)B_ * L_ * D_];

// ---------------------------------------------------------------------------
// helpers
// ---------------------------------------------------------------------------
__device__ __forceinline__ uint32_t cvta_s(const void* p) {
    return (uint32_t)__cvta_generic_to_shared(p);
}
__device__ __forceinline__ uint32_t pack_h2(__half a, __half b) {
    __half2 h = __halves2half2(a, b);
    return *(uint32_t*)&h;
}
__device__ __forceinline__ void mma_f16(float* c,
                                        uint32_t a0, uint32_t a1, uint32_t a2, uint32_t a3,
                                        uint32_t b0, uint32_t b1) {
    asm volatile(
        "mma.sync.aligned.m16n8k16.row.col.f32.f16.f16.f32 "
        "{%0,%1,%2,%3},{%4,%5,%6,%7},{%8,%9},{%0,%1,%2,%3};\n"
        : "+f"(c[0]), "+f"(c[1]), "+f"(c[2]), "+f"(c[3])
        : "r"(a0), "r"(a1), "r"(a2), "r"(a3), "r"(b0), "r"(b1));
}
#define LDSM4(r0, r1, r2, r3, addr) \
    asm volatile("ldmatrix.sync.aligned.m8n8.x4.shared.b16 {%0,%1,%2,%3},[%4];\n" \
                 : "=r"(r0), "=r"(r1), "=r"(r2), "=r"(r3) : "r"(addr))
#define LDSM4T(r0, r1, r2, r3, addr) \
    asm volatile("ldmatrix.sync.aligned.m8n8.x4.trans.shared.b16 {%0,%1,%2,%3},[%4];\n" \
                 : "=r"(r0), "=r"(r1), "=r"(r2), "=r"(r3) : "r"(addr))
#define CP16(saddr, gptr) \
    asm volatile("cp.async.cg.shared.global [%0], [%1], 16;\n" :: "r"(saddr), "l"(gptr))
#define CP_COMMIT() asm volatile("cp.async.commit_group;\n")
#define CP_WAIT0()  asm volatile("cp.async.wait_group 0;\n")
#define CP_WAIT2()  asm volatile("cp.async.wait_group 2;\n")

// ---------------------------------------------------------------------------
// fused split kernel: converts 5 fp32 arrays to fp16 in one launch.
// gridDim.y selects the array.
// ---------------------------------------------------------------------------
__global__ __launch_bounds__(256) void split5_kernel(
    const float4* __restrict__ s0, const float4* __restrict__ s1,
    const float4* __restrict__ s2, const float4* __restrict__ s3,
    const float4* __restrict__ s4,
    uint2* __restrict__ d0, uint2* __restrict__ d1, uint2* __restrict__ d2,
    uint2* __restrict__ d3, uint2* __restrict__ d4,
    int n0, int n1, int n2, int n3, int n4x) {
    const int y = blockIdx.y;
    const float4* s = (y == 0) ? s0 : (y == 1) ? s1 : (y == 2) ? s2 : (y == 3) ? s3 : s4;
    uint2* d       = (y == 0) ? d0 : (y == 1) ? d1 : (y == 2) ? d2 : (y == 3) ? d3 : d4;
    const int n    = (y == 0) ? n0 : (y == 1) ? n1 : (y == 2) ? n2 : (y == 3) ? n3 : n4x;
    int i = blockIdx.x * blockDim.x + threadIdx.x;
    if (i >= n) return;
    float4 v = s[i];
    d[i] = make_uint2(pack_h2(__float2half_rn(v.x), __float2half_rn(v.y)),
                      pack_h2(__float2half_rn(v.z), __float2half_rn(v.w)));
}

// ---------------------------------------------------------------------------
// Tensor-core GEMM (NT) on fp16 operands, 1 MMA (uncompensated).
// 128x128 tile, BK=32 (one barrier per 32-K), 8 warps (2m x 4n).
// cp.async 4-stage; 64B rows, swizzle c ^ ((r>>1)&3).
// Stage: A 8K @0 | B 8K @8192; 4 stages = 64KB.
// MODE 0: write fp32 C. MODE 1: qkv epilogue (q,k,v all fp16-hi).
// ---------------------------------------------------------------------------
#define STAGE_B 16384
#define GEMM_SMEM 65536

template <int MODE>
__global__ __launch_bounds__(256) void tgemm_h(const __half* __restrict__ Ah,
                                               const __half* __restrict__ Bh,
                                               float* __restrict__ C,
                                               __half* __restrict__ Qo,
                                               __half* __restrict__ Ko,
                                               __half* __restrict__ Vo,
                                               int M, int N, int K, int bn0) {
    extern __shared__ char sm[];
    const uint32_t sbase = cvta_s(sm);

    const int tid  = threadIdx.x;
    const int warp = tid >> 5, lane = tid & 31;
    const int g = lane >> 2, tig = lane & 3;
    const int wm = (warp >> 2) * 64;
    const int wn = (warp & 3) * 32;
    const int bm = blockIdx.y * 128, bn = bn0 + blockIdx.x * 128;

    // loaders: arr 0 -> A rows, arr 2 -> B rows; arr 1,3 idle.
    // 64 threads x 8 chunks cover 128 rows x 4 chunks (16B) per stage.
    const int arr = tid >> 6;
    const int t2  = tid & 63;
    const bool loader = (arr == 0) || (arr == 2);
    const __half* gsrc = (arr == 2) ? Bh + (size_t)bn * K : Ah + (size_t)bm * K;
    int rows[8], csrc[8];
    uint32_t soff[8];
#pragma unroll
    for (int i = 0; i < 8; ++i) {
        int u = t2 + 64 * i;                  // 0..511
        int r = u >> 2, c = u & 3;
        rows[i] = r; csrc[i] = c;
        soff[i] = (uint32_t)(((arr == 2) ? 8192 : 0) + r * 64 +
                             ((c ^ ((r >> 1) & 3)) * 16));
    }

    // ldmatrix offsets per 16-K sub-block s16 (chunks c = s16*2 + inner)
    uint32_t aoff[4][2];
#pragma unroll
    for (int mi = 0; mi < 4; ++mi)
#pragma unroll
        for (int s16 = 0; s16 < 2; ++s16) {
            int r = wm + mi * 16 + (lane & 15);
            int c = s16 * 2 + (lane >> 4);
            aoff[mi][s16] = (uint32_t)(r * 64 + ((c ^ ((r >> 1) & 3)) * 16));
        }
    uint32_t boff[2][2];
#pragma unroll
    for (int nb = 0; nb < 2; ++nb)
#pragma unroll
        for (int s16 = 0; s16 < 2; ++s16) {
            int r = wn + nb * 16 + (lane & 7) + ((lane >> 4) << 3);
            int c = s16 * 2 + ((lane >> 3) & 1);
            boff[nb][s16] = (uint32_t)(8192 + r * 64 + ((c ^ ((r >> 1) & 3)) * 16));
        }

    float acc[4][4][4];
#pragma unroll
    for (int mi = 0; mi < 4; ++mi)
#pragma unroll
        for (int ni = 0; ni < 4; ++ni)
#pragma unroll
            for (int r = 0; r < 4; ++r) acc[mi][ni][r] = 0.f;

    const int nk = K >> 5;                    // 32-K chunks
#pragma unroll
    for (int s = 0; s < 3; ++s) {
        const uint32_t sb = sbase + s * STAGE_B;
        if (loader) {
#pragma unroll
            for (int i = 0; i < 8; ++i)
                CP16(sb + soff[i], gsrc + (size_t)rows[i] * K + s * 32 + csrc[i] * 8);
        }
        CP_COMMIT();
    }
    CP_WAIT2();
    __syncthreads();

    for (int kt = 0; kt < nk; ++kt) {
        const uint32_t stg = sbase + (uint32_t)(kt & 3) * STAGE_B;

#pragma unroll
        for (int s16 = 0; s16 < 2; ++s16) {
            uint32_t bhf[4][2];
#pragma unroll
            for (int nb = 0; nb < 2; ++nb) {
                uint32_t r0, r1, r2, r3;
                LDSM4(r0, r1, r2, r3, stg + boff[nb][s16]);
                bhf[nb * 2][0] = r0; bhf[nb * 2][1] = r1;
                bhf[nb * 2 + 1][0] = r2; bhf[nb * 2 + 1][1] = r3;
            }
#pragma unroll
            for (int mi = 0; mi < 4; ++mi) {
                uint32_t ah[4];
                LDSM4(ah[0], ah[1], ah[2], ah[3], stg + aoff[mi][s16]);
#pragma unroll
                for (int ni = 0; ni < 4; ++ni)
                    mma_f16(acc[mi][ni], ah[0], ah[1], ah[2], ah[3],
                            bhf[ni][0], bhf[ni][1]);
            }
        }

        if (kt + 3 < nk) {
            const uint32_t sb = sbase + (uint32_t)((kt + 3) & 3) * STAGE_B;
            if (loader) {
#pragma unroll
                for (int i = 0; i < 8; ++i)
                    CP16(sb + soff[i], gsrc + (size_t)rows[i] * K + (kt + 3) * 32 + csrc[i] * 8);
            }
        }
        CP_COMMIT();
        CP_WAIT2();
        __syncthreads();
    }

#pragma unroll
    for (int mi = 0; mi < 4; ++mi) {
#pragma unroll
        for (int ni = 0; ni < 4; ++ni) {
            int col = bn + wn + ni * 8 + 2 * tig;
#pragma unroll
            for (int rs = 0; rs < 2; ++rs) {
                int row = bm + wm + mi * 16 + g + rs * 8;
                float v0 = acc[mi][ni][rs * 2], v1 = acc[mi][ni][rs * 2 + 1];
                if (MODE == 0) {
                    *(float2*)(C + (size_t)row * N + col) = make_float2(v0, v1);
                } else {
                    int path = col >> 10, lcol = col & 1023;
                    size_t off = (size_t)row * D_ + lcol;
                    __half* dst = (path == 0) ? Qo : (path == 1) ? Ko : Vo;
                    *(uint32_t*)(dst + off) = pack_h2(__float2half_rn(v0), __float2half_rn(v1));
                }
            }
        }
    }
}

// ---------------------------------------------------------------------------
// FA2-style dual-path causal attention, fully fp16 (unchanged from R16).
// ---------------------------------------------------------------------------
#define AS_QX 0
#define AS_QG 16384
#define AS_KV 32768
#define KV_STAGE 24576
#define ATT_SMEM (32768 + 2 * KV_STAGE)

__global__ __launch_bounds__(256) void attn_fa(
    const __half* __restrict__ qh,  const __half* __restrict__ kh,
    const __half* __restrict__ vh,
    const __half* __restrict__ qgh, const __half* __restrict__ kgh,
    __half* __restrict__ yh) {
    extern __shared__ char sm[];
    const uint32_t sb = cvta_s(sm);
    const int tid  = threadIdx.x;
    const int warp = tid >> 5, lane = tid & 31;
    const int wmr  = warp * 16;
    const int bh = blockIdx.y, b = bh >> 4, h = bh & 15;
    const int rt = blockIdx.x;
    const int l4 = lane >> 2, l2 = lane & 3;
    const float SC = 0.125f / 6.931471805599453f;

    {
        const size_t qbase = ((size_t)b * L_ + (size_t)rt * 128) * D_ + h * HD_;
#pragma unroll
        for (int i = 0; i < 4; ++i) {
            int u = tid + 256 * i;
            int r = u >> 3, c = u & 7;
            uint32_t off = (uint32_t)(r * 128 + ((c ^ (r & 7)) * 16));
            CP16(sb + AS_QX + off, qh  + qbase + (size_t)r * D_ + c * 8);
            CP16(sb + AS_QG + off, qgh + qbase + (size_t)r * D_ + c * 8);
        }
    }

    const int arr = tid >> 6, t2 = tid & 63;
    const bool kvload = (arr < 3);
    const __half* kvsrc = (arr == 0) ? kh : (arr == 1) ? kgh : vh;
    const uint32_t kvdst = sb + AS_KV + (uint32_t)arr * 8192;
    const size_t bhbase = (size_t)b * L_ * D_ + h * HD_;

#define LOAD_KV(t, s)                                                              \
    do {                                                                           \
        if (kvload) {                                                              \
            const size_t kb = bhbase + (size_t)(t) * 64 * D_;                      \
            const uint32_t db = kvdst + (uint32_t)(s) * KV_STAGE;                  \
            _Pragma("unroll") for (int i = 0; i < 8; ++i) {                        \
                int u = t2 + 64 * i;                                               \
                int r = u >> 3, c = u & 7;                                         \
                CP16(db + (uint32_t)(r * 128 + ((c ^ (r & 7)) * 16)),              \
                     kvsrc + kb + (size_t)r * D_ + c * 8);                         \
            }                                                                      \
        }                                                                          \
    } while (0)

    LOAD_KV(0, 0);
    CP_COMMIT();

    float m0 = -INFINITY, m1 = -INFINITY, l0 = 0.f, l1 = 0.f;
    float oacc[8][4];
#pragma unroll
    for (int ni = 0; ni < 8; ++ni)
#pragma unroll
        for (int r = 0; r < 4; ++r) oacc[ni][r] = 0.f;

    const int nt = 2 * rt + 2;
    for (int t = 0; t < nt; ++t) {
        CP_WAIT0();
        __syncthreads();
        if (t + 1 < nt) {
            LOAD_KV(t + 1, (t + 1) & 1);
            CP_COMMIT();
        }
        const uint32_t stg = sb + AS_KV + (uint32_t)(t & 1) * KV_STAGE;

        const bool skip = (t * 64) > (rt * 128 + wmr + 15);
        if (!skip) {
            float sacc[8][4];
#pragma unroll
            for (int ni = 0; ni < 8; ++ni)
#pragma unroll
                for (int r = 0; r < 4; ++r) sacc[ni][r] = 0.f;

#pragma unroll
            for (int kc = 0; kc < 4; ++kc) {
                int rA = wmr + (lane & 15);
                int cA = kc * 2 + (lane >> 4);
                uint32_t ada = sb + (uint32_t)(rA * 128 + ((cA ^ (rA & 7)) * 16));
                uint32_t qx[4], qg[4];
                LDSM4(qx[0], qx[1], qx[2], qx[3], ada + AS_QX);
                LDSM4(qg[0], qg[1], qg[2], qg[3], ada + AS_QG);

                int rB = (lane & 7) + ((lane >> 4) << 3);
                int cB = kc * 2 + ((lane >> 3) & 1);
#pragma unroll
                for (int nb = 0; nb < 4; ++nb) {
                    int r = nb * 16 + rB;
                    uint32_t adb = stg + (uint32_t)(r * 128 + ((cB ^ (r & 7)) * 16));
                    uint32_t k0, k1, k2, k3;
                    LDSM4(k0, k1, k2, k3, adb);
                    mma_f16(sacc[nb * 2],     qx[0], qx[1], qx[2], qx[3], k0, k1);
                    mma_f16(sacc[nb * 2 + 1], qx[0], qx[1], qx[2], qx[3], k2, k3);
                    LDSM4(k0, k1, k2, k3, adb + 8192);
                    mma_f16(sacc[nb * 2],     qg[0], qg[1], qg[2], qg[3], k0, k1);
                    mma_f16(sacc[nb * 2 + 1], qg[0], qg[1], qg[2], qg[3], k2, k3);
                }
            }

            const int rowg0 = rt * 128 + wmr + l4;
            const bool maskneed = (t * 64 + 63) > (rt * 128 + wmr);
#pragma unroll
            for (int ni = 0; ni < 8; ++ni)
#pragma unroll
                for (int c = 0; c < 4; ++c) {
                    sacc[ni][c] *= SC;
                    if (maskneed) {
                        int colg = t * 64 + ni * 8 + 2 * l2 + (c & 1);
                        int rowg = rowg0 + ((c >> 1) & 1) * 8;
                        if (colg > rowg) sacc[ni][c] = -INFINITY;
                    }
                }

            float mx0 = -INFINITY, mx1 = -INFINITY;
#pragma unroll
            for (int ni = 0; ni < 8; ++ni) {
                mx0 = fmaxf(mx0, fmaxf(sacc[ni][0], sacc[ni][1]));
                mx1 = fmaxf(mx1, fmaxf(sacc[ni][2], sacc[ni][3]));
            }
            mx0 = fmaxf(mx0, __shfl_xor_sync(0xffffffffu, mx0, 1));
            mx0 = fmaxf(mx0, __shfl_xor_sync(0xffffffffu, mx0, 2));
            mx1 = fmaxf(mx1, __shfl_xor_sync(0xffffffffu, mx1, 1));
            mx1 = fmaxf(mx1, __shfl_xor_sync(0xffffffffu, mx1, 2));
            float mn0 = fmaxf(m0, mx0), mn1 = fmaxf(m1, mx1);
            float al0 = __expf(m0 - mn0), al1 = __expf(m1 - mn1);
            m0 = mn0; m1 = mn1;

            uint32_t ph[8][2];
            float ps0 = 0.f, ps1 = 0.f;
#pragma unroll
            for (int ni = 0; ni < 8; ++ni) {
                float p0 = __expf(sacc[ni][0] - mn0);
                float p1 = __expf(sacc[ni][1] - mn0);
                float p2 = __expf(sacc[ni][2] - mn1);
                float p3 = __expf(sacc[ni][3] - mn1);
                ps0 += p0 + p1; ps1 += p2 + p3;
                ph[ni][0] = pack_h2(__float2half_rn(p0), __float2half_rn(p1));
                ph[ni][1] = pack_h2(__float2half_rn(p2), __float2half_rn(p3));
                oacc[ni][0] *= al0; oacc[ni][1] *= al0;
                oacc[ni][2] *= al1; oacc[ni][3] *= al1;
            }
            ps0 += __shfl_xor_sync(0xffffffffu, ps0, 1);
            ps0 += __shfl_xor_sync(0xffffffffu, ps0, 2);
            ps1 += __shfl_xor_sync(0xffffffffu, ps1, 1);
            ps1 += __shfl_xor_sync(0xffffffffu, ps1, 2);
            l0 = l0 * al0 + ps0;
            l1 = l1 * al1 + ps1;

#pragma unroll
            for (int kc = 0; kc < 4; ++kc) {
                uint32_t a0 = ph[2 * kc][0], a1 = ph[2 * kc][1];
                uint32_t a2 = ph[2 * kc + 1][0], a3 = ph[2 * kc + 1][1];
                int rV = kc * 16 + (lane & 7) + (((lane >> 3) & 1) << 3);
#pragma unroll
                for (int db = 0; db < 4; ++db) {
                    int cV = db * 2 + (lane >> 4);
                    uint32_t adv = stg + 16384 + (uint32_t)(rV * 128 + ((cV ^ (rV & 7)) * 16));
                    uint32_t vh0, vh1, vh2, vh3;
                    LDSM4T(vh0, vh1, vh2, vh3, adv);
                    mma_f16(oacc[db * 2],     a0, a1, a2, a3, vh0, vh1);
                    mma_f16(oacc[db * 2 + 1], a0, a1, a2, a3, vh2, vh3);
                }
            }
        }
    }

    const float inv0 = 1.f / l0, inv1 = 1.f / l1;
#pragma unroll
    for (int rh = 0; rh < 2; ++rh) {
        int row = wmr + l4 + rh * 8;
        float inv = rh ? inv1 : inv0;
        size_t base = ((size_t)b * L_ + (size_t)rt * 128 + row) * D_ + h * HD_;
#pragma unroll
        for (int ni = 0; ni < 8; ++ni) {
            int col = ni * 8 + 2 * l2;
            *(uint32_t*)(yh + base + col) =
                pack_h2(__float2half_rn(oacc[ni][rh * 2] * inv),
                        __float2half_rn(oacc[ni][rh * 2 + 1] * inv));
        }
    }
}

// ---------------------------------------------------------------------------
extern "C" void kernel_launch(void* const* d_in, const int* in_sizes, int n_in,
                              void* d_out, int out_size) {
    const float* x    = (const float*)d_in[0];
    const float* q_g  = (const float*)d_in[1];
    const float* k_g  = (const float*)d_in[2];
    const float* Wqkv = (const float*)d_in[3];
    const float* Wout = (const float*)d_in[4];
    float* out = (float*)d_out;

    __half *xh, *wqh, *woh;
    __half *qh, *kh, *vh, *qgh, *kgh, *yh;
    cudaGetSymbolAddress((void**)&xh,  g_xh);
    cudaGetSymbolAddress((void**)&wqh, g_wqh);
    cudaGetSymbolAddress((void**)&woh, g_woh);
    cudaGetSymbolAddress((void**)&qh,  g_qh);
    cudaGetSymbolAddress((void**)&kh,  g_kh);
    cudaGetSymbolAddress((void**)&vh,  g_vh);
    cudaGetSymbolAddress((void**)&qgh, g_qgh);
    cudaGetSymbolAddress((void**)&kgh, g_kgh);
    cudaGetSymbolAddress((void**)&yh,  g_yh);

    cudaFuncSetAttribute(tgemm_h<0>,
                         cudaFuncAttributeMaxDynamicSharedMemorySize, GEMM_SMEM);
    cudaFuncSetAttribute(tgemm_h<1>,
                         cudaFuncAttributeMaxDynamicSharedMemorySize, GEMM_SMEM);
    cudaFuncSetAttribute(attn_fa,
                         cudaFuncAttributeMaxDynamicSharedMemorySize, ATT_SMEM);

    const int NX  = B_ * L_ * D_ / 4;
    const int NWQ = D3_ * D_ / 4;
    const int NWO = D_ * D_ / 4;

    // 0) all fp32 -> fp16 conversions in one launch (grid.y selects array)
    split5_kernel<<<dim3((NX + 255) / 256, 5), 256>>>(
        (const float4*)x, (const float4*)q_g, (const float4*)k_g,
        (const float4*)Wqkv, (const float4*)Wout,
        (uint2*)xh, (uint2*)qgh, (uint2*)kgh, (uint2*)wqh, (uint2*)woh,
        NX, NX, NX, NWQ, NWO);

    // 1) qkv projection (single launch; q,k,v stored fp16)
    tgemm_h<1><<<dim3(24, 32), 256, GEMM_SMEM>>>(
        xh, wqh, nullptr, qh, kh, vh, B_ * L_, D3_, D_, 0);

    // 2) attention (fully fp16) -> fp16 y
    attn_fa<<<dim3(L_ / 128, B_ * H_), 256, ATT_SMEM>>>(qh, kh, vh, qgh, kgh, yh);

    // 3) out projection -> fp32 out
    tgemm_h<0><<<dim3(8, 32), 256, GEMM_SMEM>>>(
        yh, woh, out, nullptr, nullptr, nullptr, B_ * L_, D_, D_, 0);
}